// round 1
// baseline (speedup 1.0000x reference)
#include <cuda_runtime.h>

#define DMODEL 1024
#define SEQ    1024
#define BATCH  4
#define NHEAD  16
#define HDIM   64
#define RNK    64
#define MROWS  (BATCH*SEQ)
#define PMAX   64

// ---------------- device scratch (no allocations allowed) ----------------
__device__ float g_h[(size_t)MROWS * 1024];                  // low-rank bottleneck [4096, <=1024]
__device__ float g_q[(size_t)BATCH*NHEAD*SEQ*HDIM];          // [BH, S, D]
__device__ float g_k[(size_t)BATCH*NHEAD*SEQ*HDIM];
__device__ float g_v[(size_t)BATCH*NHEAD*SEQ*HDIM];
__device__ float g_att[(size_t)MROWS * DMODEL];              // [B*S, H*D]
__device__ float g_tw[3][PMAX];
__device__ int   g_ti[3][PMAX];
__device__ int   g_K;

// ---------------- top-k gating (tiny) ----------------
__global__ void topk_kernel(const float* __restrict__ ql, const float* __restrict__ kl,
                            const float* __restrict__ vl, const int* __restrict__ tkp, int P)
{
    if (threadIdx.x != 0) return;
    int K = *tkp; if (K > P) K = P; if (K < 1) K = 1;
    g_K = K;
    const float* ls[3] = {ql, kl, vl};
    for (int p = 0; p < 3; p++) {
        const float* lg = ls[p];
        bool used[PMAX];
        for (int i = 0; i < P; i++) used[i] = false;
        for (int t = 0; t < K; t++) {
            int best = 0; float bv = -3.4e38f;
            for (int i = 0; i < P; i++)
                if (!used[i] && lg[i] > bv) { bv = lg[i]; best = i; }
            used[best] = true;
            g_ti[p][t] = best;
        }
        // softmax over selected == renormalized top-k of full softmax (TEMP=1)
        float mx = -3.4e38f;
        for (int t = 0; t < K; t++) { float v = lg[g_ti[p][t]]; if (v > mx) mx = v; }
        float ssum = 0.f, w[PMAX];
        for (int t = 0; t < K; t++) { w[t] = expf(lg[g_ti[p][t]] - mx); ssum += w[t]; }
        for (int t = 0; t < K; t++) g_tw[p][t] = w[t] / ssum;
    }
}

// ---------------- GEMM 1: h[m, kc*64+j] = tw[kc] * sum_c x[m,c] * U[ti[kc], c, j] ----------------
// grid (64, 16) : blockIdx.x = M tile (64 rows), blockIdx.y = kc chunk (early exit if >= top_k)
__global__ __launch_bounds__(256) void gemm_xu(const float* __restrict__ x,
                                               const float* __restrict__ U, int proj)
{
    int kc = blockIdx.y;
    if (kc >= g_K) return;
    __shared__ __align__(16) float As[16 * 64];  // As[c][m]
    __shared__ __align__(16) float Bs[16 * 64];  // Bs[c][n]
    int tid = threadIdx.x;
    int tx = tid & 15, ty = tid >> 4;
    int m0 = blockIdx.x << 6;
    int prim = g_ti[proj][kc];
    float tw  = g_tw[proj][kc];
    const float* Bp = U + (size_t)prim * (DMODEL * RNK);

    float acc[4][4];
#pragma unroll
    for (int i = 0; i < 4; i++)
#pragma unroll
        for (int j = 0; j < 4; j++) acc[i][j] = 0.f;

    int la = tid * 4;
    int ar = la >> 4, ac = la & 15;          // A tile: 64 rows x 16 cols
    int br = tid >> 4, bc = (tid & 15) * 4;  // B tile: 16 rows x 64 cols

    for (int c0 = 0; c0 < DMODEL; c0 += 16) {
        float4 av = *(const float4*)(x + (size_t)(m0 + ar) * DMODEL + c0 + ac);
        As[(ac + 0) * 64 + ar] = av.x;
        As[(ac + 1) * 64 + ar] = av.y;
        As[(ac + 2) * 64 + ar] = av.z;
        As[(ac + 3) * 64 + ar] = av.w;
        float4 bv = *(const float4*)(Bp + (size_t)(c0 + br) * RNK + bc);
        *(float4*)(Bs + br * 64 + bc) = bv;
        __syncthreads();
#pragma unroll
        for (int kk = 0; kk < 16; kk++) {
            float4 a4 = *(float4*)(As + kk * 64 + ty * 4);
            float4 b4 = *(float4*)(Bs + kk * 64 + tx * 4);
            float a_[4] = {a4.x, a4.y, a4.z, a4.w};
            float b_[4] = {b4.x, b4.y, b4.z, b4.w};
#pragma unroll
            for (int i = 0; i < 4; i++)
#pragma unroll
                for (int j = 0; j < 4; j++) acc[i][j] += a_[i] * b_[j];
        }
        __syncthreads();
    }
#pragma unroll
    for (int i = 0; i < 4; i++) {
        float* dr = g_h + (size_t)(m0 + ty * 4 + i) * 1024 + kc * 64 + tx * 4;
#pragma unroll
        for (int j = 0; j < 4; j++) dr[j] = tw * acc[i][j];
    }
}

// ---------------- GEMM 2: qkv = h @ gathered(V), written in [B,H,S,D] layout ----------------
// grid (64, 16) : blockIdx.x = M tile, blockIdx.y = head (64-col N tile)
__global__ __launch_bounds__(256) void gemm_hv(const float* __restrict__ Vm, int proj)
{
    float* dst = (proj == 0) ? g_q : (proj == 1) ? g_k : g_v;
    int KC = g_K * 64;
    __shared__ __align__(16) float As[16 * 64];
    __shared__ __align__(16) float Bs[16 * 64];
    int tid = threadIdx.x;
    int tx = tid & 15, ty = tid >> 4;
    int m0 = blockIdx.x << 6;
    int n0 = blockIdx.y << 6;

    float acc[4][4];
#pragma unroll
    for (int i = 0; i < 4; i++)
#pragma unroll
        for (int j = 0; j < 4; j++) acc[i][j] = 0.f;

    int la = tid * 4;
    int ar = la >> 4, ac = la & 15;
    int br = tid >> 4, bc = (tid & 15) * 4;

    for (int c0 = 0; c0 < KC; c0 += 16) {
        float4 av = *(const float4*)(g_h + (size_t)(m0 + ar) * 1024 + c0 + ac);
        As[(ac + 0) * 64 + ar] = av.x;
        As[(ac + 1) * 64 + ar] = av.y;
        As[(ac + 2) * 64 + ar] = av.z;
        As[(ac + 3) * 64 + ar] = av.w;
        int t    = c0 + br;
        int prim = g_ti[proj][t >> 6];
        int jj   = t & 63;
        float4 bv = *(const float4*)(Vm + (size_t)prim * (RNK * DMODEL) + (size_t)jj * DMODEL + n0 + bc);
        *(float4*)(Bs + br * 64 + bc) = bv;
        __syncthreads();
#pragma unroll
        for (int kk = 0; kk < 16; kk++) {
            float4 a4 = *(float4*)(As + kk * 64 + ty * 4);
            float4 b4 = *(float4*)(Bs + kk * 64 + tx * 4);
            float a_[4] = {a4.x, a4.y, a4.z, a4.w};
            float b_[4] = {b4.x, b4.y, b4.z, b4.w};
#pragma unroll
            for (int i = 0; i < 4; i++)
#pragma unroll
                for (int j = 0; j < 4; j++) acc[i][j] += a_[i] * b_[j];
        }
        __syncthreads();
    }
    int hh = blockIdx.y;  // n0 = hh*64, BN==HDIM so a tile is exactly one head
#pragma unroll
    for (int i = 0; i < 4; i++) {
        int m = m0 + ty * 4 + i;
        int b = m >> 10, s = m & 1023;
        float* dr = dst + (((size_t)(b * NHEAD + hh) * SEQ + s) << 6) + tx * 4;
#pragma unroll
        for (int j = 0; j < 4; j++) dr[j] = acc[i][j];
    }
}

// ---------------- flash attention: grid (S/64, B*H), 256 threads ----------------
// thread (row = tid/4, grp = tid%4): owns score cols grp*16..grp*16+15 and out dims grp*16..+15
#define ATT_SMEM (4 * 64 * 65 * 4)
__global__ __launch_bounds__(256) void attn_kernel()
{
    extern __shared__ float sm[];
    float* qs = sm;                 // [64][65]
    float* ks = sm + 64 * 65;       // [64][65]
    float* vs = sm + 2 * 64 * 65;   // [64][65]
    float* ps = sm + 3 * 64 * 65;   // [64][65]

    int qt = blockIdx.x, bh = blockIdx.y;
    const float* qb = g_q + (size_t)bh * SEQ * HDIM;
    const float* kb = g_k + (size_t)bh * SEQ * HDIM;
    const float* vb = g_v + (size_t)bh * SEQ * HDIM;

    int tid = threadIdx.x;
    int row = tid >> 2, grp = tid & 3;
    int qr0 = qt << 6;

    for (int l = tid; l < 64 * 64; l += 256) {
        int r = l >> 6, d = l & 63;
        qs[r * 65 + d] = qb[(size_t)(qr0 + r) * 64 + d];
    }
    __syncthreads();

    float m_run = -3.0e38f, l_run = 0.f;
    float acc[16];
#pragma unroll
    for (int d = 0; d < 16; d++) acc[d] = 0.f;

    for (int kt = 0; kt <= qt; kt++) {
        int kr0 = kt << 6;
        for (int l = tid; l < 64 * 64; l += 256) {
            int r = l >> 6, d = l & 63;
            ks[r * 65 + d] = kb[(size_t)(kr0 + r) * 64 + d];
            vs[r * 65 + d] = vb[(size_t)(kr0 + r) * 64 + d];
        }
        __syncthreads();

        float s[16];
#pragma unroll
        for (int j = 0; j < 16; j++) {
            int col = grp * 16 + j;
            float a = 0.f;
#pragma unroll
            for (int d = 0; d < 64; d++) a += qs[row * 65 + d] * ks[col * 65 + d];
            s[j] = a * 0.125f;  // 1/sqrt(64)
        }
        if (kt == qt) {
#pragma unroll
            for (int j = 0; j < 16; j++) {
                int colg = kr0 + grp * 16 + j;
                if (colg > qr0 + row) s[j] = -3.0e38f;
            }
        }
        float mx = s[0];
#pragma unroll
        for (int j = 1; j < 16; j++) mx = fmaxf(mx, s[j]);
        mx = fmaxf(mx, __shfl_xor_sync(0xffffffffu, mx, 1));
        mx = fmaxf(mx, __shfl_xor_sync(0xffffffffu, mx, 2));
        float m_new = fmaxf(m_run, mx);
        float corr  = __expf(m_run - m_new);
        float psum  = 0.f;
#pragma unroll
        for (int j = 0; j < 16; j++) {
            float p = __expf(s[j] - m_new);
            s[j] = p;
            psum += p;
        }
        psum += __shfl_xor_sync(0xffffffffu, psum, 1);
        psum += __shfl_xor_sync(0xffffffffu, psum, 2);
        l_run = l_run * corr + psum;
        m_run = m_new;
#pragma unroll
        for (int d = 0; d < 16; d++) acc[d] *= corr;
#pragma unroll
        for (int j = 0; j < 16; j++) ps[row * 65 + grp * 16 + j] = s[j];
        __syncwarp();
#pragma unroll
        for (int col = 0; col < 64; col++) {
            float p = ps[row * 65 + col];
#pragma unroll
            for (int d = 0; d < 16; d++) acc[d] += p * vs[col * 65 + grp * 16 + d];
        }
        __syncthreads();
    }

    float inv = 1.f / l_run;
    int b = bh >> 4, h = bh & 15;
    float* orow = g_att + ((size_t)(b * SEQ + qr0 + row)) * DMODEL + h * 64 + grp * 16;
#pragma unroll
    for (int d = 0; d < 16; d++) orow[d] = acc[d] * inv;
}

// ---------------- GEMM 3 (TN): out[m,n] = sum_c att[m,c] * out_w[n,c] ----------------
__global__ __launch_bounds__(256) void gemm_out(const float* __restrict__ W, float* __restrict__ out)
{
    __shared__ __align__(16) float As[16 * 64];
    __shared__ __align__(16) float Bs[16 * 64];
    int tid = threadIdx.x;
    int tx = tid & 15, ty = tid >> 4;
    int m0 = blockIdx.x << 6;
    int n0 = blockIdx.y << 6;

    float acc[4][4];
#pragma unroll
    for (int i = 0; i < 4; i++)
#pragma unroll
        for (int j = 0; j < 4; j++) acc[i][j] = 0.f;

    int la = tid * 4;
    int ar = la >> 4, ac = la & 15;
    int nl = tid >> 2, cl = (tid & 3) * 4;  // B: 64 n-rows, 16 c each

    for (int c0 = 0; c0 < DMODEL; c0 += 16) {
        float4 av = *(const float4*)(g_att + (size_t)(m0 + ar) * DMODEL + c0 + ac);
        As[(ac + 0) * 64 + ar] = av.x;
        As[(ac + 1) * 64 + ar] = av.y;
        As[(ac + 2) * 64 + ar] = av.z;
        As[(ac + 3) * 64 + ar] = av.w;
        float4 bv = *(const float4*)(W + (size_t)(n0 + nl) * DMODEL + c0 + cl);
        Bs[(cl + 0) * 64 + nl] = bv.x;
        Bs[(cl + 1) * 64 + nl] = bv.y;
        Bs[(cl + 2) * 64 + nl] = bv.z;
        Bs[(cl + 3) * 64 + nl] = bv.w;
        __syncthreads();
#pragma unroll
        for (int kk = 0; kk < 16; kk++) {
            float4 a4 = *(float4*)(As + kk * 64 + ty * 4);
            float4 b4 = *(float4*)(Bs + kk * 64 + tx * 4);
            float a_[4] = {a4.x, a4.y, a4.z, a4.w};
            float b_[4] = {b4.x, b4.y, b4.z, b4.w};
#pragma unroll
            for (int i = 0; i < 4; i++)
#pragma unroll
                for (int j = 0; j < 4; j++) acc[i][j] += a_[i] * b_[j];
        }
        __syncthreads();
    }
#pragma unroll
    for (int i = 0; i < 4; i++) {
        float* dr = out + (size_t)(m0 + ty * 4 + i) * DMODEL + n0 + tx * 4;
#pragma unroll
        for (int j = 0; j < 4; j++) dr[j] = acc[i][j];
    }
}

// ---------------- launch ----------------
extern "C" void kernel_launch(void* const* d_in, const int* in_sizes, int n_in,
                              void* d_out, int out_size)
{
    (void)n_in; (void)out_size;
    const float* x   = (const float*)d_in[0];
    const float* qU  = (const float*)d_in[1];
    const float* qV  = (const float*)d_in[2];
    const float* kU  = (const float*)d_in[3];
    const float* kV  = (const float*)d_in[4];
    const float* vU  = (const float*)d_in[5];
    const float* vV  = (const float*)d_in[6];
    const float* ql  = (const float*)d_in[7];
    const float* kl  = (const float*)d_in[8];
    const float* vl  = (const float*)d_in[9];
    const float* ow  = (const float*)d_in[10];
    const int*   tk  = (const int*)d_in[11];
    int P = in_sizes[7];

    cudaFuncSetAttribute(attn_kernel, cudaFuncAttributeMaxDynamicSharedMemorySize, ATT_SMEM);

    topk_kernel<<<1, 32>>>(ql, kl, vl, tk, P);

    dim3 blk(256);
    // q / k / v projections (g_h is reused serially)
    gemm_xu<<<dim3(64, 16), blk>>>(x, qU, 0);
    gemm_hv<<<dim3(64, 16), blk>>>(qV, 0);
    gemm_xu<<<dim3(64, 16), blk>>>(x, kU, 1);
    gemm_hv<<<dim3(64, 16), blk>>>(kV, 1);
    gemm_xu<<<dim3(64, 16), blk>>>(x, vU, 2);
    gemm_hv<<<dim3(64, 16), blk>>>(vV, 2);

    attn_kernel<<<dim3(SEQ / 64, BATCH * NHEAD), blk, ATT_SMEM>>>();

    gemm_out<<<dim3(64, 16), blk>>>(ow, (float*)d_out);
}

// round 2
// speedup vs baseline: 1.5418x; 1.5418x over previous
#include <cuda_runtime.h>

#define DMODEL 1024
#define SEQ    1024
#define BATCH  4
#define NHEAD  16
#define HDIM   64
#define RNK    64
#define MROWS  (BATCH*SEQ)
#define PMAX   64

// ---------------- device scratch ----------------
__device__ float g_h[3][(size_t)MROWS * 1024];
__device__ float g_q[(size_t)BATCH*NHEAD*SEQ*HDIM];
__device__ float g_k[(size_t)BATCH*NHEAD*SEQ*HDIM];
__device__ float g_v[(size_t)BATCH*NHEAD*SEQ*HDIM];
__device__ float g_att[(size_t)MROWS * DMODEL];
__device__ float g_tw[3][PMAX];
__device__ int   g_ti[3][PMAX];
__device__ int   g_K;

// ---------------- top-k gating ----------------
__global__ void topk_kernel(const float* __restrict__ ql, const float* __restrict__ kl,
                            const float* __restrict__ vl, const int* __restrict__ tkp, int P)
{
    if (threadIdx.x != 0) return;
    int K = *tkp; if (K > P) K = P; if (K < 1) K = 1;
    g_K = K;
    const float* ls[3] = {ql, kl, vl};
    for (int p = 0; p < 3; p++) {
        const float* lg = ls[p];
        bool used[PMAX];
        for (int i = 0; i < P; i++) used[i] = false;
        for (int t = 0; t < K; t++) {
            int best = 0; float bv = -3.4e38f;
            for (int i = 0; i < P; i++)
                if (!used[i] && lg[i] > bv) { bv = lg[i]; best = i; }
            used[best] = true;
            g_ti[p][t] = best;
        }
        float mx = -3.4e38f;
        for (int t = 0; t < K; t++) { float v = lg[g_ti[p][t]]; if (v > mx) mx = v; }
        float ssum = 0.f, w[PMAX];
        for (int t = 0; t < K; t++) { w[t] = expf(lg[g_ti[p][t]] - mx); ssum += w[t]; }
        for (int t = 0; t < K; t++) g_tw[p][t] = w[t] / ssum;
    }
}

// ---------------- GEMM tiles: 128x64, BK=16, 256 thr, 8x4 micro, dbuf ----------------
#define BM 128
#define BN 64
#define BK 16
#define SA 132
#define SB 68

#define GEMM_COMPUTE(cur)                                                        \
    _Pragma("unroll")                                                            \
    for (int kk = 0; kk < BK; kk++) {                                            \
        float4 x0 = *(const float4*)&As[cur][kk*SA + ty*8];                      \
        float4 x1 = *(const float4*)&As[cur][kk*SA + ty*8 + 4];                  \
        float4 y0 = *(const float4*)&Bs[cur][kk*SB + tx*4];                      \
        float a_[8] = {x0.x,x0.y,x0.z,x0.w,x1.x,x1.y,x1.z,x1.w};                 \
        float b_[4] = {y0.x,y0.y,y0.z,y0.w};                                     \
        _Pragma("unroll")                                                        \
        for (int i = 0; i < 8; i++)                                              \
            _Pragma("unroll")                                                    \
            for (int j = 0; j < 4; j++) acc[i][j] += a_[i] * b_[j];              \
    }

#define STORE_A(buf, v0, v1)                                                     \
    As[buf][(ac0+0)*SA + ar0] = v0.x; As[buf][(ac0+1)*SA + ar0] = v0.y;          \
    As[buf][(ac0+2)*SA + ar0] = v0.z; As[buf][(ac0+3)*SA + ar0] = v0.w;          \
    As[buf][(ac0+0)*SA + ar0+64] = v1.x; As[buf][(ac0+1)*SA + ar0+64] = v1.y;    \
    As[buf][(ac0+2)*SA + ar0+64] = v1.z; As[buf][(ac0+3)*SA + ar0+64] = v1.w;

// GEMM 1: h[proj][m, kc*64+j] = tw * sum_c x[m,c]*U[ti,c,j]   grid (32, 16, 3)
__global__ __launch_bounds__(256, 2) void gemm_xu(const float* __restrict__ x,
    const float* __restrict__ qU, const float* __restrict__ kU, const float* __restrict__ vU)
{
    int proj = blockIdx.z;
    int kc   = blockIdx.y;
    if (kc >= g_K) return;
    const float* U  = proj == 0 ? qU : proj == 1 ? kU : vU;
    const float* Bp = U + (size_t)g_ti[proj][kc] * (DMODEL * RNK);
    float tw = g_tw[proj][kc];

    __shared__ __align__(16) float As[2][BK*SA];
    __shared__ __align__(16) float Bs[2][BK*SB];
    int tid = threadIdx.x;
    int tx = tid & 15, ty = tid >> 4;
    int m0 = blockIdx.x * BM;
    int ar0 = tid >> 2, ac0 = (tid & 3) * 4;
    int br  = tid >> 4, bc  = (tid & 15) * 4;
    const float* Ag = x + (size_t)m0 * DMODEL;

    float4 a0 = *(const float4*)(Ag + (size_t)ar0*DMODEL + ac0);
    float4 a1 = *(const float4*)(Ag + (size_t)(ar0+64)*DMODEL + ac0);
    float4 b0 = *(const float4*)(Bp + (size_t)br*RNK + bc);
    STORE_A(0, a0, a1)
    *(float4*)&Bs[0][br*SB + bc] = b0;
    __syncthreads();

    float acc[8][4];
#pragma unroll
    for (int i = 0; i < 8; i++)
#pragma unroll
        for (int j = 0; j < 4; j++) acc[i][j] = 0.f;

    const int nk = DMODEL / BK;
    for (int kb = 0; kb < nk; kb++) {
        int cur = kb & 1;
        float4 na0, na1, nb;
        if (kb + 1 < nk) {
            int c0 = (kb + 1) * BK;
            na0 = *(const float4*)(Ag + (size_t)ar0*DMODEL + c0 + ac0);
            na1 = *(const float4*)(Ag + (size_t)(ar0+64)*DMODEL + c0 + ac0);
            nb  = *(const float4*)(Bp + (size_t)(c0+br)*RNK + bc);
        }
        GEMM_COMPUTE(cur)
        if (kb + 1 < nk) {
            int nxt = cur ^ 1;
            STORE_A(nxt, na0, na1)
            *(float4*)&Bs[nxt][br*SB + bc] = nb;
        }
        __syncthreads();
    }
#pragma unroll
    for (int i = 0; i < 8; i++) {
        float* dr = g_h[proj] + (size_t)(m0 + ty*8 + i) * 1024 + kc*64 + tx*4;
#pragma unroll
        for (int j = 0; j < 4; j++) dr[j] = tw * acc[i][j];
    }
}

// GEMM 2: qkv = h @ gathered(V)  ->  [B,H,S,D]   grid (32, 16, 3)
__global__ __launch_bounds__(256, 2) void gemm_hv(const float* __restrict__ qV,
    const float* __restrict__ kV, const float* __restrict__ vV)
{
    int proj = blockIdx.z;
    const float* Vm = proj == 0 ? qV : proj == 1 ? kV : vV;
    float* dst = proj == 0 ? g_q : proj == 1 ? g_k : g_v;
    int KC = g_K * 64;

    __shared__ __align__(16) float As[2][BK*SA];
    __shared__ __align__(16) float Bs[2][BK*SB];
    int tid = threadIdx.x;
    int tx = tid & 15, ty = tid >> 4;
    int m0 = blockIdx.x * BM;
    int n0 = blockIdx.y * BN;
    int ar0 = tid >> 2, ac0 = (tid & 3) * 4;
    int br  = tid >> 4, bc  = (tid & 15) * 4;
    const float* Ag = g_h[proj] + (size_t)m0 * 1024;

    float4 a0 = *(const float4*)(Ag + (size_t)ar0*1024 + ac0);
    float4 a1 = *(const float4*)(Ag + (size_t)(ar0+64)*1024 + ac0);
    {
        int t = br;
        const float* bp = Vm + (size_t)g_ti[proj][t >> 6]*(RNK*DMODEL) + (size_t)(t & 63)*DMODEL;
        float4 b0 = *(const float4*)(bp + n0 + bc);
        STORE_A(0, a0, a1)
        *(float4*)&Bs[0][br*SB + bc] = b0;
    }
    __syncthreads();

    float acc[8][4];
#pragma unroll
    for (int i = 0; i < 8; i++)
#pragma unroll
        for (int j = 0; j < 4; j++) acc[i][j] = 0.f;

    const int nk = KC / BK;
    for (int kb = 0; kb < nk; kb++) {
        int cur = kb & 1;
        float4 na0, na1, nb;
        if (kb + 1 < nk) {
            int c0 = (kb + 1) * BK;
            na0 = *(const float4*)(Ag + (size_t)ar0*1024 + c0 + ac0);
            na1 = *(const float4*)(Ag + (size_t)(ar0+64)*1024 + c0 + ac0);
            int t = c0 + br;
            const float* bp = Vm + (size_t)g_ti[proj][t >> 6]*(RNK*DMODEL) + (size_t)(t & 63)*DMODEL;
            nb = *(const float4*)(bp + n0 + bc);
        }
        GEMM_COMPUTE(cur)
        if (kb + 1 < nk) {
            int nxt = cur ^ 1;
            STORE_A(nxt, na0, na1)
            *(float4*)&Bs[nxt][br*SB + bc] = nb;
        }
        __syncthreads();
    }
    int hh = blockIdx.y;
#pragma unroll
    for (int i = 0; i < 8; i++) {
        int m = m0 + ty*8 + i;
        int b = m >> 10, s = m & 1023;
        float* dr = dst + (((size_t)(b * NHEAD + hh) * SEQ + s) << 6) + tx*4;
#pragma unroll
        for (int j = 0; j < 4; j++) dr[j] = acc[i][j];
    }
}

// GEMM 3 (TN): out[m,n] = sum_c att[m,c] * W[n,c]   grid (32, 16)
__global__ __launch_bounds__(256, 2) void gemm_out(const float* __restrict__ W, float* __restrict__ out)
{
    __shared__ __align__(16) float As[2][BK*SA];
    __shared__ __align__(16) float Bs[2][BK*SB];
    int tid = threadIdx.x;
    int tx = tid & 15, ty = tid >> 4;
    int m0 = blockIdx.x * BM;
    int n0 = blockIdx.y * BN;
    int ar0 = tid >> 2, ac0 = (tid & 3) * 4;
    int nl  = tid >> 2, cl  = (tid & 3) * 4;   // B loader: W[n0+nl][c0+cl..+3]
    const float* Ag = g_att + (size_t)m0 * DMODEL;

    float4 a0 = *(const float4*)(Ag + (size_t)ar0*DMODEL + ac0);
    float4 a1 = *(const float4*)(Ag + (size_t)(ar0+64)*DMODEL + ac0);
    float4 b0 = *(const float4*)(W + (size_t)(n0+nl)*DMODEL + cl);
    STORE_A(0, a0, a1)
    Bs[0][(cl+0)*SB + nl] = b0.x; Bs[0][(cl+1)*SB + nl] = b0.y;
    Bs[0][(cl+2)*SB + nl] = b0.z; Bs[0][(cl+3)*SB + nl] = b0.w;
    __syncthreads();

    float acc[8][4];
#pragma unroll
    for (int i = 0; i < 8; i++)
#pragma unroll
        for (int j = 0; j < 4; j++) acc[i][j] = 0.f;

    const int nk = DMODEL / BK;
    for (int kb = 0; kb < nk; kb++) {
        int cur = kb & 1;
        float4 na0, na1, nb;
        if (kb + 1 < nk) {
            int c0 = (kb + 1) * BK;
            na0 = *(const float4*)(Ag + (size_t)ar0*DMODEL + c0 + ac0);
            na1 = *(const float4*)(Ag + (size_t)(ar0+64)*DMODEL + c0 + ac0);
            nb  = *(const float4*)(W + (size_t)(n0+nl)*DMODEL + c0 + cl);
        }
        GEMM_COMPUTE(cur)
        if (kb + 1 < nk) {
            int nxt = cur ^ 1;
            STORE_A(nxt, na0, na1)
            Bs[nxt][(cl+0)*SB + nl] = nb.x; Bs[nxt][(cl+1)*SB + nl] = nb.y;
            Bs[nxt][(cl+2)*SB + nl] = nb.z; Bs[nxt][(cl+3)*SB + nl] = nb.w;
        }
        __syncthreads();
    }
#pragma unroll
    for (int i = 0; i < 8; i++) {
        float* dr = out + (size_t)(m0 + ty*8 + i) * DMODEL + n0 + tx*4;
#pragma unroll
        for (int j = 0; j < 4; j++) dr[j] = acc[i][j];
    }
}

// ---------------- flash attention: grid (S/64, B*H), 256 thr ----------------
// row = tid/4 (0..63), grp = tid%4: owns score cols grp*16..+15, out dims grp*16..+15
// smem tiles swizzled: phys d4 = (d4 + (row>>4)) & 15  -> conflict-free col-group reads
#define PST 65
#define ATT_SMEM ((4096 + 4096 + 64*PST) * 4)
__global__ __launch_bounds__(256, 2) void attn_kernel()
{
    extern __shared__ float sm[];
    float* ks = sm;
    float* vs = sm + 4096;
    float* ps = sm + 8192;

    int qt = blockIdx.x, bh = blockIdx.y;
    const float* qb = g_q + (size_t)bh * SEQ * HDIM;
    const float* kb = g_k + (size_t)bh * SEQ * HDIM;
    const float* vb = g_v + (size_t)bh * SEQ * HDIM;

    int tid = threadIdx.x;
    int row = tid >> 2, grp = tid & 3;
    int qr0 = qt << 6;

    float4 q4[16];
    const float* qrow = qb + (size_t)(qr0 + row) * 64;
#pragma unroll
    for (int i = 0; i < 16; i++) q4[i] = *(const float4*)(qrow + 4*i);

    float m_run = -3.0e38f, l_run = 0.f;
    float acc[16];
#pragma unroll
    for (int d = 0; d < 16; d++) acc[d] = 0.f;

    for (int kt = 0; kt <= qt; kt++) {
        int kr0 = kt << 6;
        for (int l = tid; l < 1024; l += 256) {
            int r = l >> 4, d4 = l & 15;
            int pd = (d4 + (r >> 4)) & 15;
            float4 kvv = *(const float4*)(kb + (size_t)(kr0 + r)*64 + d4*4);
            *(float4*)(ks + r*64 + pd*4) = kvv;
            float4 vvv = *(const float4*)(vb + (size_t)(kr0 + r)*64 + d4*4);
            *(float4*)(vs + r*64 + pd*4) = vvv;
        }
        __syncthreads();

        float s[16];
#pragma unroll
        for (int j = 0; j < 16; j++) {
            const float* kc_ = ks + (grp*16 + j)*64;
            float a = 0.f;
#pragma unroll
            for (int d4 = 0; d4 < 16; d4++) {
                int pd = (d4 + grp) & 15;
                float4 k4 = *(const float4*)(kc_ + pd*4);
                a += q4[d4].x*k4.x + q4[d4].y*k4.y + q4[d4].z*k4.z + q4[d4].w*k4.w;
            }
            s[j] = a * 0.125f;
        }
        if (kt == qt) {
#pragma unroll
            for (int j = 0; j < 16; j++)
                if (kr0 + grp*16 + j > qr0 + row) s[j] = -3.0e38f;
        }
        float mx = s[0];
#pragma unroll
        for (int j = 1; j < 16; j++) mx = fmaxf(mx, s[j]);
        mx = fmaxf(mx, __shfl_xor_sync(0xffffffffu, mx, 1));
        mx = fmaxf(mx, __shfl_xor_sync(0xffffffffu, mx, 2));
        float m_new = fmaxf(m_run, mx);
        float corr  = __expf(m_run - m_new);
        float psum  = 0.f;
#pragma unroll
        for (int j = 0; j < 16; j++) {
            float p = __expf(s[j] - m_new);
            s[j] = p;
            psum += p;
        }
        psum += __shfl_xor_sync(0xffffffffu, psum, 1);
        psum += __shfl_xor_sync(0xffffffffu, psum, 2);
        l_run = l_run * corr + psum;
        m_run = m_new;
#pragma unroll
        for (int d = 0; d < 16; d++) acc[d] *= corr;
#pragma unroll
        for (int j = 0; j < 16; j++) ps[row*PST + grp*16 + j] = s[j];
        __syncwarp();
#pragma unroll 4
        for (int c = 0; c < 64; c++) {
            float p = ps[row*PST + c];
            const float* vc = vs + c*64;
            int cc = c >> 4;
#pragma unroll
            for (int i = 0; i < 4; i++) {
                int pd = (4*grp + i + cc) & 15;
                float4 v4 = *(const float4*)(vc + pd*4);
                acc[4*i+0] += p * v4.x;
                acc[4*i+1] += p * v4.y;
                acc[4*i+2] += p * v4.z;
                acc[4*i+3] += p * v4.w;
            }
        }
        __syncthreads();
    }

    float inv = 1.f / l_run;
    int b = bh >> 4, h = bh & 15;
    float* orow = g_att + ((size_t)(b * SEQ + qr0 + row)) * DMODEL + h*64 + grp*16;
#pragma unroll
    for (int d = 0; d < 16; d++) orow[d] = acc[d] * inv;
}

// ---------------- launch ----------------
extern "C" void kernel_launch(void* const* d_in, const int* in_sizes, int n_in,
                              void* d_out, int out_size)
{
    (void)n_in; (void)out_size;
    const float* x   = (const float*)d_in[0];
    const float* qU  = (const float*)d_in[1];
    const float* qV  = (const float*)d_in[2];
    const float* kU  = (const float*)d_in[3];
    const float* kV  = (const float*)d_in[4];
    const float* vU  = (const float*)d_in[5];
    const float* vV  = (const float*)d_in[6];
    const float* ql  = (const float*)d_in[7];
    const float* kl  = (const float*)d_in[8];
    const float* vl  = (const float*)d_in[9];
    const float* ow  = (const float*)d_in[10];
    const int*   tk  = (const int*)d_in[11];
    int P = in_sizes[7];

    cudaFuncSetAttribute(attn_kernel, cudaFuncAttributeMaxDynamicSharedMemorySize, ATT_SMEM);

    topk_kernel<<<1, 32>>>(ql, kl, vl, tk, P);

    dim3 blk(256);
    gemm_xu<<<dim3(32, 16, 3), blk>>>(x, qU, kU, vU);
    gemm_hv<<<dim3(32, 16, 3), blk>>>(qV, kV, vV);
    attn_kernel<<<dim3(SEQ / 64, BATCH * NHEAD), blk, ATT_SMEM>>>();
    gemm_out<<<dim3(32, 16), blk>>>(ow, (float*)d_out);
}

// round 3
// speedup vs baseline: 2.6957x; 1.7484x over previous
#include <cuda_runtime.h>

#define DMODEL 1024
#define SEQ    1024
#define BATCH  4
#define NHEAD  16
#define HDIM   64
#define RNK    64
#define MROWS  (BATCH*SEQ)
#define PMAX   64

typedef unsigned long long u64;

// packed fp32x2 helpers (Blackwell FFMA2 path — ptxas never emits from C++)
#define FMA2(c,a,b) asm("fma.rn.f32x2 %0, %1, %2, %0;" : "+l"(c) : "l"(a), "l"(b));
#define MUL2(c,s)   asm("mul.rn.f32x2 %0, %0, %1;"     : "+l"(c) : "l"(s));
#define DUP2(d,f)   asm("mov.b64 %0, {%1, %1};" : "=l"(d) : "f"(f));
#define PACK2(d,lo,hi) asm("mov.b64 %0, {%1, %2};" : "=l"(d) : "f"(lo), "f"(hi));
#define UNPK2(lo,hi,v) asm("mov.b64 {%0, %1}, %2;" : "=f"(lo), "=f"(hi) : "l"(v));

// ---------------- device scratch ----------------
__device__ float g_h[3][(size_t)MROWS * 1024];
__device__ float g_q[(size_t)BATCH*NHEAD*SEQ*HDIM];
__device__ float g_k[(size_t)BATCH*NHEAD*SEQ*HDIM];
__device__ float g_v[(size_t)BATCH*NHEAD*SEQ*HDIM];
__device__ float g_att[(size_t)MROWS * DMODEL];
__device__ float g_tw[3][PMAX];
__device__ int   g_ti[3][PMAX];
__device__ int   g_K;

// ---------------- top-k gating ----------------
__global__ void topk_kernel(const float* __restrict__ ql, const float* __restrict__ kl,
                            const float* __restrict__ vl, const int* __restrict__ tkp, int P)
{
    if (threadIdx.x != 0) return;
    int K = *tkp; if (K > P) K = P; if (K < 1) K = 1;
    g_K = K;
    const float* ls[3] = {ql, kl, vl};
    for (int p = 0; p < 3; p++) {
        const float* lg = ls[p];
        bool used[PMAX];
        for (int i = 0; i < P; i++) used[i] = false;
        for (int t = 0; t < K; t++) {
            int best = 0; float bv = -3.4e38f;
            for (int i = 0; i < P; i++)
                if (!used[i] && lg[i] > bv) { bv = lg[i]; best = i; }
            used[best] = true;
            g_ti[p][t] = best;
        }
        float mx = -3.4e38f;
        for (int t = 0; t < K; t++) { float v = lg[g_ti[p][t]]; if (v > mx) mx = v; }
        float ssum = 0.f, w[PMAX];
        for (int t = 0; t < K; t++) { w[t] = expf(lg[g_ti[p][t]] - mx); ssum += w[t]; }
        for (int t = 0; t < K; t++) g_tw[p][t] = w[t] / ssum;
    }
}

// ---------------- GEMM tiles: 128x64, BK=16, 256 thr, 8x4 micro (row-pair packed), dbuf ----
#define BM 128
#define BN 64
#define BK 16
#define SA 132
#define SB 68

#define GEMM_COMPUTE(cur)                                                        \
    _Pragma("unroll")                                                            \
    for (int kk = 0; kk < BK; kk++) {                                            \
        ulonglong2 a01 = *(const ulonglong2*)&As[cur][kk*SA + ty*8];             \
        ulonglong2 a23 = *(const ulonglong2*)&As[cur][kk*SA + ty*8 + 4];         \
        float4 y0 = *(const float4*)&Bs[cur][kk*SB + tx*4];                      \
        u64 b0,b1,b2,b3;                                                         \
        DUP2(b0,y0.x) DUP2(b1,y0.y) DUP2(b2,y0.z) DUP2(b3,y0.w)                  \
        FMA2(accp[0][0],a01.x,b0) FMA2(accp[0][1],a01.x,b1)                      \
        FMA2(accp[0][2],a01.x,b2) FMA2(accp[0][3],a01.x,b3)                      \
        FMA2(accp[1][0],a01.y,b0) FMA2(accp[1][1],a01.y,b1)                      \
        FMA2(accp[1][2],a01.y,b2) FMA2(accp[1][3],a01.y,b3)                      \
        FMA2(accp[2][0],a23.x,b0) FMA2(accp[2][1],a23.x,b1)                      \
        FMA2(accp[2][2],a23.x,b2) FMA2(accp[2][3],a23.x,b3)                      \
        FMA2(accp[3][0],a23.y,b0) FMA2(accp[3][1],a23.y,b1)                      \
        FMA2(accp[3][2],a23.y,b2) FMA2(accp[3][3],a23.y,b3)                      \
    }

#define ACC_INIT  u64 accp[4][4];                                                \
    _Pragma("unroll") for (int i = 0; i < 4; i++)                                \
    _Pragma("unroll") for (int j = 0; j < 4; j++) accp[i][j] = 0ull;

#define STORE_A(buf, v0, v1)                                                     \
    As[buf][(ac0+0)*SA + ar0] = v0.x; As[buf][(ac0+1)*SA + ar0] = v0.y;          \
    As[buf][(ac0+2)*SA + ar0] = v0.z; As[buf][(ac0+3)*SA + ar0] = v0.w;          \
    As[buf][(ac0+0)*SA + ar0+64] = v1.x; As[buf][(ac0+1)*SA + ar0+64] = v1.y;    \
    As[buf][(ac0+2)*SA + ar0+64] = v1.z; As[buf][(ac0+3)*SA + ar0+64] = v1.w;

// GEMM 1: h[proj][m, kc*64+j] = tw * sum_c x[m,c]*U[ti,c,j]   grid (32, 16, 3)
__global__ __launch_bounds__(256, 2) void gemm_xu(const float* __restrict__ x,
    const float* __restrict__ qU, const float* __restrict__ kU, const float* __restrict__ vU)
{
    int proj = blockIdx.z;
    int kc   = blockIdx.y;
    if (kc >= g_K) return;
    const float* U  = proj == 0 ? qU : proj == 1 ? kU : vU;
    const float* Bp = U + (size_t)g_ti[proj][kc] * (DMODEL * RNK);
    float tw = g_tw[proj][kc];

    __shared__ __align__(16) float As[2][BK*SA];
    __shared__ __align__(16) float Bs[2][BK*SB];
    int tid = threadIdx.x;
    int tx = tid & 15, ty = tid >> 4;
    int m0 = blockIdx.x * BM;
    int ar0 = tid >> 2, ac0 = (tid & 3) * 4;
    int br  = tid >> 4, bc  = (tid & 15) * 4;
    const float* Ag = x + (size_t)m0 * DMODEL;

    float4 a0 = *(const float4*)(Ag + (size_t)ar0*DMODEL + ac0);
    float4 a1 = *(const float4*)(Ag + (size_t)(ar0+64)*DMODEL + ac0);
    float4 b0 = *(const float4*)(Bp + (size_t)br*RNK + bc);
    STORE_A(0, a0, a1)
    *(float4*)&Bs[0][br*SB + bc] = b0;
    __syncthreads();

    ACC_INIT
    const int nk = DMODEL / BK;
    for (int kb = 0; kb < nk; kb++) {
        int cur = kb & 1;
        float4 na0, na1, nb;
        if (kb + 1 < nk) {
            int c0 = (kb + 1) * BK;
            na0 = *(const float4*)(Ag + (size_t)ar0*DMODEL + c0 + ac0);
            na1 = *(const float4*)(Ag + (size_t)(ar0+64)*DMODEL + c0 + ac0);
            nb  = *(const float4*)(Bp + (size_t)(c0+br)*RNK + bc);
        }
        GEMM_COMPUTE(cur)
        if (kb + 1 < nk) {
            int nxt = cur ^ 1;
            STORE_A(nxt, na0, na1)
            *(float4*)&Bs[nxt][br*SB + bc] = nb;
        }
        __syncthreads();
    }
#pragma unroll
    for (int ip = 0; ip < 4; ip++) {
        float o0[4], o1[4];
#pragma unroll
        for (int j = 0; j < 4; j++) { UNPK2(o0[j], o1[j], accp[ip][j]) }
        float* d0 = g_h[proj] + (size_t)(m0 + ty*8 + 2*ip) * 1024 + kc*64 + tx*4;
        float* d1 = d0 + 1024;
#pragma unroll
        for (int j = 0; j < 4; j++) { d0[j] = tw * o0[j]; d1[j] = tw * o1[j]; }
    }
}

// GEMM 2: qkv = h @ gathered(V)  ->  [B,H,S,D]   grid (32, 16, 3)
__global__ __launch_bounds__(256, 2) void gemm_hv(const float* __restrict__ qV,
    const float* __restrict__ kV, const float* __restrict__ vV)
{
    int proj = blockIdx.z;
    const float* Vm = proj == 0 ? qV : proj == 1 ? kV : vV;
    float* dst = proj == 0 ? g_q : proj == 1 ? g_k : g_v;
    int KC = g_K * 64;

    __shared__ __align__(16) float As[2][BK*SA];
    __shared__ __align__(16) float Bs[2][BK*SB];
    int tid = threadIdx.x;
    int tx = tid & 15, ty = tid >> 4;
    int m0 = blockIdx.x * BM;
    int n0 = blockIdx.y * BN;
    int ar0 = tid >> 2, ac0 = (tid & 3) * 4;
    int br  = tid >> 4, bc  = (tid & 15) * 4;
    const float* Ag = g_h[proj] + (size_t)m0 * 1024;

    float4 a0 = *(const float4*)(Ag + (size_t)ar0*1024 + ac0);
    float4 a1 = *(const float4*)(Ag + (size_t)(ar0+64)*1024 + ac0);
    {
        int t = br;
        const float* bp = Vm + (size_t)g_ti[proj][t >> 6]*(RNK*DMODEL) + (size_t)(t & 63)*DMODEL;
        float4 b0 = *(const float4*)(bp + n0 + bc);
        STORE_A(0, a0, a1)
        *(float4*)&Bs[0][br*SB + bc] = b0;
    }
    __syncthreads();

    ACC_INIT
    const int nk = KC / BK;
    for (int kb = 0; kb < nk; kb++) {
        int cur = kb & 1;
        float4 na0, na1, nb;
        if (kb + 1 < nk) {
            int c0 = (kb + 1) * BK;
            na0 = *(const float4*)(Ag + (size_t)ar0*1024 + c0 + ac0);
            na1 = *(const float4*)(Ag + (size_t)(ar0+64)*1024 + c0 + ac0);
            int t = c0 + br;
            const float* bp = Vm + (size_t)g_ti[proj][t >> 6]*(RNK*DMODEL) + (size_t)(t & 63)*DMODEL;
            nb = *(const float4*)(bp + n0 + bc);
        }
        GEMM_COMPUTE(cur)
        if (kb + 1 < nk) {
            int nxt = cur ^ 1;
            STORE_A(nxt, na0, na1)
            *(float4*)&Bs[nxt][br*SB + bc] = nb;
        }
        __syncthreads();
    }
    int hh = blockIdx.y;
#pragma unroll
    for (int ip = 0; ip < 4; ip++) {
        float o0[4], o1[4];
#pragma unroll
        for (int j = 0; j < 4; j++) { UNPK2(o0[j], o1[j], accp[ip][j]) }
#pragma unroll
        for (int hhl = 0; hhl < 2; hhl++) {
            int m = m0 + ty*8 + 2*ip + hhl;
            int b = m >> 10, s = m & 1023;
            float* dr = dst + (((size_t)(b * NHEAD + hh) * SEQ + s) << 6) + tx*4;
            float* src = hhl ? o1 : o0;
#pragma unroll
            for (int j = 0; j < 4; j++) dr[j] = src[j];
        }
    }
}

// GEMM 3 (TN): out[m,n] = sum_c att[m,c] * W[n,c]   grid (32, 16)
__global__ __launch_bounds__(256, 2) void gemm_out(const float* __restrict__ W, float* __restrict__ out)
{
    __shared__ __align__(16) float As[2][BK*SA];
    __shared__ __align__(16) float Bs[2][BK*SB];
    int tid = threadIdx.x;
    int tx = tid & 15, ty = tid >> 4;
    int m0 = blockIdx.x * BM;
    int n0 = blockIdx.y * BN;
    int ar0 = tid >> 2, ac0 = (tid & 3) * 4;
    int nl  = tid >> 2, cl  = (tid & 3) * 4;
    const float* Ag = g_att + (size_t)m0 * DMODEL;

    float4 a0 = *(const float4*)(Ag + (size_t)ar0*DMODEL + ac0);
    float4 a1 = *(const float4*)(Ag + (size_t)(ar0+64)*DMODEL + ac0);
    float4 b0 = *(const float4*)(W + (size_t)(n0+nl)*DMODEL + cl);
    STORE_A(0, a0, a1)
    Bs[0][(cl+0)*SB + nl] = b0.x; Bs[0][(cl+1)*SB + nl] = b0.y;
    Bs[0][(cl+2)*SB + nl] = b0.z; Bs[0][(cl+3)*SB + nl] = b0.w;
    __syncthreads();

    ACC_INIT
    const int nk = DMODEL / BK;
    for (int kb = 0; kb < nk; kb++) {
        int cur = kb & 1;
        float4 na0, na1, nb;
        if (kb + 1 < nk) {
            int c0 = (kb + 1) * BK;
            na0 = *(const float4*)(Ag + (size_t)ar0*DMODEL + c0 + ac0);
            na1 = *(const float4*)(Ag + (size_t)(ar0+64)*DMODEL + c0 + ac0);
            nb  = *(const float4*)(W + (size_t)(n0+nl)*DMODEL + c0 + cl);
        }
        GEMM_COMPUTE(cur)
        if (kb + 1 < nk) {
            int nxt = cur ^ 1;
            STORE_A(nxt, na0, na1)
            Bs[nxt][(cl+0)*SB + nl] = nb.x; Bs[nxt][(cl+1)*SB + nl] = nb.y;
            Bs[nxt][(cl+2)*SB + nl] = nb.z; Bs[nxt][(cl+3)*SB + nl] = nb.w;
        }
        __syncthreads();
    }
#pragma unroll
    for (int ip = 0; ip < 4; ip++) {
        float o0[4], o1[4];
#pragma unroll
        for (int j = 0; j < 4; j++) { UNPK2(o0[j], o1[j], accp[ip][j]) }
        float* d0 = out + (size_t)(m0 + ty*8 + 2*ip) * DMODEL + n0 + tx*4;
        float* d1 = d0 + DMODEL;
#pragma unroll
        for (int j = 0; j < 4; j++) { d0[j] = o0[j]; d1[j] = o1[j]; }
    }
}

// ---------------- flash attention: BQ=128, BK=64, 256 thr, 8x4 micro, packed f32x2 ------
// tx = tid&15 (col/dim group of 4), ty = tid>>4 (row group of 8)
#define SQT 132   // Qs [d][row]   64 x 132
#define SKT 68    // Ks [d][col]   64 x 68
#define SVT 68    // Vs [col][dim] 64 x 68
#define SPT 132   // Pt [col][row] 64 x 132
#define QS_OFF 0
#define KS_OFF (64*SQT)
#define VS_OFF (KS_OFF + 64*SKT)
#define PT_OFF (VS_OFF + 64*SVT)
#define ATT_SMEM ((PT_OFF + 64*SPT) * 4)

__global__ __launch_bounds__(256, 2) void attn_kernel()
{
    extern __shared__ __align__(16) float sm[];
    float* Qs = sm + QS_OFF;
    float* Ks = sm + KS_OFF;
    float* Vs = sm + VS_OFF;
    float* Pt = sm + PT_OFF;

    int qt = blockIdx.x, bh = blockIdx.y;
    const float* qb = g_q + (size_t)bh * SEQ * HDIM;
    const float* kb = g_k + (size_t)bh * SEQ * HDIM;
    const float* vb = g_v + (size_t)bh * SEQ * HDIM;

    int tid = threadIdx.x;
    int tx = tid & 15, ty = tid >> 4;
    int qr0 = qt << 7;

    // load Q tile transposed: Qs[d][r] ; 128x16 float4 = 8 per thread
#pragma unroll
    for (int it = 0; it < 8; it++) {
        int idx = tid + it * 256;
        int r = idx >> 4, d4 = idx & 15;
        float4 v = *(const float4*)(qb + (size_t)(qr0 + r) * 64 + d4 * 4);
        Qs[(d4*4+0)*SQT + r] = v.x;
        Qs[(d4*4+1)*SQT + r] = v.y;
        Qs[(d4*4+2)*SQT + r] = v.z;
        Qs[(d4*4+3)*SQT + r] = v.w;
    }

    float m_run[8], l_run[8];
#pragma unroll
    for (int i = 0; i < 8; i++) { m_run[i] = -3.0e38f; l_run[i] = 0.f; }
    u64 accO[4][4];
#pragma unroll
    for (int i = 0; i < 4; i++)
#pragma unroll
        for (int j = 0; j < 4; j++) accO[i][j] = 0ull;

    int ktmax = 2*qt + 1;
    for (int kt = 0; kt <= ktmax; kt++) {
        int kr0 = kt << 6;
        __syncthreads();   // previous PV done before overwriting K/V
        // load K transposed + V natural: 64x16 float4 each, 4 per thread
#pragma unroll
        for (int it = 0; it < 4; it++) {
            int idx = tid + it * 256;
            int r = idx >> 4, d4 = idx & 15;
            float4 kv = *(const float4*)(kb + (size_t)(kr0 + r) * 64 + d4 * 4);
            Ks[(d4*4+0)*SKT + r] = kv.x;
            Ks[(d4*4+1)*SKT + r] = kv.y;
            Ks[(d4*4+2)*SKT + r] = kv.z;
            Ks[(d4*4+3)*SKT + r] = kv.w;
            float4 vv = *(const float4*)(vb + (size_t)(kr0 + r) * 64 + d4 * 4);
            *(float4*)(Vs + r*SVT + d4*4) = vv;
        }
        __syncthreads();

        // ---- QK^T : sp[rowpair][col] packed over rows ----
        u64 sp[4][4];
#pragma unroll
        for (int i = 0; i < 4; i++)
#pragma unroll
            for (int j = 0; j < 4; j++) sp[i][j] = 0ull;
#pragma unroll 4
        for (int d = 0; d < 64; d++) {
            const float* qp = Qs + d*SQT + ty*8;
            ulonglong2 a01 = *(const ulonglong2*)qp;
            ulonglong2 a23 = *(const ulonglong2*)(qp + 4);
            float4 b4 = *(const float4*)(Ks + d*SKT + tx*4);
            u64 b0,b1,b2,b3;
            DUP2(b0,b4.x) DUP2(b1,b4.y) DUP2(b2,b4.z) DUP2(b3,b4.w)
            FMA2(sp[0][0],a01.x,b0) FMA2(sp[0][1],a01.x,b1) FMA2(sp[0][2],a01.x,b2) FMA2(sp[0][3],a01.x,b3)
            FMA2(sp[1][0],a01.y,b0) FMA2(sp[1][1],a01.y,b1) FMA2(sp[1][2],a01.y,b2) FMA2(sp[1][3],a01.y,b3)
            FMA2(sp[2][0],a23.x,b0) FMA2(sp[2][1],a23.x,b1) FMA2(sp[2][2],a23.x,b2) FMA2(sp[2][3],a23.x,b3)
            FMA2(sp[3][0],a23.y,b0) FMA2(sp[3][1],a23.y,b1) FMA2(sp[3][2],a23.y,b2) FMA2(sp[3][3],a23.y,b3)
        }

        bool need_mask = (kt >= 2*qt);
        // ---- softmax per row-pair ----
#pragma unroll
        for (int ip = 0; ip < 4; ip++) {
            float sA[4], sB[4];
#pragma unroll
            for (int j = 0; j < 4; j++) { UNPK2(sA[j], sB[j], sp[ip][j]) }
            int rA = qr0 + ty*8 + 2*ip, rB = rA + 1;
#pragma unroll
            for (int j = 0; j < 4; j++) {
                sA[j] *= 0.125f; sB[j] *= 0.125f;
                if (need_mask) {
                    int cg = kr0 + tx*4 + j;
                    if (cg > rA) sA[j] = -3.0e38f;
                    if (cg > rB) sB[j] = -3.0e38f;
                }
            }
            float mxA = fmaxf(fmaxf(sA[0],sA[1]), fmaxf(sA[2],sA[3]));
            float mxB = fmaxf(fmaxf(sB[0],sB[1]), fmaxf(sB[2],sB[3]));
#pragma unroll
            for (int o = 1; o <= 8; o <<= 1) {
                mxA = fmaxf(mxA, __shfl_xor_sync(0xffffffffu, mxA, o));
                mxB = fmaxf(mxB, __shfl_xor_sync(0xffffffffu, mxB, o));
            }
            float mnA = fmaxf(m_run[2*ip],   mxA);
            float mnB = fmaxf(m_run[2*ip+1], mxB);
            float cA = __expf(m_run[2*ip]   - mnA);
            float cB = __expf(m_run[2*ip+1] - mnB);
            float pA = 0.f, pB = 0.f;
#pragma unroll
            for (int j = 0; j < 4; j++) {
                sA[j] = __expf(sA[j] - mnA); pA += sA[j];
                sB[j] = __expf(sB[j] - mnB); pB += sB[j];
            }
#pragma unroll
            for (int o = 1; o <= 8; o <<= 1) {
                pA += __shfl_xor_sync(0xffffffffu, pA, o);
                pB += __shfl_xor_sync(0xffffffffu, pB, o);
            }
            l_run[2*ip]   = l_run[2*ip]   * cA + pA;  m_run[2*ip]   = mnA;
            l_run[2*ip+1] = l_run[2*ip+1] * cB + pB;  m_run[2*ip+1] = mnB;
            u64 cc; PACK2(cc, cA, cB)
#pragma unroll
            for (int j = 0; j < 4; j++) { MUL2(accO[ip][j], cc) }
            // store P transposed as row pairs: Pt[col][row]
#pragma unroll
            for (int j = 0; j < 4; j++)
                *(float2*)(Pt + (tx*4+j)*SPT + ty*8 + 2*ip) = make_float2(sA[j], sB[j]);
        }
        __syncthreads();

        // ---- PV : accO[rowpair][dim] += P[rowpair][c] * V[c][dim] ----
#pragma unroll 4
        for (int c = 0; c < 64; c++) {
            const float* pp = Pt + c*SPT + ty*8;
            ulonglong2 p01 = *(const ulonglong2*)pp;
            ulonglong2 p23 = *(const ulonglong2*)(pp + 4);
            float4 v4 = *(const float4*)(Vs + c*SVT + tx*4);
            u64 b0,b1,b2,b3;
            DUP2(b0,v4.x) DUP2(b1,v4.y) DUP2(b2,v4.z) DUP2(b3,v4.w)
            FMA2(accO[0][0],p01.x,b0) FMA2(accO[0][1],p01.x,b1) FMA2(accO[0][2],p01.x,b2) FMA2(accO[0][3],p01.x,b3)
            FMA2(accO[1][0],p01.y,b0) FMA2(accO[1][1],p01.y,b1) FMA2(accO[1][2],p01.y,b2) FMA2(accO[1][3],p01.y,b3)
            FMA2(accO[2][0],p23.x,b0) FMA2(accO[2][1],p23.x,b1) FMA2(accO[2][2],p23.x,b2) FMA2(accO[2][3],p23.x,b3)
            FMA2(accO[3][0],p23.y,b0) FMA2(accO[3][1],p23.y,b1) FMA2(accO[3][2],p23.y,b2) FMA2(accO[3][3],p23.y,b3)
        }
    }

    // epilogue: unpack, normalize, store to g_att [B*S, H*D]
    int b = bh >> 4, h = bh & 15;
#pragma unroll
    for (int ip = 0; ip < 4; ip++) {
        float o0[4], o1[4];
#pragma unroll
        for (int j = 0; j < 4; j++) { UNPK2(o0[j], o1[j], accO[ip][j]) }
        float i0 = 1.f / l_run[2*ip], i1 = 1.f / l_run[2*ip+1];
        int r0 = qr0 + ty*8 + 2*ip;
        float* d0 = g_att + (size_t)(b * SEQ + r0) * DMODEL + h*64 + tx*4;
        float* d1 = d0 + DMODEL;
        float4 w0 = make_float4(o0[0]*i0, o0[1]*i0, o0[2]*i0, o0[3]*i0);
        float4 w1 = make_float4(o1[0]*i1, o1[1]*i1, o1[2]*i1, o1[3]*i1);
        *(float4*)d0 = w0;
        *(float4*)d1 = w1;
    }
}

// ---------------- launch ----------------
extern "C" void kernel_launch(void* const* d_in, const int* in_sizes, int n_in,
                              void* d_out, int out_size)
{
    (void)n_in; (void)out_size;
    const float* x   = (const float*)d_in[0];
    const float* qU  = (const float*)d_in[1];
    const float* qV  = (const float*)d_in[2];
    const float* kU  = (const float*)d_in[3];
    const float* kV  = (const float*)d_in[4];
    const float* vU  = (const float*)d_in[5];
    const float* vV  = (const float*)d_in[6];
    const float* ql  = (const float*)d_in[7];
    const float* kl  = (const float*)d_in[8];
    const float* vl  = (const float*)d_in[9];
    const float* ow  = (const float*)d_in[10];
    const int*   tk  = (const int*)d_in[11];
    int P = in_sizes[7];

    cudaFuncSetAttribute(attn_kernel, cudaFuncAttributeMaxDynamicSharedMemorySize, ATT_SMEM);

    topk_kernel<<<1, 32>>>(ql, kl, vl, tk, P);

    dim3 blk(256);
    gemm_xu<<<dim3(32, 16, 3), blk>>>(x, qU, kU, vU);
    gemm_hv<<<dim3(32, 16, 3), blk>>>(qV, kV, vV);
    attn_kernel<<<dim3(SEQ / 128, BATCH * NHEAD), blk, ATT_SMEM>>>();
    gemm_out<<<dim3(32, 16), blk>>>(ow, (float*)d_out);
}

// round 8
// speedup vs baseline: 2.6966x; 1.0003x over previous
#include <cuda_runtime.h>
#include <cuda_bf16.h>
#include <cstdint>

#define DMODEL 1024
#define SEQ    1024
#define BATCH  4
#define NHEAD  16
#define HDIM   64
#define RNK    64
#define MROWS  (BATCH*SEQ)
#define PMAX   64

typedef unsigned long long u64;
typedef __nv_bfloat16 bf16;

// ---------------- packed fp32x2 helpers (attention) ----------------
#define FMA2(c,a,b) asm("fma.rn.f32x2 %0, %1, %2, %0;" : "+l"(c) : "l"(a), "l"(b));
#define MUL2(c,s)   asm("mul.rn.f32x2 %0, %0, %1;"     : "+l"(c) : "l"(s));
#define DUP2(d,f)   asm("mov.b64 %0, {%1, %1};" : "=l"(d) : "f"(f));
#define PACK2(d,lo,hi) asm("mov.b64 %0, {%1, %2};" : "=l"(d) : "f"(lo), "f"(hi));
#define UNPK2(lo,hi,v) asm("mov.b64 {%0, %1}, %2;" : "=f"(lo), "=f"(hi) : "l"(v));

// ---------------- HMMA helper (arch-agnostic sm_80+ PTX) ----------------
__device__ __forceinline__ void hmma(float* d, const uint32_t* a, const uint32_t* b) {
    asm volatile("mma.sync.aligned.m16n8k16.row.col.f32.bf16.bf16.f32 "
        "{%0,%1,%2,%3}, {%4,%5,%6,%7}, {%8,%9}, {%0,%1,%2,%3};"
        : "+f"(d[0]), "+f"(d[1]), "+f"(d[2]), "+f"(d[3])
        : "r"(a[0]), "r"(a[1]), "r"(a[2]), "r"(a[3]), "r"(b[0]), "r"(b[1]));
}

// ---------------- device scratch (uint4/float4-typed: forced 16B alignment) ------------
// NOTE: these symbols are ONLY ever referenced from device code (never as kernel args).
__device__ uint4  g_x_hi_r [(size_t)MROWS*1024/8];
__device__ uint4  g_x_lo_r [(size_t)MROWS*1024/8];
__device__ uint4  g_w_hi_r [(size_t)1024*1024/8];
__device__ uint4  g_w_lo_r [(size_t)1024*1024/8];
__device__ uint4  g_ut_hi_r[(size_t)3*16*64*1024/8];
__device__ uint4  g_ut_lo_r[(size_t)3*16*64*1024/8];
__device__ uint4  g_vt_hi_r[(size_t)3*1024*1024/8];
__device__ uint4  g_vt_lo_r[(size_t)3*1024*1024/8];
__device__ uint4  g_h_hi_r [(size_t)3*MROWS*1024/8];
__device__ uint4  g_h_lo_r [(size_t)3*MROWS*1024/8];
__device__ uint4  g_att_hi_r[(size_t)MROWS*1024/8];
__device__ uint4  g_att_lo_r[(size_t)MROWS*1024/8];
__device__ float4 g_att_r [(size_t)MROWS*1024/4];
__device__ float4 g_q_r   [(size_t)BATCH*NHEAD*SEQ*HDIM/4];
__device__ float4 g_k_r   [(size_t)BATCH*NHEAD*SEQ*HDIM/4];
__device__ float4 g_v_r   [(size_t)BATCH*NHEAD*SEQ*HDIM/4];
__device__ float g_tw[3][PMAX];
__device__ int   g_ti[3][PMAX];
__device__ int   g_K;

#define g_x_hi  ((bf16*)g_x_hi_r)
#define g_x_lo  ((bf16*)g_x_lo_r)
#define g_w_hi  ((bf16*)g_w_hi_r)
#define g_w_lo  ((bf16*)g_w_lo_r)
#define g_ut_hi ((bf16*)g_ut_hi_r)
#define g_ut_lo ((bf16*)g_ut_lo_r)
#define g_vt_hi ((bf16*)g_vt_hi_r)
#define g_vt_lo ((bf16*)g_vt_lo_r)
#define g_h_hi  ((bf16*)g_h_hi_r)
#define g_h_lo  ((bf16*)g_h_lo_r)
#define g_att_hi ((bf16*)g_att_hi_r)
#define g_att_lo ((bf16*)g_att_lo_r)
#define g_att   ((float*)g_att_r)
#define g_q     ((float*)g_q_r)
#define g_k     ((float*)g_k_r)
#define g_v     ((float*)g_v_r)

// ---------------- top-k gating ----------------
__global__ void topk_kernel(const float* __restrict__ ql, const float* __restrict__ kl,
                            const float* __restrict__ vl, const int* __restrict__ tkp, int P)
{
    if (threadIdx.x != 0) return;
    int K = *tkp; if (K > P) K = P; if (K < 1) K = 1;
    g_K = K;
    const float* ls[3] = {ql, kl, vl};
    for (int p = 0; p < 3; p++) {
        const float* lg = ls[p];
        bool used[PMAX];
        for (int i = 0; i < P; i++) used[i] = false;
        for (int t = 0; t < K; t++) {
            int best = 0; float bv = -3.4e38f;
            for (int i = 0; i < P; i++)
                if (!used[i] && lg[i] > bv) { bv = lg[i]; best = i; }
            used[best] = true;
            g_ti[p][t] = best;
        }
        float mx = -3.4e38f;
        for (int t = 0; t < K; t++) { float v = lg[g_ti[p][t]]; if (v > mx) mx = v; }
        float ssum = 0.f, w[PMAX];
        for (int t = 0; t < K; t++) { w[t] = expf(lg[g_ti[p][t]] - mx); ssum += w[t]; }
        for (int t = 0; t < K; t++) g_tw[p][t] = w[t] / ssum;
    }
}

// ---------------- bf16 split conversions (globals referenced from device only) ----------
__device__ __forceinline__ void split1(float v, bf16& h, bf16& l) {
    h = __float2bfloat16(v);
    l = __float2bfloat16(v - __bfloat162float(h));
}

__global__ void conv_x(const float* __restrict__ src)
{
    int i = blockIdx.x * blockDim.x + threadIdx.x;   // 1M float4s exactly
    float4 v = ((const float4*)src)[i];
    bf16 h0,h1,h2,h3,l0,l1,l2,l3;
    split1(v.x,h0,l0); split1(v.y,h1,l1); split1(v.z,h2,l2); split1(v.w,h3,l3);
    g_x_hi[4*i+0]=h0; g_x_hi[4*i+1]=h1; g_x_hi[4*i+2]=h2; g_x_hi[4*i+3]=h3;
    g_x_lo[4*i+0]=l0; g_x_lo[4*i+1]=l1; g_x_lo[4*i+2]=l2; g_x_lo[4*i+3]=l3;
}

__global__ void conv_w(const float* __restrict__ src)
{
    int i = blockIdx.x * blockDim.x + threadIdx.x;   // 256K float4s exactly
    float4 v = ((const float4*)src)[i];
    bf16 h0,h1,h2,h3,l0,l1,l2,l3;
    split1(v.x,h0,l0); split1(v.y,h1,l1); split1(v.z,h2,l2); split1(v.w,h3,l3);
    g_w_hi[4*i+0]=h0; g_w_hi[4*i+1]=h1; g_w_hi[4*i+2]=h2; g_w_hi[4*i+3]=h3;
    g_w_lo[4*i+0]=l0; g_w_lo[4*i+1]=l1; g_w_lo[4*i+2]=l2; g_w_lo[4*i+3]=l3;
}

__global__ void conv_att()
{
    int i = blockIdx.x * blockDim.x + threadIdx.x;   // 1M float4s exactly
    float4 v = g_att_r[i];
    bf16 h0,h1,h2,h3,l0,l1,l2,l3;
    split1(v.x,h0,l0); split1(v.y,h1,l1); split1(v.z,h2,l2); split1(v.w,h3,l3);
    g_att_hi[4*i+0]=h0; g_att_hi[4*i+1]=h1; g_att_hi[4*i+2]=h2; g_att_hi[4*i+3]=h3;
    g_att_lo[4*i+0]=l0; g_att_lo[4*i+1]=l1; g_att_lo[4*i+2]=l2; g_att_lo[4*i+3]=l3;
}

// Ut[p][kc][j][c] = U[prim][c][j]   grid (3, 16, 8)
__global__ __launch_bounds__(256) void conv_ut(const float* __restrict__ qU,
    const float* __restrict__ kU, const float* __restrict__ vU)
{
    int p = blockIdx.x, kc = blockIdx.y;
    if (kc >= g_K) return;
    const float* U = p == 0 ? qU : p == 1 ? kU : vU;
    const float* Up = U + (size_t)g_ti[p][kc] * 65536;
    size_t base = (size_t)(p * 16 + kc) * 65536;
    int i0 = blockIdx.z * 8192;
    for (int idx = i0 + threadIdx.x; idx < i0 + 8192; idx += 256) {
        int j = idx >> 10, c = idx & 1023;
        bf16 h, l; split1(Up[c * 64 + j], h, l);
        g_ut_hi[base + idx] = h;
        g_ut_lo[base + idx] = l;
    }
}

// Vt[p][n][kc*64+j] = V[prim(kc)][j][n]   grid (3, 16, 8)
__global__ __launch_bounds__(256) void conv_vt(const float* __restrict__ qV,
    const float* __restrict__ kV, const float* __restrict__ vV)
{
    int p = blockIdx.x, kc = blockIdx.y;
    if (kc >= g_K) return;
    const float* V = p == 0 ? qV : p == 1 ? kV : vV;
    const float* Vp = V + (size_t)g_ti[p][kc] * 65536;
    int i0 = blockIdx.z * 8192;
    for (int idx = i0 + threadIdx.x; idx < i0 + 8192; idx += 256) {
        int n = idx >> 6, j = idx & 63;
        bf16 h, l; split1(Vp[(size_t)j * 1024 + n], h, l);
        size_t dst = ((size_t)p * 1024 + n) * 1024 + kc * 64 + j;
        g_vt_hi[dst] = h;
        g_vt_lo[dst] = l;
    }
}

// ---------------- HMMA GEMM: 128x64 tile, BK=32, 256 thr, direct-LDS fragments ----------
// smem row stride 40 bf16 (80 B, 16B-aligned rows); fragment 4B reads: banks
// (gid*20 + tig) mod 32 all distinct -> conflict-free. Double buffer, 1 sync/chunk.
#define SAS 40
#define ASZE (128*SAS)
#define BSZE (64*SAS)

#define MMA_BODY(AhP, AlP, BhP, BlP, Abase, Bbase, PST, NST)                          \
    __shared__ __align__(16) bf16 shA[2][ASZE];                                       \
    __shared__ __align__(16) bf16 shB[2][BSZE];                                       \
    int tid = threadIdx.x, w = tid >> 5, l = tid & 31;                                \
    int gid = l >> 2, tig = l & 3;                                                    \
    int lr = tid >> 2, lc = (tid & 3) * 8;                                            \
    float acc[8][4];                                                                  \
    _Pragma("unroll") for (int i_ = 0; i_ < 8; i_++)                                  \
    _Pragma("unroll") for (int j_ = 0; j_ < 4; j_++) acc[i_][j_] = 0.f;               \
    uint4 A0, A1, B0;                                                                 \
    {                                                                                 \
        const bf16* Ap = (AhP); const bf16* Bp = (BhP);                               \
        A0 = *(const uint4*)(Ap + (Abase) + (size_t)lr * 1024 + lc);                  \
        A1 = *(const uint4*)(Ap + (Abase) + (size_t)(lr + 64) * 1024 + lc);           \
        B0 = *(const uint4*)(Bp + (Bbase) + (size_t)lr * 1024 + lc);                  \
    }                                                                                 \
    *(uint4*)&shA[0][lr * SAS + lc]        = A0;                                      \
    *(uint4*)&shA[0][(lr + 64) * SAS + lc] = A1;                                      \
    *(uint4*)&shB[0][lr * SAS + lc]        = B0;                                      \
    __syncthreads();                                                                  \
    for (int c = 0; c < (NST); c++) {                                                 \
        int cur = c & 1;                                                              \
        if (c + 1 < (NST)) {                                                          \
            int s_ = 0, kk = c + 1;                                                   \
            if (kk >= (PST)) { s_ = 1; kk -= (PST); }                                 \
            if (kk >= (PST)) { s_ = 2; kk -= (PST); }                                 \
            const bf16* Ap = (s_ == 1) ? (AlP) : (AhP);                               \
            const bf16* Bp = (s_ == 2) ? (BlP) : (BhP);                               \
            size_t ko = (size_t)kk * 32;                                              \
            A0 = *(const uint4*)(Ap + (Abase) + (size_t)lr * 1024 + ko + lc);         \
            A1 = *(const uint4*)(Ap + (Abase) + (size_t)(lr + 64) * 1024 + ko + lc);  \
            B0 = *(const uint4*)(Bp + (Bbase) + (size_t)lr * 1024 + ko + lc);         \
        }                                                                             \
        _Pragma("unroll")                                                             \
        for (int k16 = 0; k16 < 32; k16 += 16) {                                      \
            uint32_t av[4];                                                           \
            av[0] = *(const uint32_t*)&shA[cur][(w*16 + gid)     * SAS + 2*tig     + k16]; \
            av[1] = *(const uint32_t*)&shA[cur][(w*16 + gid + 8) * SAS + 2*tig     + k16]; \
            av[2] = *(const uint32_t*)&shA[cur][(w*16 + gid)     * SAS + 2*tig + 8 + k16]; \
            av[3] = *(const uint32_t*)&shA[cur][(w*16 + gid + 8) * SAS + 2*tig + 8 + k16]; \
            _Pragma("unroll")                                                         \
            for (int nt = 0; nt < 8; nt++) {                                          \
                uint32_t bv[2];                                                       \
                bv[0] = *(const uint32_t*)&shB[cur][(nt*8 + gid) * SAS + 2*tig     + k16]; \
                bv[1] = *(const uint32_t*)&shB[cur][(nt*8 + gid) * SAS + 2*tig + 8 + k16]; \
                hmma(acc[nt], av, bv);                                                \
            }                                                                         \
        }                                                                             \
        if (c + 1 < (NST)) {                                                          \
            int nxt = cur ^ 1;                                                        \
            *(uint4*)&shA[nxt][lr * SAS + lc]        = A0;                            \
            *(uint4*)&shA[nxt][(lr + 64) * SAS + lc] = A1;                            \
            *(uint4*)&shB[nxt][lr * SAS + lc]        = B0;                            \
        }                                                                             \
        __syncthreads();                                                              \
    }

// GEMM 1: h[p][m][kc*64+n] = tw * x[m,:] @ U[prim]    grid (32, 16, 3)
__global__ __launch_bounds__(256, 2) void mma_gemm_xu()
{
    int proj = blockIdx.z, kc = blockIdx.y;
    if (kc >= g_K) return;
    int m0 = blockIdx.x << 7;
    const bf16* Bh = g_ut_hi + (size_t)(proj * 16 + kc) * 65536;
    const bf16* Bl = g_ut_lo + (size_t)(proj * 16 + kc) * 65536;
    float tw = g_tw[proj][kc];
    MMA_BODY(g_x_hi, g_x_lo, Bh, Bl, (size_t)m0 * 1024, 0, 32, 96)
    int row = m0 + w * 16 + gid, lp = tig * 2;
    size_t b0_ = ((size_t)proj * MROWS + row) * 1024 + kc * 64;
    size_t b1_ = b0_ + (size_t)8 * 1024;
#pragma unroll
    for (int nt = 0; nt < 8; nt++) {
        bf16 h0, l0, h1, l1;
        split1(tw * acc[nt][0], h0, l0); split1(tw * acc[nt][1], h1, l1);
        g_h_hi[b0_ + nt*8 + lp] = h0; g_h_hi[b0_ + nt*8 + lp + 1] = h1;
        g_h_lo[b0_ + nt*8 + lp] = l0; g_h_lo[b0_ + nt*8 + lp + 1] = l1;
        split1(tw * acc[nt][2], h0, l0); split1(tw * acc[nt][3], h1, l1);
        g_h_hi[b1_ + nt*8 + lp] = h0; g_h_hi[b1_ + nt*8 + lp + 1] = h1;
        g_h_lo[b1_ + nt*8 + lp] = l0; g_h_lo[b1_ + nt*8 + lp + 1] = l1;
    }
}

// GEMM 2: qkv = h @ Vt -> [B,H,S,D] fp32    grid (32, 16, 3)
__global__ __launch_bounds__(256, 2) void mma_gemm_hv()
{
    int proj = blockIdx.z, hh = blockIdx.y;
    int m0 = blockIdx.x << 7;
    int pst = g_K * 2;
    int nst = 3 * pst;
    const bf16* Ah = g_h_hi + (size_t)proj * MROWS * 1024;
    const bf16* Al = g_h_lo + (size_t)proj * MROWS * 1024;
    const bf16* Bh = g_vt_hi + ((size_t)proj * 1024 + (hh << 6)) * 1024;
    const bf16* Bl = g_vt_lo + ((size_t)proj * 1024 + (hh << 6)) * 1024;
    MMA_BODY(Ah, Al, Bh, Bl, (size_t)m0 * 1024, 0, pst, nst)
    float* dst = proj == 0 ? g_q : proj == 1 ? g_k : g_v;
    int lp = tig * 2;
    int m = m0 + w * 16 + gid;
    int bb = m >> 10, sq = m & 1023;
    float* d0 = dst + (((size_t)(bb * NHEAD + hh) * SEQ + sq) << 6);
    float* d1 = d0 + (8 << 6);
#pragma unroll
    for (int nt = 0; nt < 8; nt++) {
        d0[nt*8 + lp] = acc[nt][0]; d0[nt*8 + lp + 1] = acc[nt][1];
        d1[nt*8 + lp] = acc[nt][2]; d1[nt*8 + lp + 1] = acc[nt][3];
    }
}

// GEMM 3: out = att @ W^T    grid (32, 16)
__global__ __launch_bounds__(256, 2) void mma_gemm_out(float* __restrict__ out)
{
    int n0 = blockIdx.y << 6;
    int m0 = blockIdx.x << 7;
    MMA_BODY(g_att_hi, g_att_lo, g_w_hi, g_w_lo, (size_t)m0 * 1024, (size_t)n0 * 1024, 32, 96)
    int lp = tig * 2;
    int row = m0 + w * 16 + gid;
    float* d0 = out + (size_t)row * 1024 + n0;
    float* d1 = d0 + (size_t)8 * 1024;
#pragma unroll
    for (int nt = 0; nt < 8; nt++) {
        d0[nt*8 + lp] = acc[nt][0]; d0[nt*8 + lp + 1] = acc[nt][1];
        d1[nt*8 + lp] = acc[nt][2]; d1[nt*8 + lp + 1] = acc[nt][3];
    }
}

// ---------------- flash attention (round-3 proven, fp32 output) ----------------
#define SQT 132
#define SKT 68
#define SVT 68
#define SPT 132
#define QS_OFF 0
#define KS_OFF (64*SQT)
#define VS_OFF (KS_OFF + 64*SKT)
#define PT_OFF (VS_OFF + 64*SVT)
#define ATT_SMEM ((PT_OFF + 64*SPT) * 4)

__global__ __launch_bounds__(256, 2) void attn_kernel()
{
    extern __shared__ __align__(16) float sm[];
    float* Qs = sm + QS_OFF;
    float* Ks = sm + KS_OFF;
    float* Vs = sm + VS_OFF;
    float* Pt = sm + PT_OFF;

    int qt = blockIdx.x, bh = blockIdx.y;
    const float* qb = g_q + (size_t)bh * SEQ * HDIM;
    const float* kb = g_k + (size_t)bh * SEQ * HDIM;
    const float* vb = g_v + (size_t)bh * SEQ * HDIM;

    int tid = threadIdx.x;
    int tx = tid & 15, ty = tid >> 4;
    int qr0 = qt << 7;

#pragma unroll
    for (int it = 0; it < 8; it++) {
        int idx = tid + it * 256;
        int r = idx >> 4, d4 = idx & 15;
        float4 v = *(const float4*)(qb + (size_t)(qr0 + r) * 64 + d4 * 4);
        Qs[(d4*4+0)*SQT + r] = v.x;
        Qs[(d4*4+1)*SQT + r] = v.y;
        Qs[(d4*4+2)*SQT + r] = v.z;
        Qs[(d4*4+3)*SQT + r] = v.w;
    }

    float m_run[8], l_run[8];
#pragma unroll
    for (int i = 0; i < 8; i++) { m_run[i] = -3.0e38f; l_run[i] = 0.f; }
    u64 accO[4][4];
#pragma unroll
    for (int i = 0; i < 4; i++)
#pragma unroll
        for (int j = 0; j < 4; j++) accO[i][j] = 0ull;

    int ktmax = 2*qt + 1;
    for (int kt = 0; kt <= ktmax; kt++) {
        int kr0 = kt << 6;
        __syncthreads();
#pragma unroll
        for (int it = 0; it < 4; it++) {
            int idx = tid + it * 256;
            int r = idx >> 4, d4 = idx & 15;
            float4 kv = *(const float4*)(kb + (size_t)(kr0 + r) * 64 + d4 * 4);
            Ks[(d4*4+0)*SKT + r] = kv.x;
            Ks[(d4*4+1)*SKT + r] = kv.y;
            Ks[(d4*4+2)*SKT + r] = kv.z;
            Ks[(d4*4+3)*SKT + r] = kv.w;
            float4 vv = *(const float4*)(vb + (size_t)(kr0 + r) * 64 + d4 * 4);
            *(float4*)(Vs + r*SVT + d4*4) = vv;
        }
        __syncthreads();

        u64 sp[4][4];
#pragma unroll
        for (int i = 0; i < 4; i++)
#pragma unroll
            for (int j = 0; j < 4; j++) sp[i][j] = 0ull;
#pragma unroll 4
        for (int d = 0; d < 64; d++) {
            const float* qp = Qs + d*SQT + ty*8;
            ulonglong2 a01 = *(const ulonglong2*)qp;
            ulonglong2 a23 = *(const ulonglong2*)(qp + 4);
            float4 b4 = *(const float4*)(Ks + d*SKT + tx*4);
            u64 b0,b1,b2,b3;
            DUP2(b0,b4.x) DUP2(b1,b4.y) DUP2(b2,b4.z) DUP2(b3,b4.w)
            FMA2(sp[0][0],a01.x,b0) FMA2(sp[0][1],a01.x,b1) FMA2(sp[0][2],a01.x,b2) FMA2(sp[0][3],a01.x,b3)
            FMA2(sp[1][0],a01.y,b0) FMA2(sp[1][1],a01.y,b1) FMA2(sp[1][2],a01.y,b2) FMA2(sp[1][3],a01.y,b3)
            FMA2(sp[2][0],a23.x,b0) FMA2(sp[2][1],a23.x,b1) FMA2(sp[2][2],a23.x,b2) FMA2(sp[2][3],a23.x,b3)
            FMA2(sp[3][0],a23.y,b0) FMA2(sp[3][1],a23.y,b1) FMA2(sp[3][2],a23.y,b2) FMA2(sp[3][3],a23.y,b3)
        }

        bool need_mask = (kt >= 2*qt);
#pragma unroll
        for (int ip = 0; ip < 4; ip++) {
            float sA[4], sB[4];
#pragma unroll
            for (int j = 0; j < 4; j++) { UNPK2(sA[j], sB[j], sp[ip][j]) }
            int rA = qr0 + ty*8 + 2*ip, rB = rA + 1;
#pragma unroll
            for (int j = 0; j < 4; j++) {
                sA[j] *= 0.125f; sB[j] *= 0.125f;
                if (need_mask) {
                    int cg = kr0 + tx*4 + j;
                    if (cg > rA) sA[j] = -3.0e38f;
                    if (cg > rB) sB[j] = -3.0e38f;
                }
            }
            float mxA = fmaxf(fmaxf(sA[0],sA[1]), fmaxf(sA[2],sA[3]));
            float mxB = fmaxf(fmaxf(sB[0],sB[1]), fmaxf(sB[2],sB[3]));
#pragma unroll
            for (int o = 1; o <= 8; o <<= 1) {
                mxA = fmaxf(mxA, __shfl_xor_sync(0xffffffffu, mxA, o));
                mxB = fmaxf(mxB, __shfl_xor_sync(0xffffffffu, mxB, o));
            }
            float mnA = fmaxf(m_run[2*ip],   mxA);
            float mnB = fmaxf(m_run[2*ip+1], mxB);
            float cA = __expf(m_run[2*ip]   - mnA);
            float cB = __expf(m_run[2*ip+1] - mnB);
            float pA = 0.f, pB = 0.f;
#pragma unroll
            for (int j = 0; j < 4; j++) {
                sA[j] = __expf(sA[j] - mnA); pA += sA[j];
                sB[j] = __expf(sB[j] - mnB); pB += sB[j];
            }
#pragma unroll
            for (int o = 1; o <= 8; o <<= 1) {
                pA += __shfl_xor_sync(0xffffffffu, pA, o);
                pB += __shfl_xor_sync(0xffffffffu, pB, o);
            }
            l_run[2*ip]   = l_run[2*ip]   * cA + pA;  m_run[2*ip]   = mnA;
            l_run[2*ip+1] = l_run[2*ip+1] * cB + pB;  m_run[2*ip+1] = mnB;
            u64 cc; PACK2(cc, cA, cB)
#pragma unroll
            for (int j = 0; j < 4; j++) { MUL2(accO[ip][j], cc) }
#pragma unroll
            for (int j = 0; j < 4; j++)
                *(float2*)(Pt + (tx*4+j)*SPT + ty*8 + 2*ip) = make_float2(sA[j], sB[j]);
        }
        __syncthreads();

#pragma unroll 4
        for (int c = 0; c < 64; c++) {
            const float* pp = Pt + c*SPT + ty*8;
            ulonglong2 p01 = *(const ulonglong2*)pp;
            ulonglong2 p23 = *(const ulonglong2*)(pp + 4);
            float4 v4 = *(const float4*)(Vs + c*SVT + tx*4);
            u64 b0,b1,b2,b3;
            DUP2(b0,v4.x) DUP2(b1,v4.y) DUP2(b2,v4.z) DUP2(b3,v4.w)
            FMA2(accO[0][0],p01.x,b0) FMA2(accO[0][1],p01.x,b1) FMA2(accO[0][2],p01.x,b2) FMA2(accO[0][3],p01.x,b3)
            FMA2(accO[1][0],p01.y,b0) FMA2(accO[1][1],p01.y,b1) FMA2(accO[1][2],p01.y,b2) FMA2(accO[1][3],p01.y,b3)
            FMA2(accO[2][0],p23.x,b0) FMA2(accO[2][1],p23.x,b1) FMA2(accO[2][2],p23.x,b2) FMA2(accO[2][3],p23.x,b3)
            FMA2(accO[3][0],p23.y,b0) FMA2(accO[3][1],p23.y,b1) FMA2(accO[3][2],p23.y,b2) FMA2(accO[3][3],p23.y,b3)
        }
    }

    // epilogue: normalize, store fp32 g_att [B*S, H*D]
    int b = bh >> 4, h = bh & 15;
#pragma unroll
    for (int ip = 0; ip < 4; ip++) {
        float o0[4], o1[4];
#pragma unroll
        for (int j = 0; j < 4; j++) { UNPK2(o0[j], o1[j], accO[ip][j]) }
        float i0 = 1.f / l_run[2*ip], i1 = 1.f / l_run[2*ip+1];
        int r0 = qr0 + ty*8 + 2*ip;
        float* d0 = g_att + (size_t)(b * SEQ + r0) * DMODEL + h*64 + tx*4;
        float* d1 = d0 + DMODEL;
        *(float4*)d0 = make_float4(o0[0]*i0, o0[1]*i0, o0[2]*i0, o0[3]*i0);
        *(float4*)d1 = make_float4(o1[0]*i1, o1[1]*i1, o1[2]*i1, o1[3]*i1);
    }
}

// ---------------- launch ----------------
extern "C" void kernel_launch(void* const* d_in, const int* in_sizes, int n_in,
                              void* d_out, int out_size)
{
    (void)n_in; (void)out_size;
    const float* x   = (const float*)d_in[0];
    const float* qU  = (const float*)d_in[1];
    const float* qV  = (const float*)d_in[2];
    const float* kU  = (const float*)d_in[3];
    const float* kV  = (const float*)d_in[4];
    const float* vU  = (const float*)d_in[5];
    const float* vV  = (const float*)d_in[6];
    const float* ql  = (const float*)d_in[7];
    const float* kl  = (const float*)d_in[8];
    const float* vl  = (const float*)d_in[9];
    const float* ow  = (const float*)d_in[10];
    const int*   tk  = (const int*)d_in[11];
    int P = in_sizes[7];

    cudaFuncSetAttribute(attn_kernel, cudaFuncAttributeMaxDynamicSharedMemorySize, ATT_SMEM);

    topk_kernel<<<1, 32>>>(ql, kl, vl, tk, P);

    conv_x<<<4096, 256>>>(x);
    conv_w<<<1024, 256>>>(ow);
    conv_ut<<<dim3(3, 16, 8), 256>>>(qU, kU, vU);
    conv_vt<<<dim3(3, 16, 8), 256>>>(qV, kV, vV);

    mma_gemm_xu<<<dim3(32, 16, 3), 256>>>();
    mma_gemm_hv<<<dim3(32, 16, 3), 256>>>();
    attn_kernel<<<dim3(SEQ / 128, BATCH * NHEAD), 256, ATT_SMEM>>>();
    conv_att<<<4096, 256>>>();
    mma_gemm_out<<<dim3(32, 16), 256>>>((float*)d_out);
}

// round 9
// speedup vs baseline: 2.8443x; 1.0548x over previous
#include <cuda_runtime.h>
#include <cuda_bf16.h>
#include <cstdint>

#define DMODEL 1024
#define SEQ    1024
#define BATCH  4
#define NHEAD  16
#define HDIM   64
#define RNK    64
#define MROWS  (BATCH*SEQ)
#define PMAX   64

typedef unsigned long long u64;
typedef __nv_bfloat16 bf16;

// ---------------- packed fp32x2 helpers (attention) ----------------
#define FMA2(c,a,b) asm("fma.rn.f32x2 %0, %1, %2, %0;" : "+l"(c) : "l"(a), "l"(b));
#define MUL2(c,s)   asm("mul.rn.f32x2 %0, %0, %1;"     : "+l"(c) : "l"(s));
#define DUP2(d,f)   asm("mov.b64 %0, {%1, %1};" : "=l"(d) : "f"(f));
#define PACK2(d,lo,hi) asm("mov.b64 %0, {%1, %2};" : "=l"(d) : "f"(lo), "f"(hi));
#define UNPK2(lo,hi,v) asm("mov.b64 {%0, %1}, %2;" : "=f"(lo), "=f"(hi) : "l"(v));

// ---------------- warp MMA helpers (arch-agnostic sm_80+ PTX) ----------------
__device__ __forceinline__ uint32_t smem_u32(const void* p) {
    uint32_t a;
    asm("{ .reg .u64 t; cvta.to.shared.u64 t, %1; cvt.u32.u64 %0, t; }" : "=r"(a) : "l"(p));
    return a;
}
__device__ __forceinline__ void ldsm4(uint32_t* r, uint32_t addr) {
    asm volatile("ldmatrix.sync.aligned.m8n8.x4.shared.b16 {%0,%1,%2,%3}, [%4];"
        : "=r"(r[0]), "=r"(r[1]), "=r"(r[2]), "=r"(r[3]) : "r"(addr));
}
__device__ __forceinline__ void hmma(float* d, const uint32_t* a, const uint32_t* b) {
    asm volatile("mma.sync.aligned.m16n8k16.row.col.f32.bf16.bf16.f32 "
        "{%0,%1,%2,%3}, {%4,%5,%6,%7}, {%8,%9}, {%0,%1,%2,%3};"
        : "+f"(d[0]), "+f"(d[1]), "+f"(d[2]), "+f"(d[3])
        : "r"(a[0]), "r"(a[1]), "r"(a[2]), "r"(a[3]), "r"(b[0]), "r"(b[1]));
}

// ---------------- device scratch (uint4/float4-typed: forced 16B alignment) ------------
// NOTE: these symbols are ONLY ever referenced from device code (never as kernel args).
__device__ uint4  g_x_hi_r [(size_t)MROWS*1024/8];
__device__ uint4  g_x_lo_r [(size_t)MROWS*1024/8];
__device__ uint4  g_w_hi_r [(size_t)1024*1024/8];
__device__ uint4  g_w_lo_r [(size_t)1024*1024/8];
__device__ uint4  g_ut_hi_r[(size_t)3*16*64*1024/8];
__device__ uint4  g_ut_lo_r[(size_t)3*16*64*1024/8];
__device__ uint4  g_vt_hi_r[(size_t)3*1024*1024/8];
__device__ uint4  g_vt_lo_r[(size_t)3*1024*1024/8];
__device__ uint4  g_h_hi_r [(size_t)3*MROWS*1024/8];
__device__ uint4  g_h_lo_r [(size_t)3*MROWS*1024/8];
__device__ uint4  g_att_hi_r[(size_t)MROWS*1024/8];
__device__ uint4  g_att_lo_r[(size_t)MROWS*1024/8];
__device__ float4 g_att_r [(size_t)MROWS*1024/4];
__device__ float4 g_q_r   [(size_t)BATCH*NHEAD*SEQ*HDIM/4];
__device__ float4 g_k_r   [(size_t)BATCH*NHEAD*SEQ*HDIM/4];
__device__ float4 g_v_r   [(size_t)BATCH*NHEAD*SEQ*HDIM/4];
__device__ float g_tw[3][PMAX];
__device__ int   g_ti[3][PMAX];
__device__ int   g_K;

#define g_x_hi  ((bf16*)g_x_hi_r)
#define g_x_lo  ((bf16*)g_x_lo_r)
#define g_w_hi  ((bf16*)g_w_hi_r)
#define g_w_lo  ((bf16*)g_w_lo_r)
#define g_ut_hi ((bf16*)g_ut_hi_r)
#define g_ut_lo ((bf16*)g_ut_lo_r)
#define g_vt_hi ((bf16*)g_vt_hi_r)
#define g_vt_lo ((bf16*)g_vt_lo_r)
#define g_h_hi  ((bf16*)g_h_hi_r)
#define g_h_lo  ((bf16*)g_h_lo_r)
#define g_att_hi ((bf16*)g_att_hi_r)
#define g_att_lo ((bf16*)g_att_lo_r)
#define g_att   ((float*)g_att_r)
#define g_q     ((float*)g_q_r)
#define g_k     ((float*)g_k_r)
#define g_v     ((float*)g_v_r)

// ---------------- top-k gating ----------------
__global__ void topk_kernel(const float* __restrict__ ql, const float* __restrict__ kl,
                            const float* __restrict__ vl, const int* __restrict__ tkp, int P)
{
    if (threadIdx.x != 0) return;
    int K = *tkp; if (K > P) K = P; if (K < 1) K = 1;
    g_K = K;
    const float* ls[3] = {ql, kl, vl};
    for (int p = 0; p < 3; p++) {
        const float* lg = ls[p];
        bool used[PMAX];
        for (int i = 0; i < P; i++) used[i] = false;
        for (int t = 0; t < K; t++) {
            int best = 0; float bv = -3.4e38f;
            for (int i = 0; i < P; i++)
                if (!used[i] && lg[i] > bv) { bv = lg[i]; best = i; }
            used[best] = true;
            g_ti[p][t] = best;
        }
        float mx = -3.4e38f;
        for (int t = 0; t < K; t++) { float v = lg[g_ti[p][t]]; if (v > mx) mx = v; }
        float ssum = 0.f, w[PMAX];
        for (int t = 0; t < K; t++) { w[t] = expf(lg[g_ti[p][t]] - mx); ssum += w[t]; }
        for (int t = 0; t < K; t++) g_tw[p][t] = w[t] / ssum;
    }
}

// ---------------- bf16 split conversions (globals referenced from device only) ----------
__device__ __forceinline__ void split1(float v, bf16& h, bf16& l) {
    h = __float2bfloat16(v);
    l = __float2bfloat16(v - __bfloat162float(h));
}

__global__ void conv_x(const float* __restrict__ src)
{
    int i = blockIdx.x * blockDim.x + threadIdx.x;   // 1M float4s exactly
    float4 v = ((const float4*)src)[i];
    bf16 h0,h1,h2,h3,l0,l1,l2,l3;
    split1(v.x,h0,l0); split1(v.y,h1,l1); split1(v.z,h2,l2); split1(v.w,h3,l3);
    g_x_hi[4*i+0]=h0; g_x_hi[4*i+1]=h1; g_x_hi[4*i+2]=h2; g_x_hi[4*i+3]=h3;
    g_x_lo[4*i+0]=l0; g_x_lo[4*i+1]=l1; g_x_lo[4*i+2]=l2; g_x_lo[4*i+3]=l3;
}

__global__ void conv_w(const float* __restrict__ src)
{
    int i = blockIdx.x * blockDim.x + threadIdx.x;   // 256K float4s exactly
    float4 v = ((const float4*)src)[i];
    bf16 h0,h1,h2,h3,l0,l1,l2,l3;
    split1(v.x,h0,l0); split1(v.y,h1,l1); split1(v.z,h2,l2); split1(v.w,h3,l3);
    g_w_hi[4*i+0]=h0; g_w_hi[4*i+1]=h1; g_w_hi[4*i+2]=h2; g_w_hi[4*i+3]=h3;
    g_w_lo[4*i+0]=l0; g_w_lo[4*i+1]=l1; g_w_lo[4*i+2]=l2; g_w_lo[4*i+3]=l3;
}

__global__ void conv_att()
{
    int i = blockIdx.x * blockDim.x + threadIdx.x;   // 1M float4s exactly
    float4 v = g_att_r[i];
    bf16 h0,h1,h2,h3,l0,l1,l2,l3;
    split1(v.x,h0,l0); split1(v.y,h1,l1); split1(v.z,h2,l2); split1(v.w,h3,l3);
    g_att_hi[4*i+0]=h0; g_att_hi[4*i+1]=h1; g_att_hi[4*i+2]=h2; g_att_hi[4*i+3]=h3;
    g_att_lo[4*i+0]=l0; g_att_lo[4*i+1]=l1; g_att_lo[4*i+2]=l2; g_att_lo[4*i+3]=l3;
}

// Ut[p][kc][j][c] = U[prim][c][j]   grid (3, 16, 8)
__global__ __launch_bounds__(256) void conv_ut(const float* __restrict__ qU,
    const float* __restrict__ kU, const float* __restrict__ vU)
{
    int p = blockIdx.x, kc = blockIdx.y;
    if (kc >= g_K) return;
    const float* U = p == 0 ? qU : p == 1 ? kU : vU;
    const float* Up = U + (size_t)g_ti[p][kc] * 65536;
    size_t base = (size_t)(p * 16 + kc) * 65536;
    int i0 = blockIdx.z * 8192;
    for (int idx = i0 + threadIdx.x; idx < i0 + 8192; idx += 256) {
        int j = idx >> 10, c = idx & 1023;
        bf16 h, l; split1(Up[c * 64 + j], h, l);
        g_ut_hi[base + idx] = h;
        g_ut_lo[base + idx] = l;
    }
}

// Vt[p][n][kc*64+j] = V[prim(kc)][j][n]   grid (3, 16, 8)
__global__ __launch_bounds__(256) void conv_vt(const float* __restrict__ qV,
    const float* __restrict__ kV, const float* __restrict__ vV)
{
    int p = blockIdx.x, kc = blockIdx.y;
    if (kc >= g_K) return;
    const float* V = p == 0 ? qV : p == 1 ? kV : vV;
    const float* Vp = V + (size_t)g_ti[p][kc] * 65536;
    int i0 = blockIdx.z * 8192;
    for (int idx = i0 + threadIdx.x; idx < i0 + 8192; idx += 256) {
        int n = idx >> 6, j = idx & 63;
        bf16 h, l; split1(Vp[(size_t)j * 1024 + n], h, l);
        size_t dst = ((size_t)p * 1024 + n) * 1024 + kc * 64 + j;
        g_vt_hi[dst] = h;
        g_vt_lo[dst] = l;
    }
}

// ---------------- HMMA GEMM: 128x64 tile, BK=32, 256 thr, ldmatrix fragments ------------
// smem row stride 40 bf16 (80 B). ldmatrix phases: 8 row-addresses stride 80B are 8
// distinct 16B slots mod 128B -> conflict-free. Double buffer, 1 sync/chunk.
#define SAS 40
#define ASZE (128*SAS)
#define BSZE (64*SAS)

#define MMA_BODY(AhP, AlP, BhP, BlP, Abase, Bbase, PST, NST)                          \
    __shared__ __align__(16) bf16 shA[2][ASZE];                                       \
    __shared__ __align__(16) bf16 shB[2][BSZE];                                       \
    int tid = threadIdx.x, w = tid >> 5, l = tid & 31;                                \
    int gid = l >> 2, tig = l & 3;                                                    \
    int lr = tid >> 2, lc = (tid & 3) * 8;                                            \
    int g_ = l >> 3, rrl = l & 7;                                                     \
    int aB = w * (16*SAS) + ((g_ & 1) * 8 + rrl) * SAS + (g_ >> 1) * 8;               \
    int bB = ((g_ >> 1) * 8 + rrl) * SAS + (g_ & 1) * 8;                              \
    uint32_t sbA = smem_u32(&shA[0][0]), sbB = smem_u32(&shB[0][0]);                  \
    float acc[8][4];                                                                  \
    _Pragma("unroll") for (int i_ = 0; i_ < 8; i_++)                                  \
    _Pragma("unroll") for (int j_ = 0; j_ < 4; j_++) acc[i_][j_] = 0.f;               \
    uint4 A0, A1, B0;                                                                 \
    {                                                                                 \
        const bf16* Ap = (AhP); const bf16* Bp = (BhP);                               \
        A0 = *(const uint4*)(Ap + (Abase) + (size_t)lr * 1024 + lc);                  \
        A1 = *(const uint4*)(Ap + (Abase) + (size_t)(lr + 64) * 1024 + lc);           \
        B0 = *(const uint4*)(Bp + (Bbase) + (size_t)lr * 1024 + lc);                  \
    }                                                                                 \
    *(uint4*)&shA[0][lr * SAS + lc]        = A0;                                      \
    *(uint4*)&shA[0][(lr + 64) * SAS + lc] = A1;                                      \
    *(uint4*)&shB[0][lr * SAS + lc]        = B0;                                      \
    __syncthreads();                                                                  \
    for (int c = 0; c < (NST); c++) {                                                 \
        int cur = c & 1;                                                              \
        if (c + 1 < (NST)) {                                                          \
            int s_ = 0, kk = c + 1;                                                   \
            if (kk >= (PST)) { s_ = 1; kk -= (PST); }                                 \
            if (kk >= (PST)) { s_ = 2; kk -= (PST); }                                 \
            const bf16* Ap = (s_ == 1) ? (AlP) : (AhP);                               \
            const bf16* Bp = (s_ == 2) ? (BlP) : (BhP);                               \
            size_t ko = (size_t)kk * 32;                                              \
            A0 = *(const uint4*)(Ap + (Abase) + (size_t)lr * 1024 + ko + lc);         \
            A1 = *(const uint4*)(Ap + (Abase) + (size_t)(lr + 64) * 1024 + ko + lc);  \
            B0 = *(const uint4*)(Bp + (Bbase) + (size_t)lr * 1024 + ko + lc);         \
        }                                                                             \
        _Pragma("unroll")                                                             \
        for (int k16 = 0; k16 < 2; k16++) {                                           \
            uint32_t av[4];                                                           \
            ldsm4(av, sbA + (uint32_t)(cur*ASZE + aB + k16*16) * 2);                  \
            uint32_t bfr[16];                                                         \
            _Pragma("unroll")                                                         \
            for (int t = 0; t < 4; t++)                                               \
                ldsm4(bfr + 4*t, sbB + (uint32_t)(cur*BSZE + bB + t*(16*SAS) + k16*16) * 2); \
            _Pragma("unroll")                                                         \
            for (int nt = 0; nt < 8; nt++)                                            \
                hmma(acc[nt], av, bfr + (nt >> 1) * 4 + (nt & 1) * 2);                \
        }                                                                             \
        if (c + 1 < (NST)) {                                                          \
            int nxt = cur ^ 1;                                                        \
            *(uint4*)&shA[nxt][lr * SAS + lc]        = A0;                            \
            *(uint4*)&shA[nxt][(lr + 64) * SAS + lc] = A1;                            \
            *(uint4*)&shB[nxt][lr * SAS + lc]        = B0;                            \
        }                                                                             \
        __syncthreads();                                                              \
    }

// GEMM 1: h[p][m][kc*64+n] = tw * x[m,:] @ U[prim]    grid (32, 16, 3)
__global__ __launch_bounds__(256, 2) void mma_gemm_xu()
{
    int proj = blockIdx.z, kc = blockIdx.y;
    if (kc >= g_K) return;
    int m0 = blockIdx.x << 7;
    const bf16* Bh = g_ut_hi + (size_t)(proj * 16 + kc) * 65536;
    const bf16* Bl = g_ut_lo + (size_t)(proj * 16 + kc) * 65536;
    float tw = g_tw[proj][kc];
    MMA_BODY(g_x_hi, g_x_lo, Bh, Bl, (size_t)m0 * 1024, 0, 32, 96)
    int row = m0 + w * 16 + gid, lp = tig * 2;
    size_t b0_ = ((size_t)proj * MROWS + row) * 1024 + kc * 64;
    size_t b1_ = b0_ + (size_t)8 * 1024;
#pragma unroll
    for (int nt = 0; nt < 8; nt++) {
        bf16 h0, l0, h1, l1;
        split1(tw * acc[nt][0], h0, l0); split1(tw * acc[nt][1], h1, l1);
        g_h_hi[b0_ + nt*8 + lp] = h0; g_h_hi[b0_ + nt*8 + lp + 1] = h1;
        g_h_lo[b0_ + nt*8 + lp] = l0; g_h_lo[b0_ + nt*8 + lp + 1] = l1;
        split1(tw * acc[nt][2], h0, l0); split1(tw * acc[nt][3], h1, l1);
        g_h_hi[b1_ + nt*8 + lp] = h0; g_h_hi[b1_ + nt*8 + lp + 1] = h1;
        g_h_lo[b1_ + nt*8 + lp] = l0; g_h_lo[b1_ + nt*8 + lp + 1] = l1;
    }
}

// GEMM 2: qkv = h @ Vt -> [B,H,S,D] fp32    grid (32, 16, 3)
__global__ __launch_bounds__(256, 2) void mma_gemm_hv()
{
    int proj = blockIdx.z, hh = blockIdx.y;
    int m0 = blockIdx.x << 7;
    int pst = g_K * 2;
    int nst = 3 * pst;
    const bf16* Ah = g_h_hi + (size_t)proj * MROWS * 1024;
    const bf16* Al = g_h_lo + (size_t)proj * MROWS * 1024;
    const bf16* Bh = g_vt_hi + ((size_t)proj * 1024 + (hh << 6)) * 1024;
    const bf16* Bl = g_vt_lo + ((size_t)proj * 1024 + (hh << 6)) * 1024;
    MMA_BODY(Ah, Al, Bh, Bl, (size_t)m0 * 1024, 0, pst, nst)
    float* dst = proj == 0 ? g_q : proj == 1 ? g_k : g_v;
    int lp = tig * 2;
    int m = m0 + w * 16 + gid;
    int bb = m >> 10, sq = m & 1023;
    float* d0 = dst + (((size_t)(bb * NHEAD + hh) * SEQ + sq) << 6);
    float* d1 = d0 + (8 << 6);
#pragma unroll
    for (int nt = 0; nt < 8; nt++) {
        d0[nt*8 + lp] = acc[nt][0]; d0[nt*8 + lp + 1] = acc[nt][1];
        d1[nt*8 + lp] = acc[nt][2]; d1[nt*8 + lp + 1] = acc[nt][3];
    }
}

// GEMM 3: out = att @ W^T    grid (32, 16)
__global__ __launch_bounds__(256, 2) void mma_gemm_out(float* __restrict__ out)
{
    int n0 = blockIdx.y << 6;
    int m0 = blockIdx.x << 7;
    MMA_BODY(g_att_hi, g_att_lo, g_w_hi, g_w_lo, (size_t)m0 * 1024, (size_t)n0 * 1024, 32, 96)
    int lp = tig * 2;
    int row = m0 + w * 16 + gid;
    float* d0 = out + (size_t)row * 1024 + n0;
    float* d1 = d0 + (size_t)8 * 1024;
#pragma unroll
    for (int nt = 0; nt < 8; nt++) {
        d0[nt*8 + lp] = acc[nt][0]; d0[nt*8 + lp + 1] = acc[nt][1];
        d1[nt*8 + lp] = acc[nt][2]; d1[nt*8 + lp + 1] = acc[nt][3];
    }
}

// ---------------- flash attention (round-3 proven, fp32 output) ----------------
#define SQT 132
#define SKT 68
#define SVT 68
#define SPT 132
#define QS_OFF 0
#define KS_OFF (64*SQT)
#define VS_OFF (KS_OFF + 64*SKT)
#define PT_OFF (VS_OFF + 64*SVT)
#define ATT_SMEM ((PT_OFF + 64*SPT) * 4)

__global__ __launch_bounds__(256, 2) void attn_kernel()
{
    extern __shared__ __align__(16) float sm[];
    float* Qs = sm + QS_OFF;
    float* Ks = sm + KS_OFF;
    float* Vs = sm + VS_OFF;
    float* Pt = sm + PT_OFF;

    int qt = blockIdx.x, bh = blockIdx.y;
    const float* qb = g_q + (size_t)bh * SEQ * HDIM;
    const float* kb = g_k + (size_t)bh * SEQ * HDIM;
    const float* vb = g_v + (size_t)bh * SEQ * HDIM;

    int tid = threadIdx.x;
    int tx = tid & 15, ty = tid >> 4;
    int qr0 = qt << 7;

#pragma unroll
    for (int it = 0; it < 8; it++) {
        int idx = tid + it * 256;
        int r = idx >> 4, d4 = idx & 15;
        float4 v = *(const float4*)(qb + (size_t)(qr0 + r) * 64 + d4 * 4);
        Qs[(d4*4+0)*SQT + r] = v.x;
        Qs[(d4*4+1)*SQT + r] = v.y;
        Qs[(d4*4+2)*SQT + r] = v.z;
        Qs[(d4*4+3)*SQT + r] = v.w;
    }

    float m_run[8], l_run[8];
#pragma unroll
    for (int i = 0; i < 8; i++) { m_run[i] = -3.0e38f; l_run[i] = 0.f; }
    u64 accO[4][4];
#pragma unroll
    for (int i = 0; i < 4; i++)
#pragma unroll
        for (int j = 0; j < 4; j++) accO[i][j] = 0ull;

    int ktmax = 2*qt + 1;
    for (int kt = 0; kt <= ktmax; kt++) {
        int kr0 = kt << 6;
        __syncthreads();
#pragma unroll
        for (int it = 0; it < 4; it++) {
            int idx = tid + it * 256;
            int r = idx >> 4, d4 = idx & 15;
            float4 kv = *(const float4*)(kb + (size_t)(kr0 + r) * 64 + d4 * 4);
            Ks[(d4*4+0)*SKT + r] = kv.x;
            Ks[(d4*4+1)*SKT + r] = kv.y;
            Ks[(d4*4+2)*SKT + r] = kv.z;
            Ks[(d4*4+3)*SKT + r] = kv.w;
            float4 vv = *(const float4*)(vb + (size_t)(kr0 + r) * 64 + d4 * 4);
            *(float4*)(Vs + r*SVT + d4*4) = vv;
        }
        __syncthreads();

        u64 sp[4][4];
#pragma unroll
        for (int i = 0; i < 4; i++)
#pragma unroll
            for (int j = 0; j < 4; j++) sp[i][j] = 0ull;
#pragma unroll 4
        for (int d = 0; d < 64; d++) {
            const float* qp = Qs + d*SQT + ty*8;
            ulonglong2 a01 = *(const ulonglong2*)qp;
            ulonglong2 a23 = *(const ulonglong2*)(qp + 4);
            float4 b4 = *(const float4*)(Ks + d*SKT + tx*4);
            u64 b0,b1,b2,b3;
            DUP2(b0,b4.x) DUP2(b1,b4.y) DUP2(b2,b4.z) DUP2(b3,b4.w)
            FMA2(sp[0][0],a01.x,b0) FMA2(sp[0][1],a01.x,b1) FMA2(sp[0][2],a01.x,b2) FMA2(sp[0][3],a01.x,b3)
            FMA2(sp[1][0],a01.y,b0) FMA2(sp[1][1],a01.y,b1) FMA2(sp[1][2],a01.y,b2) FMA2(sp[1][3],a01.y,b3)
            FMA2(sp[2][0],a23.x,b0) FMA2(sp[2][1],a23.x,b1) FMA2(sp[2][2],a23.x,b2) FMA2(sp[2][3],a23.x,b3)
            FMA2(sp[3][0],a23.y,b0) FMA2(sp[3][1],a23.y,b1) FMA2(sp[3][2],a23.y,b2) FMA2(sp[3][3],a23.y,b3)
        }

        bool need_mask = (kt >= 2*qt);
#pragma unroll
        for (int ip = 0; ip < 4; ip++) {
            float sA[4], sB[4];
#pragma unroll
            for (int j = 0; j < 4; j++) { UNPK2(sA[j], sB[j], sp[ip][j]) }
            int rA = qr0 + ty*8 + 2*ip, rB = rA + 1;
#pragma unroll
            for (int j = 0; j < 4; j++) {
                sA[j] *= 0.125f; sB[j] *= 0.125f;
                if (need_mask) {
                    int cg = kr0 + tx*4 + j;
                    if (cg > rA) sA[j] = -3.0e38f;
                    if (cg > rB) sB[j] = -3.0e38f;
                }
            }
            float mxA = fmaxf(fmaxf(sA[0],sA[1]), fmaxf(sA[2],sA[3]));
            float mxB = fmaxf(fmaxf(sB[0],sB[1]), fmaxf(sB[2],sB[3]));
#pragma unroll
            for (int o = 1; o <= 8; o <<= 1) {
                mxA = fmaxf(mxA, __shfl_xor_sync(0xffffffffu, mxA, o));
                mxB = fmaxf(mxB, __shfl_xor_sync(0xffffffffu, mxB, o));
            }
            float mnA = fmaxf(m_run[2*ip],   mxA);
            float mnB = fmaxf(m_run[2*ip+1], mxB);
            float cA = __expf(m_run[2*ip]   - mnA);
            float cB = __expf(m_run[2*ip+1] - mnB);
            float pA = 0.f, pB = 0.f;
#pragma unroll
            for (int j = 0; j < 4; j++) {
                sA[j] = __expf(sA[j] - mnA); pA += sA[j];
                sB[j] = __expf(sB[j] - mnB); pB += sB[j];
            }
#pragma unroll
            for (int o = 1; o <= 8; o <<= 1) {
                pA += __shfl_xor_sync(0xffffffffu, pA, o);
                pB += __shfl_xor_sync(0xffffffffu, pB, o);
            }
            l_run[2*ip]   = l_run[2*ip]   * cA + pA;  m_run[2*ip]   = mnA;
            l_run[2*ip+1] = l_run[2*ip+1] * cB + pB;  m_run[2*ip+1] = mnB;
            u64 cc; PACK2(cc, cA, cB)
#pragma unroll
            for (int j = 0; j < 4; j++) { MUL2(accO[ip][j], cc) }
#pragma unroll
            for (int j = 0; j < 4; j++)
                *(float2*)(Pt + (tx*4+j)*SPT + ty*8 + 2*ip) = make_float2(sA[j], sB[j]);
        }
        __syncthreads();

#pragma unroll 4
        for (int c = 0; c < 64; c++) {
            const float* pp = Pt + c*SPT + ty*8;
            ulonglong2 p01 = *(const ulonglong2*)pp;
            ulonglong2 p23 = *(const ulonglong2*)(pp + 4);
            float4 v4 = *(const float4*)(Vs + c*SVT + tx*4);
            u64 b0,b1,b2,b3;
            DUP2(b0,v4.x) DUP2(b1,v4.y) DUP2(b2,v4.z) DUP2(b3,v4.w)
            FMA2(accO[0][0],p01.x,b0) FMA2(accO[0][1],p01.x,b1) FMA2(accO[0][2],p01.x,b2) FMA2(accO[0][3],p01.x,b3)
            FMA2(accO[1][0],p01.y,b0) FMA2(accO[1][1],p01.y,b1) FMA2(accO[1][2],p01.y,b2) FMA2(accO[1][3],p01.y,b3)
            FMA2(accO[2][0],p23.x,b0) FMA2(accO[2][1],p23.x,b1) FMA2(accO[2][2],p23.x,b2) FMA2(accO[2][3],p23.x,b3)
            FMA2(accO[3][0],p23.y,b0) FMA2(accO[3][1],p23.y,b1) FMA2(accO[3][2],p23.y,b2) FMA2(accO[3][3],p23.y,b3)
        }
    }

    // epilogue: normalize, store fp32 g_att [B*S, H*D]
    int b = bh >> 4, h = bh & 15;
#pragma unroll
    for (int ip = 0; ip < 4; ip++) {
        float o0[4], o1[4];
#pragma unroll
        for (int j = 0; j < 4; j++) { UNPK2(o0[j], o1[j], accO[ip][j]) }
        float i0 = 1.f / l_run[2*ip], i1 = 1.f / l_run[2*ip+1];
        int r0 = qr0 + ty*8 + 2*ip;
        float* d0 = g_att + (size_t)(b * SEQ + r0) * DMODEL + h*64 + tx*4;
        float* d1 = d0 + DMODEL;
        *(float4*)d0 = make_float4(o0[0]*i0, o0[1]*i0, o0[2]*i0, o0[3]*i0);
        *(float4*)d1 = make_float4(o1[0]*i1, o1[1]*i1, o1[2]*i1, o1[3]*i1);
    }
}

// ---------------- launch ----------------
extern "C" void kernel_launch(void* const* d_in, const int* in_sizes, int n_in,
                              void* d_out, int out_size)
{
    (void)n_in; (void)out_size;
    const float* x   = (const float*)d_in[0];
    const float* qU  = (const float*)d_in[1];
    const float* qV  = (const float*)d_in[2];
    const float* kU  = (const float*)d_in[3];
    const float* kV  = (const float*)d_in[4];
    const float* vU  = (const float*)d_in[5];
    const float* vV  = (const float*)d_in[6];
    const float* ql  = (const float*)d_in[7];
    const float* kl  = (const float*)d_in[8];
    const float* vl  = (const float*)d_in[9];
    const float* ow  = (const float*)d_in[10];
    const int*   tk  = (const int*)d_in[11];
    int P = in_sizes[7];

    cudaFuncSetAttribute(attn_kernel, cudaFuncAttributeMaxDynamicSharedMemorySize, ATT_SMEM);

    topk_kernel<<<1, 32>>>(ql, kl, vl, tk, P);

    conv_x<<<4096, 256>>>(x);
    conv_w<<<1024, 256>>>(ow);
    conv_ut<<<dim3(3, 16, 8), 256>>>(qU, kU, vU);
    conv_vt<<<dim3(3, 16, 8), 256>>>(qV, kV, vV);

    mma_gemm_xu<<<dim3(32, 16, 3), 256>>>();
    mma_gemm_hv<<<dim3(32, 16, 3), 256>>>();
    attn_kernel<<<dim3(SEQ / 128, BATCH * NHEAD), 256, ATT_SMEM>>>();
    conv_att<<<4096, 256>>>();
    mma_gemm_out<<<dim3(32, 16), 256>>>((float*)d_out);
}

// round 11
// speedup vs baseline: 3.0016x; 1.0553x over previous
#include <cuda_runtime.h>
#include <cuda_bf16.h>
#include <cstdint>

#define DMODEL 1024
#define SEQ    1024
#define BATCH  4
#define NHEAD  16
#define HDIM   64
#define RNK    64
#define MROWS  (BATCH*SEQ)
#define PMAX   64

typedef unsigned long long u64;
typedef __nv_bfloat16 bf16;

// ---------------- packed fp32x2 helpers (attention) ----------------
#define FMA2(c,a,b) asm("fma.rn.f32x2 %0, %1, %2, %0;" : "+l"(c) : "l"(a), "l"(b));
#define MUL2(c,s)   asm("mul.rn.f32x2 %0, %0, %1;"     : "+l"(c) : "l"(s));
#define DUP2(d,f)   asm("mov.b64 %0, {%1, %1};" : "=l"(d) : "f"(f));
#define PACK2(d,lo,hi) asm("mov.b64 %0, {%1, %2};" : "=l"(d) : "f"(lo), "f"(hi));
#define UNPK2(lo,hi,v) asm("mov.b64 {%0, %1}, %2;" : "=f"(lo), "=f"(hi) : "l"(v));

// ---------------- warp MMA helpers (arch-agnostic sm_80+ PTX) ----------------
__device__ __forceinline__ uint32_t smem_u32(const void* p) {
    uint32_t a;
    asm("{ .reg .u64 t; cvta.to.shared.u64 t, %1; cvt.u32.u64 %0, t; }" : "=r"(a) : "l"(p));
    return a;
}
__device__ __forceinline__ void ldsm4(uint32_t* r, uint32_t addr) {
    asm volatile("ldmatrix.sync.aligned.m8n8.x4.shared.b16 {%0,%1,%2,%3}, [%4];"
        : "=r"(r[0]), "=r"(r[1]), "=r"(r[2]), "=r"(r[3]) : "r"(addr));
}
__device__ __forceinline__ void hmma(float* d, const uint32_t* a, const uint32_t* b) {
    asm volatile("mma.sync.aligned.m16n8k16.row.col.f32.bf16.bf16.f32 "
        "{%0,%1,%2,%3}, {%4,%5,%6,%7}, {%8,%9}, {%0,%1,%2,%3};"
        : "+f"(d[0]), "+f"(d[1]), "+f"(d[2]), "+f"(d[3])
        : "r"(a[0]), "r"(a[1]), "r"(a[2]), "r"(a[3]), "r"(b[0]), "r"(b[1]));
}

// ---------------- device scratch (uint4/float4-typed: forced 16B alignment) ------------
// NOTE: these symbols are ONLY ever referenced from device code (never as kernel args).
__device__ uint4  g_x_hi_r [(size_t)MROWS*1024/8];
__device__ uint4  g_x_lo_r [(size_t)MROWS*1024/8];
__device__ uint4  g_w_hi_r [(size_t)1024*1024/8];
__device__ uint4  g_w_lo_r [(size_t)1024*1024/8];
__device__ uint4  g_ut_hi_r[(size_t)3*16*64*1024/8];
__device__ uint4  g_ut_lo_r[(size_t)3*16*64*1024/8];
__device__ uint4  g_vt_hi_r[(size_t)3*1024*1024/8];
__device__ uint4  g_vt_lo_r[(size_t)3*1024*1024/8];
__device__ uint4  g_h_hi_r [(size_t)3*MROWS*1024/8];
__device__ uint4  g_h_lo_r [(size_t)3*MROWS*1024/8];
__device__ uint4  g_att_hi_r[(size_t)MROWS*1024/8];
__device__ uint4  g_att_lo_r[(size_t)MROWS*1024/8];
__device__ float4 g_q_r   [(size_t)BATCH*NHEAD*SEQ*HDIM/4];
__device__ float4 g_k_r   [(size_t)BATCH*NHEAD*SEQ*HDIM/4];
__device__ float4 g_v_r   [(size_t)BATCH*NHEAD*SEQ*HDIM/4];
__device__ float g_tw[3][PMAX];
__device__ int   g_ti[3][PMAX];
__device__ int   g_K;

#define g_x_hi  ((bf16*)g_x_hi_r)
#define g_x_lo  ((bf16*)g_x_lo_r)
#define g_w_hi  ((bf16*)g_w_hi_r)
#define g_w_lo  ((bf16*)g_w_lo_r)
#define g_ut_hi ((bf16*)g_ut_hi_r)
#define g_ut_lo ((bf16*)g_ut_lo_r)
#define g_vt_hi ((bf16*)g_vt_hi_r)
#define g_vt_lo ((bf16*)g_vt_lo_r)
#define g_h_hi  ((bf16*)g_h_hi_r)
#define g_h_lo  ((bf16*)g_h_lo_r)
#define g_att_hi ((bf16*)g_att_hi_r)
#define g_att_lo ((bf16*)g_att_lo_r)
#define g_q     ((float*)g_q_r)
#define g_k     ((float*)g_k_r)
#define g_v     ((float*)g_v_r)

// ---------------- top-k gating ----------------
__global__ void topk_kernel(const float* __restrict__ ql, const float* __restrict__ kl,
                            const float* __restrict__ vl, const int* __restrict__ tkp, int P)
{
    if (threadIdx.x != 0) return;
    int K = *tkp; if (K > P) K = P; if (K < 1) K = 1;
    g_K = K;
    const float* ls[3] = {ql, kl, vl};
    for (int p = 0; p < 3; p++) {
        const float* lg = ls[p];
        bool used[PMAX];
        for (int i = 0; i < P; i++) used[i] = false;
        for (int t = 0; t < K; t++) {
            int best = 0; float bv = -3.4e38f;
            for (int i = 0; i < P; i++)
                if (!used[i] && lg[i] > bv) { bv = lg[i]; best = i; }
            used[best] = true;
            g_ti[p][t] = best;
        }
        float mx = -3.4e38f;
        for (int t = 0; t < K; t++) { float v = lg[g_ti[p][t]]; if (v > mx) mx = v; }
        float ssum = 0.f, w[PMAX];
        for (int t = 0; t < K; t++) { w[t] = expf(lg[g_ti[p][t]] - mx); ssum += w[t]; }
        for (int t = 0; t < K; t++) g_tw[p][t] = w[t] / ssum;
    }
}

// ---------------- bf16 split conversions ----------------
__device__ __forceinline__ void split1(float v, bf16& h, bf16& l) {
    h = __float2bfloat16(v);
    l = __float2bfloat16(v - __bfloat162float(h));
}

__global__ void conv_x(const float* __restrict__ src)
{
    int i = blockIdx.x * blockDim.x + threadIdx.x;   // 1M float4s exactly
    float4 v = ((const float4*)src)[i];
    bf16 h0,h1,h2,h3,l0,l1,l2,l3;
    split1(v.x,h0,l0); split1(v.y,h1,l1); split1(v.z,h2,l2); split1(v.w,h3,l3);
    g_x_hi[4*i+0]=h0; g_x_hi[4*i+1]=h1; g_x_hi[4*i+2]=h2; g_x_hi[4*i+3]=h3;
    g_x_lo[4*i+0]=l0; g_x_lo[4*i+1]=l1; g_x_lo[4*i+2]=l2; g_x_lo[4*i+3]=l3;
}

__global__ void conv_w(const float* __restrict__ src)
{
    int i = blockIdx.x * blockDim.x + threadIdx.x;   // 256K float4s exactly
    float4 v = ((const float4*)src)[i];
    bf16 h0,h1,h2,h3,l0,l1,l2,l3;
    split1(v.x,h0,l0); split1(v.y,h1,l1); split1(v.z,h2,l2); split1(v.w,h3,l3);
    g_w_hi[4*i+0]=h0; g_w_hi[4*i+1]=h1; g_w_hi[4*i+2]=h2; g_w_hi[4*i+3]=h3;
    g_w_lo[4*i+0]=l0; g_w_lo[4*i+1]=l1; g_w_lo[4*i+2]=l2; g_w_lo[4*i+3]=l3;
}

// Ut[p][kc][j][c] = U[prim][c][j]   grid (3, 16, 8)
__global__ __launch_bounds__(256) void conv_ut(const float* __restrict__ qU,
    const float* __restrict__ kU, const float* __restrict__ vU)
{
    int p = blockIdx.x, kc = blockIdx.y;
    if (kc >= g_K) return;
    const float* U = p == 0 ? qU : p == 1 ? kU : vU;
    const float* Up = U + (size_t)g_ti[p][kc] * 65536;
    size_t base = (size_t)(p * 16 + kc) * 65536;
    int i0 = blockIdx.z * 8192;
    for (int idx = i0 + threadIdx.x; idx < i0 + 8192; idx += 256) {
        int j = idx >> 10, c = idx & 1023;
        bf16 h, l; split1(Up[c * 64 + j], h, l);
        g_ut_hi[base + idx] = h;
        g_ut_lo[base + idx] = l;
    }
}

// Vt[p][n][kc*64+j] = V[prim(kc)][j][n]   grid (3, 16, 8)
__global__ __launch_bounds__(256) void conv_vt(const float* __restrict__ qV,
    const float* __restrict__ kV, const float* __restrict__ vV)
{
    int p = blockIdx.x, kc = blockIdx.y;
    if (kc >= g_K) return;
    const float* V = p == 0 ? qV : p == 1 ? kV : vV;
    const float* Vp = V + (size_t)g_ti[p][kc] * 65536;
    int i0 = blockIdx.z * 8192;
    for (int idx = i0 + threadIdx.x; idx < i0 + 8192; idx += 256) {
        int n = idx >> 6, j = idx & 63;
        bf16 h, l; split1(Vp[(size_t)j * 1024 + n], h, l);
        size_t dst = ((size_t)p * 1024 + n) * 1024 + kc * 64 + j;
        g_vt_hi[dst] = h;
        g_vt_lo[dst] = l;
    }
}

// ---------------- HMMA GEMM: 128x128 tile, BK=32, 256 thr, ldmatrix fragments -----------
// smem row stride 40 bf16 (80 B) -> conflict-free ldmatrix phases. Double buffer.
#define SAS 40
#define ASZE (128*SAS)
#define BSZE (128*SAS)

#define MMA_BODY(AhP, AlP, BhP, BlP, Abase, Bbase, PST, NST)                          \
    __shared__ __align__(16) bf16 shA[2][ASZE];                                       \
    __shared__ __align__(16) bf16 shB[2][BSZE];                                       \
    int tid = threadIdx.x, w = tid >> 5, l = tid & 31;                                \
    int gid = l >> 2, tig = l & 3;                                                    \
    int lr = tid >> 2, lc = (tid & 3) * 8;                                            \
    int g_ = l >> 3, rrl = l & 7;                                                     \
    int aB = w * (16*SAS) + ((g_ & 1) * 8 + rrl) * SAS + (g_ >> 1) * 8;               \
    int bB = ((g_ >> 1) * 8 + rrl) * SAS + (g_ & 1) * 8;                              \
    uint32_t sbA = smem_u32(&shA[0][0]), sbB = smem_u32(&shB[0][0]);                  \
    float acc[16][4];                                                                 \
    _Pragma("unroll") for (int i_ = 0; i_ < 16; i_++)                                 \
    _Pragma("unroll") for (int j_ = 0; j_ < 4; j_++) acc[i_][j_] = 0.f;               \
    uint4 A0, A1, B0, B1;                                                             \
    {                                                                                 \
        const bf16* Ap = (AhP); const bf16* Bp = (BhP);                               \
        A0 = *(const uint4*)(Ap + (Abase) + (size_t)lr * 1024 + lc);                  \
        A1 = *(const uint4*)(Ap + (Abase) + (size_t)(lr + 64) * 1024 + lc);           \
        B0 = *(const uint4*)(Bp + (Bbase) + (size_t)lr * 1024 + lc);                  \
        B1 = *(const uint4*)(Bp + (Bbase) + (size_t)(lr + 64) * 1024 + lc);           \
    }                                                                                 \
    *(uint4*)&shA[0][lr * SAS + lc]        = A0;                                      \
    *(uint4*)&shA[0][(lr + 64) * SAS + lc] = A1;                                      \
    *(uint4*)&shB[0][lr * SAS + lc]        = B0;                                      \
    *(uint4*)&shB[0][(lr + 64) * SAS + lc] = B1;                                      \
    __syncthreads();                                                                  \
    for (int c = 0; c < (NST); c++) {                                                 \
        int cur = c & 1;                                                              \
        if (c + 1 < (NST)) {                                                          \
            int s_ = 0, kk = c + 1;                                                   \
            if (kk >= (PST)) { s_ = 1; kk -= (PST); }                                 \
            if (kk >= (PST)) { s_ = 2; kk -= (PST); }                                 \
            const bf16* Ap = (s_ == 1) ? (AlP) : (AhP);                               \
            const bf16* Bp = (s_ == 2) ? (BlP) : (BhP);                               \
            size_t ko = (size_t)kk * 32;                                              \
            A0 = *(const uint4*)(Ap + (Abase) + (size_t)lr * 1024 + ko + lc);         \
            A1 = *(const uint4*)(Ap + (Abase) + (size_t)(lr + 64) * 1024 + ko + lc);  \
            B0 = *(const uint4*)(Bp + (Bbase) + (size_t)lr * 1024 + ko + lc);         \
            B1 = *(const uint4*)(Bp + (Bbase) + (size_t)(lr + 64) * 1024 + ko + lc);  \
        }                                                                             \
        _Pragma("unroll")                                                             \
        for (int k16 = 0; k16 < 2; k16++) {                                           \
            uint32_t av[4];                                                           \
            ldsm4(av, sbA + (uint32_t)(cur*ASZE + aB + k16*16) * 2);                  \
            _Pragma("unroll")                                                         \
            for (int ph = 0; ph < 2; ph++) {                                          \
                uint32_t bfr[16];                                                     \
                _Pragma("unroll")                                                     \
                for (int t = 0; t < 4; t++)                                           \
                    ldsm4(bfr + 4*t, sbB + (uint32_t)(cur*BSZE + bB + (ph*4+t)*(16*SAS) + k16*16) * 2); \
                _Pragma("unroll")                                                     \
                for (int nt8 = 0; nt8 < 8; nt8++)                                     \
                    hmma(acc[ph*8 + nt8], av, bfr + (nt8 >> 1) * 4 + (nt8 & 1) * 2);  \
            }                                                                         \
        }                                                                             \
        if (c + 1 < (NST)) {                                                          \
            int nxt = cur ^ 1;                                                        \
            *(uint4*)&shA[nxt][lr * SAS + lc]        = A0;                            \
            *(uint4*)&shA[nxt][(lr + 64) * SAS + lc] = A1;                            \
            *(uint4*)&shB[nxt][lr * SAS + lc]        = B0;                            \
            *(uint4*)&shB[nxt][(lr + 64) * SAS + lc] = B1;                            \
        }                                                                             \
        __syncthreads();                                                              \
    }

// GEMM 1: h[p][m][kc*64+n] = tw * x[m,:] @ U[prim], kc-pairs fused  grid (32, 8, 3)
__global__ __launch_bounds__(256, 2) void mma_gemm_xu()
{
    int proj = blockIdx.z, kc0 = blockIdx.y * 2;
    int K = g_K;
    if (kc0 >= K) return;
    int m0 = blockIdx.x << 7;
    // Ut rows for kc0 and kc0+1 are contiguous: base + r*1024, r in 0..127
    const bf16* Bh = g_ut_hi + (size_t)(proj * 16 + kc0) * 65536;
    const bf16* Bl = g_ut_lo + (size_t)(proj * 16 + kc0) * 65536;
    float tws[2];
    tws[0] = g_tw[proj][kc0];
    tws[1] = (kc0 + 1 < K) ? g_tw[proj][kc0 + 1] : 0.f;
    MMA_BODY(g_x_hi, g_x_lo, Bh, Bl, (size_t)m0 * 1024, 0, 32, 96)
    int row = m0 + w * 16 + gid, lp = tig * 2;
#pragma unroll
    for (int nt = 0; nt < 16; nt++) {
        int n = nt * 8 + lp;
        int kcl = n >> 6;
        int kc = kc0 + kcl;
        if (kc < K) {
            float tw = tws[kcl];
            size_t b0_ = ((size_t)proj * MROWS + row) * 1024 + kc * 64 + (n & 63);
            size_t b1_ = b0_ + (size_t)8 * 1024;
            bf16 h0, l0, h1, l1;
            split1(tw * acc[nt][0], h0, l0); split1(tw * acc[nt][1], h1, l1);
            g_h_hi[b0_] = h0; g_h_hi[b0_ + 1] = h1;
            g_h_lo[b0_] = l0; g_h_lo[b0_ + 1] = l1;
            split1(tw * acc[nt][2], h0, l0); split1(tw * acc[nt][3], h1, l1);
            g_h_hi[b1_] = h0; g_h_hi[b1_ + 1] = h1;
            g_h_lo[b1_] = l0; g_h_lo[b1_ + 1] = l1;
        }
    }
}

// GEMM 2: qkv = h @ Vt -> [B,H,S,D] fp32, head-pairs fused   grid (32, 8, 3)
__global__ __launch_bounds__(256, 2) void mma_gemm_hv()
{
    int proj = blockIdx.z, hh0 = blockIdx.y * 2;
    int m0 = blockIdx.x << 7;
    int pst = g_K * 2;
    int nst = 3 * pst;
    const bf16* Ah = g_h_hi + (size_t)proj * MROWS * 1024;
    const bf16* Al = g_h_lo + (size_t)proj * MROWS * 1024;
    const bf16* Bh = g_vt_hi + ((size_t)proj * 1024 + (hh0 << 6)) * 1024;
    const bf16* Bl = g_vt_lo + ((size_t)proj * 1024 + (hh0 << 6)) * 1024;
    MMA_BODY(Ah, Al, Bh, Bl, (size_t)m0 * 1024, 0, pst, nst)
    float* dst = proj == 0 ? g_q : proj == 1 ? g_k : g_v;
    int lp = tig * 2;
    int m = m0 + w * 16 + gid;
    int bb = m >> 10, sq = m & 1023;
#pragma unroll
    for (int nt = 0; nt < 16; nt++) {
        int n = nt * 8 + lp;
        int hh = hh0 + (n >> 6);
        float* d0 = dst + (((size_t)(bb * NHEAD + hh) * SEQ + sq) << 6) + (n & 63);
        float* d1 = d0 + (8 << 6);
        d0[0] = acc[nt][0]; d0[1] = acc[nt][1];
        d1[0] = acc[nt][2]; d1[1] = acc[nt][3];
    }
}

// GEMM 3: out = att @ W^T    grid (32, 8)
__global__ __launch_bounds__(256, 2) void mma_gemm_out(float* __restrict__ out)
{
    int n0 = blockIdx.y << 7;
    int m0 = blockIdx.x << 7;
    MMA_BODY(g_att_hi, g_att_lo, g_w_hi, g_w_lo, (size_t)m0 * 1024, (size_t)n0 * 1024, 32, 96)
    int lp = tig * 2;
    int row = m0 + w * 16 + gid;
    float* d0 = out + (size_t)row * 1024 + n0;
    float* d1 = d0 + (size_t)8 * 1024;
#pragma unroll
    for (int nt = 0; nt < 16; nt++) {
        int n = nt * 8 + lp;
        d0[n] = acc[nt][0]; d0[n + 1] = acc[nt][1];
        d1[n] = acc[nt][2]; d1[n + 1] = acc[nt][3];
    }
}

// ---------------- flash attention (proven core; bf16 hi/lo split epilogue) --------------
#define SQT 132
#define SKT 68
#define SVT 68
#define SPT 132
#define QS_OFF 0
#define KS_OFF (64*SQT)
#define VS_OFF (KS_OFF + 64*SKT)
#define PT_OFF (VS_OFF + 64*SVT)
#define ATT_SMEM ((PT_OFF + 64*SPT) * 4)

__global__ __launch_bounds__(256, 2) void attn_kernel()
{
    extern __shared__ __align__(16) float sm[];
    float* Qs = sm + QS_OFF;
    float* Ks = sm + KS_OFF;
    float* Vs = sm + VS_OFF;
    float* Pt = sm + PT_OFF;

    int qt = blockIdx.x, bh = blockIdx.y;
    const float* qb = g_q + (size_t)bh * SEQ * HDIM;
    const float* kb = g_k + (size_t)bh * SEQ * HDIM;
    const float* vb = g_v + (size_t)bh * SEQ * HDIM;

    int tid = threadIdx.x;
    int tx = tid & 15, ty = tid >> 4;
    int qr0 = qt << 7;

#pragma unroll
    for (int it = 0; it < 8; it++) {
        int idx = tid + it * 256;
        int r = idx >> 4, d4 = idx & 15;
        float4 v = *(const float4*)(qb + (size_t)(qr0 + r) * 64 + d4 * 4);
        Qs[(d4*4+0)*SQT + r] = v.x;
        Qs[(d4*4+1)*SQT + r] = v.y;
        Qs[(d4*4+2)*SQT + r] = v.z;
        Qs[(d4*4+3)*SQT + r] = v.w;
    }

    float m_run[8], l_run[8];
#pragma unroll
    for (int i = 0; i < 8; i++) { m_run[i] = -3.0e38f; l_run[i] = 0.f; }
    u64 accO[4][4];
#pragma unroll
    for (int i = 0; i < 4; i++)
#pragma unroll
        for (int j = 0; j < 4; j++) accO[i][j] = 0ull;

    int ktmax = 2*qt + 1;
    for (int kt = 0; kt <= ktmax; kt++) {
        int kr0 = kt << 6;
        __syncthreads();
#pragma unroll
        for (int it = 0; it < 4; it++) {
            int idx = tid + it * 256;
            int r = idx >> 4, d4 = idx & 15;
            float4 kv = *(const float4*)(kb + (size_t)(kr0 + r) * 64 + d4 * 4);
            Ks[(d4*4+0)*SKT + r] = kv.x;
            Ks[(d4*4+1)*SKT + r] = kv.y;
            Ks[(d4*4+2)*SKT + r] = kv.z;
            Ks[(d4*4+3)*SKT + r] = kv.w;
            float4 vv = *(const float4*)(vb + (size_t)(kr0 + r) * 64 + d4 * 4);
            *(float4*)(Vs + r*SVT + d4*4) = vv;
        }
        __syncthreads();

        u64 sp[4][4];
#pragma unroll
        for (int i = 0; i < 4; i++)
#pragma unroll
            for (int j = 0; j < 4; j++) sp[i][j] = 0ull;
#pragma unroll 4
        for (int d = 0; d < 64; d++) {
            const float* qp = Qs + d*SQT + ty*8;
            ulonglong2 a01 = *(const ulonglong2*)qp;
            ulonglong2 a23 = *(const ulonglong2*)(qp + 4);
            float4 b4 = *(const float4*)(Ks + d*SKT + tx*4);
            u64 b0,b1,b2,b3;
            DUP2(b0,b4.x) DUP2(b1,b4.y) DUP2(b2,b4.z) DUP2(b3,b4.w)
            FMA2(sp[0][0],a01.x,b0) FMA2(sp[0][1],a01.x,b1) FMA2(sp[0][2],a01.x,b2) FMA2(sp[0][3],a01.x,b3)
            FMA2(sp[1][0],a01.y,b0) FMA2(sp[1][1],a01.y,b1) FMA2(sp[1][2],a01.y,b2) FMA2(sp[1][3],a01.y,b3)
            FMA2(sp[2][0],a23.x,b0) FMA2(sp[2][1],a23.x,b1) FMA2(sp[2][2],a23.x,b2) FMA2(sp[2][3],a23.x,b3)
            FMA2(sp[3][0],a23.y,b0) FMA2(sp[3][1],a23.y,b1) FMA2(sp[3][2],a23.y,b2) FMA2(sp[3][3],a23.y,b3)
        }

        bool need_mask = (kt >= 2*qt);
#pragma unroll
        for (int ip = 0; ip < 4; ip++) {
            float sA[4], sB[4];
#pragma unroll
            for (int j = 0; j < 4; j++) { UNPK2(sA[j], sB[j], sp[ip][j]) }
            int rA = qr0 + ty*8 + 2*ip, rB = rA + 1;
#pragma unroll
            for (int j = 0; j < 4; j++) {
                sA[j] *= 0.125f; sB[j] *= 0.125f;
                if (need_mask) {
                    int cg = kr0 + tx*4 + j;
                    if (cg > rA) sA[j] = -3.0e38f;
                    if (cg > rB) sB[j] = -3.0e38f;
                }
            }
            float mxA = fmaxf(fmaxf(sA[0],sA[1]), fmaxf(sA[2],sA[3]));
            float mxB = fmaxf(fmaxf(sB[0],sB[1]), fmaxf(sB[2],sB[3]));
#pragma unroll
            for (int o = 1; o <= 8; o <<= 1) {
                mxA = fmaxf(mxA, __shfl_xor_sync(0xffffffffu, mxA, o));
                mxB = fmaxf(mxB, __shfl_xor_sync(0xffffffffu, mxB, o));
            }
            float mnA = fmaxf(m_run[2*ip],   mxA);
            float mnB = fmaxf(m_run[2*ip+1], mxB);
            float cA = __expf(m_run[2*ip]   - mnA);
            float cB = __expf(m_run[2*ip+1] - mnB);
            float pA = 0.f, pB = 0.f;
#pragma unroll
            for (int j = 0; j < 4; j++) {
                sA[j] = __expf(sA[j] - mnA); pA += sA[j];
                sB[j] = __expf(sB[j] - mnB); pB += sB[j];
            }
#pragma unroll
            for (int o = 1; o <= 8; o <<= 1) {
                pA += __shfl_xor_sync(0xffffffffu, pA, o);
                pB += __shfl_xor_sync(0xffffffffu, pB, o);
            }
            l_run[2*ip]   = l_run[2*ip]   * cA + pA;  m_run[2*ip]   = mnA;
            l_run[2*ip+1] = l_run[2*ip+1] * cB + pB;  m_run[2*ip+1] = mnB;
            u64 cc; PACK2(cc, cA, cB)
#pragma unroll
            for (int j = 0; j < 4; j++) { MUL2(accO[ip][j], cc) }
#pragma unroll
            for (int j = 0; j < 4; j++)
                *(float2*)(Pt + (tx*4+j)*SPT + ty*8 + 2*ip) = make_float2(sA[j], sB[j]);
        }
        __syncthreads();

#pragma unroll 4
        for (int c = 0; c < 64; c++) {
            const float* pp = Pt + c*SPT + ty*8;
            ulonglong2 p01 = *(const ulonglong2*)pp;
            ulonglong2 p23 = *(const ulonglong2*)(pp + 4);
            float4 v4 = *(const float4*)(Vs + c*SVT + tx*4);
            u64 b0,b1,b2,b3;
            DUP2(b0,v4.x) DUP2(b1,v4.y) DUP2(b2,v4.z) DUP2(b3,v4.w)
            FMA2(accO[0][0],p01.x,b0) FMA2(accO[0][1],p01.x,b1) FMA2(accO[0][2],p01.x,b2) FMA2(accO[0][3],p01.x,b3)
            FMA2(accO[1][0],p01.y,b0) FMA2(accO[1][1],p01.y,b1) FMA2(accO[1][2],p01.y,b2) FMA2(accO[1][3],p01.y,b3)
            FMA2(accO[2][0],p23.x,b0) FMA2(accO[2][1],p23.x,b1) FMA2(accO[2][2],p23.x,b2) FMA2(accO[2][3],p23.x,b3)
            FMA2(accO[3][0],p23.y,b0) FMA2(accO[3][1],p23.y,b1) FMA2(accO[3][2],p23.y,b2) FMA2(accO[3][3],p23.y,b3)
        }
    }

    // epilogue: normalize + bf16 hi/lo split directly into g_att_hi/lo
    int b = bh >> 4, h = bh & 15;
#pragma unroll
    for (int ip = 0; ip < 4; ip++) {
        float o0[4], o1[4];
#pragma unroll
        for (int j = 0; j < 4; j++) { UNPK2(o0[j], o1[j], accO[ip][j]) }
        float i0 = 1.f / l_run[2*ip], i1 = 1.f / l_run[2*ip+1];
        int r0 = qr0 + ty*8 + 2*ip;
        size_t d0 = (size_t)(b * SEQ + r0) * DMODEL + h*64 + tx*4;
        size_t d1 = d0 + DMODEL;
#pragma unroll
        for (int j = 0; j < 4; j++) {
            bf16 hh_, ll_;
            split1(o0[j]*i0, hh_, ll_);
            g_att_hi[d0 + j] = hh_; g_att_lo[d0 + j] = ll_;
            split1(o1[j]*i1, hh_, ll_);
            g_att_hi[d1 + j] = hh_; g_att_lo[d1 + j] = ll_;
        }
    }
}

// ---------------- launch ----------------
extern "C" void kernel_launch(void* const* d_in, const int* in_sizes, int n_in,
                              void* d_out, int out_size)
{
    (void)n_in; (void)out_size;
    const float* x   = (const float*)d_in[0];
    const float* qU  = (const float*)d_in[1];
    const float* qV  = (const float*)d_in[2];
    const float* kU  = (const float*)d_in[3];
    const float* kV  = (const float*)d_in[4];
    const float* vU  = (const float*)d_in[5];
    const float* vV  = (const float*)d_in[6];
    const float* ql  = (const float*)d_in[7];
    const float* kl  = (const float*)d_in[8];
    const float* vl  = (const float*)d_in[9];
    const float* ow  = (const float*)d_in[10];
    const int*   tk  = (const int*)d_in[11];
    int P = in_sizes[7];

    cudaFuncSetAttribute(attn_kernel, cudaFuncAttributeMaxDynamicSharedMemorySize, ATT_SMEM);

    topk_kernel<<<1, 32>>>(ql, kl, vl, tk, P);

    conv_x<<<4096, 256>>>(x);
    conv_w<<<1024, 256>>>(ow);
    conv_ut<<<dim3(3, 16, 8), 256>>>(qU, kU, vU);
    conv_vt<<<dim3(3, 16, 8), 256>>>(qV, kV, vV);

    mma_gemm_xu<<<dim3(32, 8, 3), 256>>>();
    mma_gemm_hv<<<dim3(32, 8, 3), 256>>>();
    attn_kernel<<<dim3(SEQ / 128, BATCH * NHEAD), 256, ATT_SMEM>>>();
    mma_gemm_out<<<dim3(32, 8), 256>>>((float*)d_out);
}

// round 14
// speedup vs baseline: 3.4016x; 1.1332x over previous
#include <cuda_runtime.h>
#include <cuda_bf16.h>
#include <cstdint>

#define DMODEL 1024
#define SEQ    1024
#define BATCH  4
#define NHEAD  16
#define HDIM   64
#define RNK    64
#define MROWS  (BATCH*SEQ)
#define PMAX   64

typedef unsigned long long u64;
typedef __nv_bfloat16 bf16;

// ---------------- packed fp32x2 helpers (attention) ----------------
#define FMA2(c,a,b) asm("fma.rn.f32x2 %0, %1, %2, %0;" : "+l"(c) : "l"(a), "l"(b));
#define MUL2(c,s)   asm("mul.rn.f32x2 %0, %0, %1;"     : "+l"(c) : "l"(s));
#define DUP2(d,f)   asm("mov.b64 %0, {%1, %1};" : "=l"(d) : "f"(f));
#define PACK2(d,lo,hi) asm("mov.b64 %0, {%1, %2};" : "=l"(d) : "f"(lo), "f"(hi));
#define UNPK2(lo,hi,v) asm("mov.b64 {%0, %1}, %2;" : "=f"(lo), "=f"(hi) : "l"(v));

// ---------------- warp MMA helpers (arch-agnostic sm_80+ PTX) ----------------
__device__ __forceinline__ uint32_t smem_u32(const void* p) {
    uint32_t a;
    asm("{ .reg .u64 t; cvta.to.shared.u64 t, %1; cvt.u32.u64 %0, t; }" : "=r"(a) : "l"(p));
    return a;
}
__device__ __forceinline__ void ldsm4(uint32_t* r, uint32_t addr) {
    asm volatile("ldmatrix.sync.aligned.m8n8.x4.shared.b16 {%0,%1,%2,%3}, [%4];"
        : "=r"(r[0]), "=r"(r[1]), "=r"(r[2]), "=r"(r[3]) : "r"(addr));
}
__device__ __forceinline__ void hmma(float* d, const uint32_t* a, const uint32_t* b) {
    asm volatile("mma.sync.aligned.m16n8k16.row.col.f32.bf16.bf16.f32 "
        "{%0,%1,%2,%3}, {%4,%5,%6,%7}, {%8,%9}, {%0,%1,%2,%3};"
        : "+f"(d[0]), "+f"(d[1]), "+f"(d[2]), "+f"(d[3])
        : "r"(a[0]), "r"(a[1]), "r"(a[2]), "r"(a[3]), "r"(b[0]), "r"(b[1]));
}
#define CP_ASYNC16(dst, src) \
    asm volatile("cp.async.cg.shared.global [%0], [%1], 16;" :: "r"(dst), "l"(src))
#define CP_COMMIT() asm volatile("cp.async.commit_group;")
#define CP_WAIT1()  asm volatile("cp.async.wait_group 1;" ::: "memory")
#define CP_WAIT0()  asm volatile("cp.async.wait_group 0;" ::: "memory")

// ---------------- device scratch (uint4/float4-typed: forced 16B alignment) ------------
// NOTE: these symbols are ONLY ever referenced from device code (never as kernel args).
__device__ uint4  g_x_hi_r [(size_t)MROWS*1024/8];
__device__ uint4  g_x_lo_r [(size_t)MROWS*1024/8];
__device__ uint4  g_w_hi_r [(size_t)1024*1024/8];
__device__ uint4  g_w_lo_r [(size_t)1024*1024/8];
__device__ uint4  g_ut_hi_r[(size_t)3*16*64*1024/8];
__device__ uint4  g_ut_lo_r[(size_t)3*16*64*1024/8];
__device__ uint4  g_vt_hi_r[(size_t)3*1024*1024/8];
__device__ uint4  g_vt_lo_r[(size_t)3*1024*1024/8];
__device__ uint4  g_h_hi_r [(size_t)3*MROWS*1024/8];
__device__ uint4  g_h_lo_r [(size_t)3*MROWS*1024/8];
__device__ uint4  g_att_hi_r[(size_t)MROWS*1024/8];
__device__ uint4  g_att_lo_r[(size_t)MROWS*1024/8];
__device__ float4 g_q_r   [(size_t)BATCH*NHEAD*SEQ*HDIM/4];
__device__ float4 g_k_r   [(size_t)BATCH*NHEAD*SEQ*HDIM/4];
__device__ float4 g_v_r   [(size_t)BATCH*NHEAD*SEQ*HDIM/4];
__device__ float g_tw[3][PMAX];
__device__ int   g_ti[3][PMAX];
__device__ int   g_K;

#define g_x_hi  ((bf16*)g_x_hi_r)
#define g_x_lo  ((bf16*)g_x_lo_r)
#define g_w_hi  ((bf16*)g_w_hi_r)
#define g_w_lo  ((bf16*)g_w_lo_r)
#define g_ut_hi ((bf16*)g_ut_hi_r)
#define g_ut_lo ((bf16*)g_ut_lo_r)
#define g_vt_hi ((bf16*)g_vt_hi_r)
#define g_vt_lo ((bf16*)g_vt_lo_r)
#define g_h_hi  ((bf16*)g_h_hi_r)
#define g_h_lo  ((bf16*)g_h_lo_r)
#define g_att_hi ((bf16*)g_att_hi_r)
#define g_att_lo ((bf16*)g_att_lo_r)
#define g_q     ((float*)g_q_r)
#define g_k     ((float*)g_k_r)
#define g_v     ((float*)g_v_r)

// ---------------- top-k gating ----------------
__global__ void topk_kernel(const float* __restrict__ ql, const float* __restrict__ kl,
                            const float* __restrict__ vl, const int* __restrict__ tkp, int P)
{
    if (threadIdx.x != 0) return;
    int K = *tkp; if (K > P) K = P; if (K < 1) K = 1;
    g_K = K;
    const float* ls[3] = {ql, kl, vl};
    for (int p = 0; p < 3; p++) {
        const float* lg = ls[p];
        bool used[PMAX];
        for (int i = 0; i < P; i++) used[i] = false;
        for (int t = 0; t < K; t++) {
            int best = 0; float bv = -3.4e38f;
            for (int i = 0; i < P; i++)
                if (!used[i] && lg[i] > bv) { bv = lg[i]; best = i; }
            used[best] = true;
            g_ti[p][t] = best;
        }
        float mx = -3.4e38f;
        for (int t = 0; t < K; t++) { float v = lg[g_ti[p][t]]; if (v > mx) mx = v; }
        float ssum = 0.f, w[PMAX];
        for (int t = 0; t < K; t++) { w[t] = expf(lg[g_ti[p][t]] - mx); ssum += w[t]; }
        for (int t = 0; t < K; t++) g_tw[p][t] = w[t] / ssum;
    }
}

// ---------------- bf16 split conversions ----------------
__device__ __forceinline__ void split1(float v, bf16& h, bf16& l) {
    h = __float2bfloat16(v);
    l = __float2bfloat16(v - __bfloat162float(h));
}

__global__ void conv_x(const float* __restrict__ src)
{
    int i = blockIdx.x * blockDim.x + threadIdx.x;   // 1M float4s exactly
    float4 v = ((const float4*)src)[i];
    bf16 h0,h1,h2,h3,l0,l1,l2,l3;
    split1(v.x,h0,l0); split1(v.y,h1,l1); split1(v.z,h2,l2); split1(v.w,h3,l3);
    g_x_hi[4*i+0]=h0; g_x_hi[4*i+1]=h1; g_x_hi[4*i+2]=h2; g_x_hi[4*i+3]=h3;
    g_x_lo[4*i+0]=l0; g_x_lo[4*i+1]=l1; g_x_lo[4*i+2]=l2; g_x_lo[4*i+3]=l3;
}

__global__ void conv_w(const float* __restrict__ src)
{
    int i = blockIdx.x * blockDim.x + threadIdx.x;   // 256K float4s exactly
    float4 v = ((const float4*)src)[i];
    bf16 h0,h1,h2,h3,l0,l1,l2,l3;
    split1(v.x,h0,l0); split1(v.y,h1,l1); split1(v.z,h2,l2); split1(v.w,h3,l3);
    g_w_hi[4*i+0]=h0; g_w_hi[4*i+1]=h1; g_w_hi[4*i+2]=h2; g_w_hi[4*i+3]=h3;
    g_w_lo[4*i+0]=l0; g_w_lo[4*i+1]=l1; g_w_lo[4*i+2]=l2; g_w_lo[4*i+3]=l3;
}

// Ut[p][kc][j][c] = U[prim][c][j]   grid (3, 16, 16), smem-tiled transpose
__global__ __launch_bounds__(256) void conv_ut(const float* __restrict__ qU,
    const float* __restrict__ kU, const float* __restrict__ vU)
{
    int p = blockIdx.x, kc = blockIdx.y;
    if (kc >= g_K) return;
    __shared__ float tile[64][65];
    const float* U = p == 0 ? qU : p == 1 ? kU : vU;
    const float* Up = U + (size_t)g_ti[p][kc] * 65536;
    int c0 = blockIdx.z * 64;
    for (int idx = threadIdx.x; idx < 4096; idx += 256) {
        int rc = idx >> 6, jj = idx & 63;
        tile[rc][jj] = Up[(size_t)(c0 + rc) * 64 + jj];     // coalesced read
    }
    __syncthreads();
    size_t base = (size_t)(p * 16 + kc) * 65536;
    for (int idx = threadIdx.x; idx < 4096; idx += 256) {
        int jj = idx >> 6, rc = idx & 63;
        bf16 h, l; split1(tile[rc][jj], h, l);
        g_ut_hi[base + (size_t)jj * 1024 + c0 + rc] = h;    // coalesced write
        g_ut_lo[base + (size_t)jj * 1024 + c0 + rc] = l;
    }
}

// Vt[p][n][kc*64+j] = V[prim(kc)][j][n]   grid (3, 16, 16), smem-tiled transpose
__global__ __launch_bounds__(256) void conv_vt(const float* __restrict__ qV,
    const float* __restrict__ kV, const float* __restrict__ vV)
{
    int p = blockIdx.x, kc = blockIdx.y;
    if (kc >= g_K) return;
    __shared__ float tile[64][65];
    const float* V = p == 0 ? qV : p == 1 ? kV : vV;
    const float* Vp = V + (size_t)g_ti[p][kc] * 65536;
    int n0 = blockIdx.z * 64;
    for (int idx = threadIdx.x; idx < 4096; idx += 256) {
        int j = idx >> 6, nn = idx & 63;
        tile[j][nn] = Vp[(size_t)j * 1024 + n0 + nn];       // coalesced read
    }
    __syncthreads();
    for (int idx = threadIdx.x; idx < 4096; idx += 256) {
        int nn = idx >> 6, j = idx & 63;
        bf16 h, l; split1(tile[j][nn], h, l);
        size_t dst = ((size_t)p * 1024 + n0 + nn) * 1024 + kc * 64 + j;  // coalesced write
        g_vt_hi[dst] = h;
        g_vt_lo[dst] = l;
    }
}

// ---------------- HMMA GEMM: 128x128 tile, BK=64, 256 thr, cp.async 2-stage -------------
// smem row stride 72 bf16 (144 B): ldmatrix 8-row phases hit 8 distinct 16B slots mod 128B.
#define SAS 72
#define ASZE (128*SAS)
#define BSZE (128*SAS)
#define GSMEM (2*(ASZE + BSZE) * 2)

#define MMA_ISSUE(buf, s_, kkv)                                                       \
    {                                                                                 \
        const bf16* Ap_ = ((s_) == 1) ? (AlP) : (AhP);                                \
        const bf16* Bp_ = ((s_) == 2) ? (BlP) : (BhP);                                \
        size_t ko_ = (size_t)(kkv) * 64;                                              \
        _Pragma("unroll")                                                             \
        for (int it = 0; it < 4; it++) {                                              \
            int u = tid + it * 256; int r = u >> 3, k8 = (u & 7) * 8;                 \
            CP_ASYNC16(sbA + (uint32_t)((buf)*ASZE + r*SAS + k8) * 2,                 \
                       Ap_ + (Abase) + (size_t)r * 1024 + ko_ + k8);                  \
            CP_ASYNC16(sbB + (uint32_t)((buf)*BSZE + r*SAS + k8) * 2,                 \
                       Bp_ + (Bbase) + (size_t)r * 1024 + ko_ + k8);                  \
        }                                                                             \
        CP_COMMIT();                                                                  \
    }

#define MMA_BODY(AhP, AlP, BhP, BlP, Abase, Bbase, PST, NST)                          \
    extern __shared__ __align__(16) bf16 dsm[];                                       \
    int tid = threadIdx.x, w = tid >> 5, l = tid & 31;                                \
    int gid = l >> 2, tig = l & 3;                                                    \
    int g_ = l >> 3, rrl = l & 7;                                                     \
    int aB = w * (16*SAS) + ((g_ & 1) * 8 + rrl) * SAS + (g_ >> 1) * 8;               \
    int bB = ((g_ >> 1) * 8 + rrl) * SAS + (g_ & 1) * 8;                              \
    uint32_t sbA = smem_u32(dsm);                                                     \
    uint32_t sbB = sbA + 2*ASZE*2;                                                    \
    float acc[16][4];                                                                 \
    _Pragma("unroll") for (int i_ = 0; i_ < 16; i_++)                                 \
    _Pragma("unroll") for (int j_ = 0; j_ < 4; j_++) acc[i_][j_] = 0.f;               \
    MMA_ISSUE(0, 0, 0)                                                                \
    for (int c = 0; c < (NST); c++) {                                                 \
        int cur = c & 1;                                                              \
        if (c + 1 < (NST)) {                                                          \
            int s_ = 0, kk = c + 1;                                                   \
            if (kk >= (PST)) { s_ = 1; kk -= (PST); }                                 \
            if (kk >= (PST)) { s_ = 2; kk -= (PST); }                                 \
            MMA_ISSUE(cur ^ 1, s_, kk)                                                \
            CP_WAIT1();                                                               \
        } else {                                                                      \
            CP_WAIT0();                                                               \
        }                                                                             \
        __syncthreads();                                                              \
        _Pragma("unroll")                                                             \
        for (int k16 = 0; k16 < 4; k16++) {                                           \
            uint32_t av[4];                                                           \
            ldsm4(av, sbA + (uint32_t)(cur*ASZE + aB + k16*16) * 2);                  \
            _Pragma("unroll")                                                         \
            for (int ph = 0; ph < 2; ph++) {                                          \
                uint32_t bfr[16];                                                     \
                _Pragma("unroll")                                                     \
                for (int t = 0; t < 4; t++)                                           \
                    ldsm4(bfr + 4*t, sbB + (uint32_t)(cur*BSZE + bB + (ph*4+t)*(16*SAS) + k16*16) * 2); \
                _Pragma("unroll")                                                     \
                for (int nt8 = 0; nt8 < 8; nt8++)                                     \
                    hmma(acc[ph*8 + nt8], av, bfr + (nt8 >> 1) * 4 + (nt8 & 1) * 2);  \
            }                                                                         \
        }                                                                             \
        __syncthreads();                                                              \
    }

// GEMM 1: h[p][m][kc*64+n] = tw * x[m,:] @ U[prim], kc-pairs fused  grid (32, 8, 3)
__global__ __launch_bounds__(256, 2) void mma_gemm_xu()
{
    int proj = blockIdx.z, kc0 = blockIdx.y * 2;
    int K = g_K;
    if (kc0 >= K) return;
    int m0 = blockIdx.x << 7;
    const bf16* Bh = g_ut_hi + (size_t)(proj * 16 + kc0) * 65536;
    const bf16* Bl = g_ut_lo + (size_t)(proj * 16 + kc0) * 65536;
    float tws[2];
    tws[0] = g_tw[proj][kc0];
    tws[1] = (kc0 + 1 < K) ? g_tw[proj][kc0 + 1] : 0.f;
    const bf16* AhP = g_x_hi; const bf16* AlP = g_x_lo;
    const bf16* BhP = Bh;     const bf16* BlP = Bl;
    size_t Abase = (size_t)m0 * 1024, Bbase = 0;
    MMA_BODY(AhP, AlP, BhP, BlP, Abase, Bbase, 16, 48)
    int row = m0 + w * 16 + gid, lp = tig * 2;
#pragma unroll
    for (int nt = 0; nt < 16; nt++) {
        int n = nt * 8 + lp;
        int kcl = n >> 6;
        int kc = kc0 + kcl;
        if (kc < K) {
            float tw = tws[kcl];
            size_t b0_ = ((size_t)proj * MROWS + row) * 1024 + kc * 64 + (n & 63);
            size_t b1_ = b0_ + (size_t)8 * 1024;
            bf16 h0, l0, h1, l1;
            split1(tw * acc[nt][0], h0, l0); split1(tw * acc[nt][1], h1, l1);
            g_h_hi[b0_] = h0; g_h_hi[b0_ + 1] = h1;
            g_h_lo[b0_] = l0; g_h_lo[b0_ + 1] = l1;
            split1(tw * acc[nt][2], h0, l0); split1(tw * acc[nt][3], h1, l1);
            g_h_hi[b1_] = h0; g_h_hi[b1_ + 1] = h1;
            g_h_lo[b1_] = l0; g_h_lo[b1_ + 1] = l1;
        }
    }
}

// GEMM 2: qkv = h @ Vt -> [B,H,S,D] fp32, head-pairs fused   grid (32, 8, 3)
__global__ __launch_bounds__(256, 2) void mma_gemm_hv()
{
    int proj = blockIdx.z, hh0 = blockIdx.y * 2;
    int m0 = blockIdx.x << 7;
    int pst = g_K;
    int nst = 3 * pst;
    const bf16* AhP = g_h_hi + (size_t)proj * MROWS * 1024;
    const bf16* AlP = g_h_lo + (size_t)proj * MROWS * 1024;
    const bf16* BhP = g_vt_hi + ((size_t)proj * 1024 + (hh0 << 6)) * 1024;
    const bf16* BlP = g_vt_lo + ((size_t)proj * 1024 + (hh0 << 6)) * 1024;
    size_t Abase = (size_t)m0 * 1024, Bbase = 0;
    MMA_BODY(AhP, AlP, BhP, BlP, Abase, Bbase, pst, nst)
    float* dst = proj == 0 ? g_q : proj == 1 ? g_k : g_v;
    int lp = tig * 2;
    int m = m0 + w * 16 + gid;
    int bb = m >> 10, sq = m & 1023;
#pragma unroll
    for (int nt = 0; nt < 16; nt++) {
        int n = nt * 8 + lp;
        int hh = hh0 + (n >> 6);
        float* d0 = dst + (((size_t)(bb * NHEAD + hh) * SEQ + sq) << 6) + (n & 63);
        float* d1 = d0 + (8 << 6);
        d0[0] = acc[nt][0]; d0[1] = acc[nt][1];
        d1[0] = acc[nt][2]; d1[1] = acc[nt][3];
    }
}

// GEMM 3: out = att @ W^T    grid (32, 8)
__global__ __launch_bounds__(256, 2) void mma_gemm_out(float* __restrict__ out)
{
    int n0 = blockIdx.y << 7;
    int m0 = blockIdx.x << 7;
    const bf16* AhP = g_att_hi; const bf16* AlP = g_att_lo;
    const bf16* BhP = g_w_hi;   const bf16* BlP = g_w_lo;
    size_t Abase = (size_t)m0 * 1024, Bbase = (size_t)n0 * 1024;
    MMA_BODY(AhP, AlP, BhP, BlP, Abase, Bbase, 16, 48)
    int lp = tig * 2;
    int row = m0 + w * 16 + gid;
    float* d0 = out + (size_t)row * 1024 + n0;
    float* d1 = d0 + (size_t)8 * 1024;
#pragma unroll
    for (int nt = 0; nt < 16; nt++) {
        int n = nt * 8 + lp;
        d0[n] = acc[nt][0]; d0[n + 1] = acc[nt][1];
        d1[n] = acc[nt][2]; d1[n + 1] = acc[nt][3];
    }
}

// ---------------- flash attention (proven core; bf16 hi/lo split epilogue) --------------
#define SQT 132
#define SKT 68
#define SVT 68
#define SPT 132
#define QS_OFF 0
#define KS_OFF (64*SQT)
#define VS_OFF (KS_OFF + 64*SKT)
#define PT_OFF (VS_OFF + 64*SVT)
#define ATT_SMEM ((PT_OFF + 64*SPT) * 4)

__global__ __launch_bounds__(256, 2) void attn_kernel()
{
    extern __shared__ __align__(16) float sm[];
    float* Qs = sm + QS_OFF;
    float* Ks = sm + KS_OFF;
    float* Vs = sm + VS_OFF;
    float* Pt = sm + PT_OFF;

    int qt = blockIdx.x, bh = blockIdx.y;
    const float* qb = g_q + (size_t)bh * SEQ * HDIM;
    const float* kb = g_k + (size_t)bh * SEQ * HDIM;
    const float* vb = g_v + (size_t)bh * SEQ * HDIM;

    int tid = threadIdx.x;
    int tx = tid & 15, ty = tid >> 4;
    int qr0 = qt << 7;

#pragma unroll
    for (int it = 0; it < 8; it++) {
        int idx = tid + it * 256;
        int r = idx >> 4, d4 = idx & 15;
        float4 v = *(const float4*)(qb + (size_t)(qr0 + r) * 64 + d4 * 4);
        Qs[(d4*4+0)*SQT + r] = v.x;
        Qs[(d4*4+1)*SQT + r] = v.y;
        Qs[(d4*4+2)*SQT + r] = v.z;
        Qs[(d4*4+3)*SQT + r] = v.w;
    }

    float m_run[8], l_run[8];
#pragma unroll
    for (int i = 0; i < 8; i++) { m_run[i] = -3.0e38f; l_run[i] = 0.f; }
    u64 accO[4][4];
#pragma unroll
    for (int i = 0; i < 4; i++)
#pragma unroll
        for (int j = 0; j < 4; j++) accO[i][j] = 0ull;

    int ktmax = 2*qt + 1;
    for (int kt = 0; kt <= ktmax; kt++) {
        int kr0 = kt << 6;
        __syncthreads();
#pragma unroll
        for (int it = 0; it < 4; it++) {
            int idx = tid + it * 256;
            int r = idx >> 4, d4 = idx & 15;
            float4 kv = *(const float4*)(kb + (size_t)(kr0 + r) * 64 + d4 * 4);
            Ks[(d4*4+0)*SKT + r] = kv.x;
            Ks[(d4*4+1)*SKT + r] = kv.y;
            Ks[(d4*4+2)*SKT + r] = kv.z;
            Ks[(d4*4+3)*SKT + r] = kv.w;
            float4 vv = *(const float4*)(vb + (size_t)(kr0 + r) * 64 + d4 * 4);
            *(float4*)(Vs + r*SVT + d4*4) = vv;
        }
        __syncthreads();

        u64 sp[4][4];
#pragma unroll
        for (int i = 0; i < 4; i++)
#pragma unroll
            for (int j = 0; j < 4; j++) sp[i][j] = 0ull;
#pragma unroll 4
        for (int d = 0; d < 64; d++) {
            const float* qp = Qs + d*SQT + ty*8;
            ulonglong2 a01 = *(const ulonglong2*)qp;
            ulonglong2 a23 = *(const ulonglong2*)(qp + 4);
            float4 b4 = *(const float4*)(Ks + d*SKT + tx*4);
            u64 b0,b1,b2,b3;
            DUP2(b0,b4.x) DUP2(b1,b4.y) DUP2(b2,b4.z) DUP2(b3,b4.w)
            FMA2(sp[0][0],a01.x,b0) FMA2(sp[0][1],a01.x,b1) FMA2(sp[0][2],a01.x,b2) FMA2(sp[0][3],a01.x,b3)
            FMA2(sp[1][0],a01.y,b0) FMA2(sp[1][1],a01.y,b1) FMA2(sp[1][2],a01.y,b2) FMA2(sp[1][3],a01.y,b3)
            FMA2(sp[2][0],a23.x,b0) FMA2(sp[2][1],a23.x,b1) FMA2(sp[2][2],a23.x,b2) FMA2(sp[2][3],a23.x,b3)
            FMA2(sp[3][0],a23.y,b0) FMA2(sp[3][1],a23.y,b1) FMA2(sp[3][2],a23.y,b2) FMA2(sp[3][3],a23.y,b3)
        }

        bool need_mask = (kt >= 2*qt);
#pragma unroll
        for (int ip = 0; ip < 4; ip++) {
            float sA[4], sB[4];
#pragma unroll
            for (int j = 0; j < 4; j++) { UNPK2(sA[j], sB[j], sp[ip][j]) }
            int rA = qr0 + ty*8 + 2*ip, rB = rA + 1;
#pragma unroll
            for (int j = 0; j < 4; j++) {
                sA[j] *= 0.125f; sB[j] *= 0.125f;
                if (need_mask) {
                    int cg = kr0 + tx*4 + j;
                    if (cg > rA) sA[j] = -3.0e38f;
                    if (cg > rB) sB[j] = -3.0e38f;
                }
            }
            float mxA = fmaxf(fmaxf(sA[0],sA[1]), fmaxf(sA[2],sA[3]));
            float mxB = fmaxf(fmaxf(sB[0],sB[1]), fmaxf(sB[2],sB[3]));
#pragma unroll
            for (int o = 1; o <= 8; o <<= 1) {
                mxA = fmaxf(mxA, __shfl_xor_sync(0xffffffffu, mxA, o));
                mxB = fmaxf(mxB, __shfl_xor_sync(0xffffffffu, mxB, o));
            }
            float mnA = fmaxf(m_run[2*ip],   mxA);
            float mnB = fmaxf(m_run[2*ip+1], mxB);
            float cA = __expf(m_run[2*ip]   - mnA);
            float cB = __expf(m_run[2*ip+1] - mnB);
            float pA = 0.f, pB = 0.f;
#pragma unroll
            for (int j = 0; j < 4; j++) {
                sA[j] = __expf(sA[j] - mnA); pA += sA[j];
                sB[j] = __expf(sB[j] - mnB); pB += sB[j];
            }
#pragma unroll
            for (int o = 1; o <= 8; o <<= 1) {
                pA += __shfl_xor_sync(0xffffffffu, pA, o);
                pB += __shfl_xor_sync(0xffffffffu, pB, o);
            }
            l_run[2*ip]   = l_run[2*ip]   * cA + pA;  m_run[2*ip]   = mnA;
            l_run[2*ip+1] = l_run[2*ip+1] * cB + pB;  m_run[2*ip+1] = mnB;
            u64 cc; PACK2(cc, cA, cB)
#pragma unroll
            for (int j = 0; j < 4; j++) { MUL2(accO[ip][j], cc) }
#pragma unroll
            for (int j = 0; j < 4; j++)
                *(float2*)(Pt + (tx*4+j)*SPT + ty*8 + 2*ip) = make_float2(sA[j], sB[j]);
        }
        __syncthreads();

#pragma unroll 4
        for (int c = 0; c < 64; c++) {
            const float* pp = Pt + c*SPT + ty*8;
            ulonglong2 p01 = *(const ulonglong2*)pp;
            ulonglong2 p23 = *(const ulonglong2*)(pp + 4);
            float4 v4 = *(const float4*)(Vs + c*SVT + tx*4);
            u64 b0,b1,b2,b3;
            DUP2(b0,v4.x) DUP2(b1,v4.y) DUP2(b2,v4.z) DUP2(b3,v4.w)
            FMA2(accO[0][0],p01.x,b0) FMA2(accO[0][1],p01.x,b1) FMA2(accO[0][2],p01.x,b2) FMA2(accO[0][3],p01.x,b3)
            FMA2(accO[1][0],p01.y,b0) FMA2(accO[1][1],p01.y,b1) FMA2(accO[1][2],p01.y,b2) FMA2(accO[1][3],p01.y,b3)
            FMA2(accO[2][0],p23.x,b0) FMA2(accO[2][1],p23.x,b1) FMA2(accO[2][2],p23.x,b2) FMA2(accO[2][3],p23.x,b3)
            FMA2(accO[3][0],p23.y,b0) FMA2(accO[3][1],p23.y,b1) FMA2(accO[3][2],p23.y,b2) FMA2(accO[3][3],p23.y,b3)
        }
    }

    // epilogue: normalize + bf16 hi/lo split directly into g_att_hi/lo
    int b = bh >> 4, h = bh & 15;
#pragma unroll
    for (int ip = 0; ip < 4; ip++) {
        float o0[4], o1[4];
#pragma unroll
        for (int j = 0; j < 4; j++) { UNPK2(o0[j], o1[j], accO[ip][j]) }
        float i0 = 1.f / l_run[2*ip], i1 = 1.f / l_run[2*ip+1];
        int r0 = qr0 + ty*8 + 2*ip;
        size_t d0 = (size_t)(b * SEQ + r0) * DMODEL + h*64 + tx*4;
        size_t d1 = d0 + DMODEL;
#pragma unroll
        for (int j = 0; j < 4; j++) {
            bf16 hh_, ll_;
            split1(o0[j]*i0, hh_, ll_);
            g_att_hi[d0 + j] = hh_; g_att_lo[d0 + j] = ll_;
            split1(o1[j]*i1, hh_, ll_);
            g_att_hi[d1 + j] = hh_; g_att_lo[d1 + j] = ll_;
        }
    }
}

// ---------------- launch ----------------
extern "C" void kernel_launch(void* const* d_in, const int* in_sizes, int n_in,
                              void* d_out, int out_size)
{
    (void)n_in; (void)out_size;
    const float* x   = (const float*)d_in[0];
    const float* qU  = (const float*)d_in[1];
    const float* qV  = (const float*)d_in[2];
    const float* kU  = (const float*)d_in[3];
    const float* kV  = (const float*)d_in[4];
    const float* vU  = (const float*)d_in[5];
    const float* vV  = (const float*)d_in[6];
    const float* ql  = (const float*)d_in[7];
    const float* kl  = (const float*)d_in[8];
    const float* vl  = (const float*)d_in[9];
    const float* ow  = (const float*)d_in[10];
    const int*   tk  = (const int*)d_in[11];
    int P = in_sizes[7];

    cudaFuncSetAttribute(attn_kernel,  cudaFuncAttributeMaxDynamicSharedMemorySize, ATT_SMEM);
    cudaFuncSetAttribute(mma_gemm_xu,  cudaFuncAttributeMaxDynamicSharedMemorySize, GSMEM);
    cudaFuncSetAttribute(mma_gemm_hv,  cudaFuncAttributeMaxDynamicSharedMemorySize, GSMEM);
    cudaFuncSetAttribute(mma_gemm_out, cudaFuncAttributeMaxDynamicSharedMemorySize, GSMEM);

    topk_kernel<<<1, 32>>>(ql, kl, vl, tk, P);

    conv_x<<<4096, 256>>>(x);
    conv_w<<<1024, 256>>>(ow);
    conv_ut<<<dim3(3, 16, 16), 256>>>(qU, kU, vU);
    conv_vt<<<dim3(3, 16, 16), 256>>>(qV, kV, vV);

    mma_gemm_xu<<<dim3(32, 8, 3), 256, GSMEM>>>();
    mma_gemm_hv<<<dim3(32, 8, 3), 256, GSMEM>>>();
    attn_kernel<<<dim3(SEQ / 128, BATCH * NHEAD), 256, ATT_SMEM>>>();
    mma_gemm_out<<<dim3(32, 8), 256, GSMEM>>>((float*)d_out);
}

// round 15
// speedup vs baseline: 4.5949x; 1.3508x over previous
#include <cuda_runtime.h>
#include <cuda_bf16.h>
#include <cstdint>

#define DMODEL 1024
#define SEQ    1024
#define BATCH  4
#define NHEAD  16
#define HDIM   64
#define RNK    64
#define MROWS  (BATCH*SEQ)
#define PMAX   64

typedef unsigned long long u64;
typedef __nv_bfloat16 bf16;

// ---------------- warp MMA helpers (arch-agnostic sm_80+ PTX) ----------------
__device__ __forceinline__ uint32_t smem_u32(const void* p) {
    uint32_t a;
    asm("{ .reg .u64 t; cvta.to.shared.u64 t, %1; cvt.u32.u64 %0, t; }" : "=r"(a) : "l"(p));
    return a;
}
__device__ __forceinline__ void ldsm4(uint32_t* r, uint32_t addr) {
    asm volatile("ldmatrix.sync.aligned.m8n8.x4.shared.b16 {%0,%1,%2,%3}, [%4];"
        : "=r"(r[0]), "=r"(r[1]), "=r"(r[2]), "=r"(r[3]) : "r"(addr));
}
__device__ __forceinline__ void hmma(float* d, const uint32_t* a, const uint32_t* b) {
    asm volatile("mma.sync.aligned.m16n8k16.row.col.f32.bf16.bf16.f32 "
        "{%0,%1,%2,%3}, {%4,%5,%6,%7}, {%8,%9}, {%0,%1,%2,%3};"
        : "+f"(d[0]), "+f"(d[1]), "+f"(d[2]), "+f"(d[3])
        : "r"(a[0]), "r"(a[1]), "r"(a[2]), "r"(a[3]), "r"(b[0]), "r"(b[1]));
}
#define CP_ASYNC16(dst, src) \
    asm volatile("cp.async.cg.shared.global [%0], [%1], 16;" :: "r"(dst), "l"(src))
#define CP_COMMIT() asm volatile("cp.async.commit_group;")
#define CP_WAIT1()  asm volatile("cp.async.wait_group 1;" ::: "memory")
#define CP_WAIT0()  asm volatile("cp.async.wait_group 0;" ::: "memory")

// ---------------- device scratch (uint4/float4-typed: forced 16B alignment) ------------
__device__ uint4  g_x_hi_r [(size_t)MROWS*1024/8];
__device__ uint4  g_x_lo_r [(size_t)MROWS*1024/8];
__device__ uint4  g_w_hi_r [(size_t)1024*1024/8];
__device__ uint4  g_w_lo_r [(size_t)1024*1024/8];
__device__ uint4  g_ut_hi_r[(size_t)3*16*64*1024/8];
__device__ uint4  g_ut_lo_r[(size_t)3*16*64*1024/8];
__device__ uint4  g_vt_hi_r[(size_t)3*1024*1024/8];
__device__ uint4  g_vt_lo_r[(size_t)3*1024*1024/8];
__device__ uint4  g_h_hi_r [(size_t)3*MROWS*1024/8];
__device__ uint4  g_h_lo_r [(size_t)3*MROWS*1024/8];
__device__ uint4  g_att_hi_r[(size_t)MROWS*1024/8];
__device__ uint4  g_att_lo_r[(size_t)MROWS*1024/8];
__device__ float4 g_q_r   [(size_t)BATCH*NHEAD*SEQ*HDIM/4];
__device__ float4 g_k_r   [(size_t)BATCH*NHEAD*SEQ*HDIM/4];
__device__ float4 g_v_r   [(size_t)BATCH*NHEAD*SEQ*HDIM/4];
__device__ float g_tw[3][PMAX];
__device__ int   g_ti[3][PMAX];
__device__ int   g_K;

#define g_x_hi  ((bf16*)g_x_hi_r)
#define g_x_lo  ((bf16*)g_x_lo_r)
#define g_w_hi  ((bf16*)g_w_hi_r)
#define g_w_lo  ((bf16*)g_w_lo_r)
#define g_ut_hi ((bf16*)g_ut_hi_r)
#define g_ut_lo ((bf16*)g_ut_lo_r)
#define g_vt_hi ((bf16*)g_vt_hi_r)
#define g_vt_lo ((bf16*)g_vt_lo_r)
#define g_h_hi  ((bf16*)g_h_hi_r)
#define g_h_lo  ((bf16*)g_h_lo_r)
#define g_att_hi ((bf16*)g_att_hi_r)
#define g_att_lo ((bf16*)g_att_lo_r)
#define g_q     ((float*)g_q_r)
#define g_k     ((float*)g_k_r)
#define g_v     ((float*)g_v_r)

// ---------------- top-k gating ----------------
__global__ void topk_kernel(const float* __restrict__ ql, const float* __restrict__ kl,
                            const float* __restrict__ vl, const int* __restrict__ tkp, int P)
{
    if (threadIdx.x != 0) return;
    int K = *tkp; if (K > P) K = P; if (K < 1) K = 1;
    g_K = K;
    const float* ls[3] = {ql, kl, vl};
    for (int p = 0; p < 3; p++) {
        const float* lg = ls[p];
        bool used[PMAX];
        for (int i = 0; i < P; i++) used[i] = false;
        for (int t = 0; t < K; t++) {
            int best = 0; float bv = -3.4e38f;
            for (int i = 0; i < P; i++)
                if (!used[i] && lg[i] > bv) { bv = lg[i]; best = i; }
            used[best] = true;
            g_ti[p][t] = best;
        }
        float mx = -3.4e38f;
        for (int t = 0; t < K; t++) { float v = lg[g_ti[p][t]]; if (v > mx) mx = v; }
        float ssum = 0.f, w[PMAX];
        for (int t = 0; t < K; t++) { w[t] = expf(lg[g_ti[p][t]] - mx); ssum += w[t]; }
        for (int t = 0; t < K; t++) g_tw[p][t] = w[t] / ssum;
    }
}

// ---------------- bf16 split conversions ----------------
__device__ __forceinline__ void split1(float v, bf16& h, bf16& l) {
    h = __float2bfloat16(v);
    l = __float2bfloat16(v - __bfloat162float(h));
}

__global__ void conv_x(const float* __restrict__ src)
{
    int i = blockIdx.x * blockDim.x + threadIdx.x;
    float4 v = ((const float4*)src)[i];
    bf16 h0,h1,h2,h3,l0,l1,l2,l3;
    split1(v.x,h0,l0); split1(v.y,h1,l1); split1(v.z,h2,l2); split1(v.w,h3,l3);
    g_x_hi[4*i+0]=h0; g_x_hi[4*i+1]=h1; g_x_hi[4*i+2]=h2; g_x_hi[4*i+3]=h3;
    g_x_lo[4*i+0]=l0; g_x_lo[4*i+1]=l1; g_x_lo[4*i+2]=l2; g_x_lo[4*i+3]=l3;
}

__global__ void conv_w(const float* __restrict__ src)
{
    int i = blockIdx.x * blockDim.x + threadIdx.x;
    float4 v = ((const float4*)src)[i];
    bf16 h0,h1,h2,h3,l0,l1,l2,l3;
    split1(v.x,h0,l0); split1(v.y,h1,l1); split1(v.z,h2,l2); split1(v.w,h3,l3);
    g_w_hi[4*i+0]=h0; g_w_hi[4*i+1]=h1; g_w_hi[4*i+2]=h2; g_w_hi[4*i+3]=h3;
    g_w_lo[4*i+0]=l0; g_w_lo[4*i+1]=l1; g_w_lo[4*i+2]=l2; g_w_lo[4*i+3]=l3;
}

// Ut[p][kc][j][c] = U[prim][c][j]   grid (3, 16, 16), smem-tiled transpose
__global__ __launch_bounds__(256) void conv_ut(const float* __restrict__ qU,
    const float* __restrict__ kU, const float* __restrict__ vU)
{
    int p = blockIdx.x, kc = blockIdx.y;
    if (kc >= g_K) return;
    __shared__ float tile[64][65];
    const float* U = p == 0 ? qU : p == 1 ? kU : vU;
    const float* Up = U + (size_t)g_ti[p][kc] * 65536;
    int c0 = blockIdx.z * 64;
    for (int idx = threadIdx.x; idx < 4096; idx += 256) {
        int rc = idx >> 6, jj = idx & 63;
        tile[rc][jj] = Up[(size_t)(c0 + rc) * 64 + jj];
    }
    __syncthreads();
    size_t base = (size_t)(p * 16 + kc) * 65536;
    for (int idx = threadIdx.x; idx < 4096; idx += 256) {
        int jj = idx >> 6, rc = idx & 63;
        bf16 h, l; split1(tile[rc][jj], h, l);
        g_ut_hi[base + (size_t)jj * 1024 + c0 + rc] = h;
        g_ut_lo[base + (size_t)jj * 1024 + c0 + rc] = l;
    }
}

// Vt[p][n][kc*64+j] = V[prim(kc)][j][n]   grid (3, 16, 16), smem-tiled transpose
__global__ __launch_bounds__(256) void conv_vt(const float* __restrict__ qV,
    const float* __restrict__ kV, const float* __restrict__ vV)
{
    int p = blockIdx.x, kc = blockIdx.y;
    if (kc >= g_K) return;
    __shared__ float tile[64][65];
    const float* V = p == 0 ? qV : p == 1 ? kV : vV;
    const float* Vp = V + (size_t)g_ti[p][kc] * 65536;
    int n0 = blockIdx.z * 64;
    for (int idx = threadIdx.x; idx < 4096; idx += 256) {
        int j = idx >> 6, nn = idx & 63;
        tile[j][nn] = Vp[(size_t)j * 1024 + n0 + nn];
    }
    __syncthreads();
    for (int idx = threadIdx.x; idx < 4096; idx += 256) {
        int nn = idx >> 6, j = idx & 63;
        bf16 h, l; split1(tile[j][nn], h, l);
        size_t dst = ((size_t)p * 1024 + n0 + nn) * 1024 + kc * 64 + j;
        g_vt_hi[dst] = h;
        g_vt_lo[dst] = l;
    }
}

// ---------------- HMMA GEMM: 128x128 tile, BK=64, 256 thr, cp.async 2-stage -------------
#define SAS 72
#define ASZE (128*SAS)
#define BSZE (128*SAS)
#define GSMEM (2*(ASZE + BSZE) * 2)

#define MMA_ISSUE(buf, s_, kkv)                                                       \
    {                                                                                 \
        const bf16* Ap_ = ((s_) == 1) ? (AlP) : (AhP);                                \
        const bf16* Bp_ = ((s_) == 2) ? (BlP) : (BhP);                                \
        size_t ko_ = (size_t)(kkv) * 64;                                              \
        _Pragma("unroll")                                                             \
        for (int it = 0; it < 4; it++) {                                              \
            int u = tid + it * 256; int r = u >> 3, k8 = (u & 7) * 8;                 \
            CP_ASYNC16(sbA + (uint32_t)((buf)*ASZE + r*SAS + k8) * 2,                 \
                       Ap_ + (Abase) + (size_t)r * 1024 + ko_ + k8);                  \
            CP_ASYNC16(sbB + (uint32_t)((buf)*BSZE + r*SAS + k8) * 2,                 \
                       Bp_ + (Bbase) + (size_t)r * 1024 + ko_ + k8);                  \
        }                                                                             \
        CP_COMMIT();                                                                  \
    }

#define MMA_BODY(AhP, AlP, BhP, BlP, Abase, Bbase, PST, NST)                          \
    extern __shared__ __align__(16) bf16 dsm[];                                       \
    int tid = threadIdx.x, w = tid >> 5, l = tid & 31;                                \
    int gid = l >> 2, tig = l & 3;                                                    \
    int g_ = l >> 3, rrl = l & 7;                                                     \
    int aB = w * (16*SAS) + ((g_ & 1) * 8 + rrl) * SAS + (g_ >> 1) * 8;               \
    int bB = ((g_ >> 1) * 8 + rrl) * SAS + (g_ & 1) * 8;                              \
    uint32_t sbA = smem_u32(dsm);                                                     \
    uint32_t sbB = sbA + 2*ASZE*2;                                                    \
    float acc[16][4];                                                                 \
    _Pragma("unroll") for (int i_ = 0; i_ < 16; i_++)                                 \
    _Pragma("unroll") for (int j_ = 0; j_ < 4; j_++) acc[i_][j_] = 0.f;               \
    MMA_ISSUE(0, 0, 0)                                                                \
    for (int c = 0; c < (NST); c++) {                                                 \
        int cur = c & 1;                                                              \
        if (c + 1 < (NST)) {                                                          \
            int s_ = 0, kk = c + 1;                                                   \
            if (kk >= (PST)) { s_ = 1; kk -= (PST); }                                 \
            if (kk >= (PST)) { s_ = 2; kk -= (PST); }                                 \
            MMA_ISSUE(cur ^ 1, s_, kk)                                                \
            CP_WAIT1();                                                               \
        } else {                                                                      \
            CP_WAIT0();                                                               \
        }                                                                             \
        __syncthreads();                                                              \
        _Pragma("unroll")                                                             \
        for (int k16 = 0; k16 < 4; k16++) {                                           \
            uint32_t av[4];                                                           \
            ldsm4(av, sbA + (uint32_t)(cur*ASZE + aB + k16*16) * 2);                  \
            _Pragma("unroll")                                                         \
            for (int ph = 0; ph < 2; ph++) {                                          \
                uint32_t bfr[16];                                                     \
                _Pragma("unroll")                                                     \
                for (int t = 0; t < 4; t++)                                           \
                    ldsm4(bfr + 4*t, sbB + (uint32_t)(cur*BSZE + bB + (ph*4+t)*(16*SAS) + k16*16) * 2); \
                _Pragma("unroll")                                                     \
                for (int nt8 = 0; nt8 < 8; nt8++)                                     \
                    hmma(acc[ph*8 + nt8], av, bfr + (nt8 >> 1) * 4 + (nt8 & 1) * 2);  \
            }                                                                         \
        }                                                                             \
        __syncthreads();                                                              \
    }

// GEMM 1: h[p][m][kc*64+n] = tw * x[m,:] @ U[prim], kc-pairs fused  grid (32, 8, 3)
__global__ __launch_bounds__(256, 2) void mma_gemm_xu()
{
    int proj = blockIdx.z, kc0 = blockIdx.y * 2;
    int K = g_K;
    if (kc0 >= K) return;
    int m0 = blockIdx.x << 7;
    const bf16* Bh = g_ut_hi + (size_t)(proj * 16 + kc0) * 65536;
    const bf16* Bl = g_ut_lo + (size_t)(proj * 16 + kc0) * 65536;
    float tws[2];
    tws[0] = g_tw[proj][kc0];
    tws[1] = (kc0 + 1 < K) ? g_tw[proj][kc0 + 1] : 0.f;
    const bf16* AhP = g_x_hi; const bf16* AlP = g_x_lo;
    const bf16* BhP = Bh;     const bf16* BlP = Bl;
    size_t Abase = (size_t)m0 * 1024, Bbase = 0;
    MMA_BODY(AhP, AlP, BhP, BlP, Abase, Bbase, 16, 48)
    int row = m0 + w * 16 + gid, lp = tig * 2;
#pragma unroll
    for (int nt = 0; nt < 16; nt++) {
        int n = nt * 8 + lp;
        int kcl = n >> 6;
        int kc = kc0 + kcl;
        if (kc < K) {
            float tw = tws[kcl];
            size_t b0_ = ((size_t)proj * MROWS + row) * 1024 + kc * 64 + (n & 63);
            size_t b1_ = b0_ + (size_t)8 * 1024;
            bf16 h0, l0, h1, l1;
            split1(tw * acc[nt][0], h0, l0); split1(tw * acc[nt][1], h1, l1);
            g_h_hi[b0_] = h0; g_h_hi[b0_ + 1] = h1;
            g_h_lo[b0_] = l0; g_h_lo[b0_ + 1] = l1;
            split1(tw * acc[nt][2], h0, l0); split1(tw * acc[nt][3], h1, l1);
            g_h_hi[b1_] = h0; g_h_hi[b1_ + 1] = h1;
            g_h_lo[b1_] = l0; g_h_lo[b1_ + 1] = l1;
        }
    }
}

// GEMM 2: qkv = h @ Vt -> [B,H,S,D] fp32, head-pairs fused   grid (32, 8, 3)
__global__ __launch_bounds__(256, 2) void mma_gemm_hv()
{
    int proj = blockIdx.z, hh0 = blockIdx.y * 2;
    int m0 = blockIdx.x << 7;
    int pst = g_K;
    int nst = 3 * pst;
    const bf16* AhP = g_h_hi + (size_t)proj * MROWS * 1024;
    const bf16* AlP = g_h_lo + (size_t)proj * MROWS * 1024;
    const bf16* BhP = g_vt_hi + ((size_t)proj * 1024 + (hh0 << 6)) * 1024;
    const bf16* BlP = g_vt_lo + ((size_t)proj * 1024 + (hh0 << 6)) * 1024;
    size_t Abase = (size_t)m0 * 1024, Bbase = 0;
    MMA_BODY(AhP, AlP, BhP, BlP, Abase, Bbase, pst, nst)
    float* dst = proj == 0 ? g_q : proj == 1 ? g_k : g_v;
    int lp = tig * 2;
    int m = m0 + w * 16 + gid;
    int bb = m >> 10, sq = m & 1023;
#pragma unroll
    for (int nt = 0; nt < 16; nt++) {
        int n = nt * 8 + lp;
        int hh = hh0 + (n >> 6);
        float* d0 = dst + (((size_t)(bb * NHEAD + hh) * SEQ + sq) << 6) + (n & 63);
        float* d1 = d0 + (8 << 6);
        d0[0] = acc[nt][0]; d0[1] = acc[nt][1];
        d1[0] = acc[nt][2]; d1[1] = acc[nt][3];
    }
}

// GEMM 3: out = att @ W^T    grid (32, 8)
__global__ __launch_bounds__(256, 2) void mma_gemm_out(float* __restrict__ out)
{
    int n0 = blockIdx.y << 7;
    int m0 = blockIdx.x << 7;
    const bf16* AhP = g_att_hi; const bf16* AlP = g_att_lo;
    const bf16* BhP = g_w_hi;   const bf16* BlP = g_w_lo;
    size_t Abase = (size_t)m0 * 1024, Bbase = (size_t)n0 * 1024;
    MMA_BODY(AhP, AlP, BhP, BlP, Abase, Bbase, 16, 48)
    int lp = tig * 2;
    int row = m0 + w * 16 + gid;
    float* d0 = out + (size_t)row * 1024 + n0;
    float* d1 = d0 + (size_t)8 * 1024;
#pragma unroll
    for (int nt = 0; nt < 16; nt++) {
        int n = nt * 8 + lp;
        d0[n] = acc[nt][0]; d0[n + 1] = acc[nt][1];
        d1[n] = acc[nt][2]; d1[n + 1] = acc[nt][3];
    }
}

// ---------------- HMMA flash attention: BQ=128, BK=64, 256 thr, 3-pass hi/lo ------------
// smem (bf16 elems, stride 72): Qhi[128], Qlo[128], Khi[64], Klo[64], Vthi[64], Vtlo[64]
#define ASQ 72
#define AQH 0
#define AQL (128*ASQ)
#define AKH (2*128*ASQ)
#define AKL (AKH + 64*ASQ)
#define AVH (AKL + 64*ASQ)
#define AVL (AVH + 64*ASQ)
#define ATT_SMEM ((AVL + 64*ASQ) * 2)

__global__ __launch_bounds__(256, 2) void attn_kernel()
{
    extern __shared__ __align__(16) bf16 asmem[];
    int tid = threadIdx.x, w = tid >> 5, l = tid & 31;
    int gid = l >> 2, tig = l & 3;
    int g_ = l >> 3, rrl = l & 7;
    int aB = w * (16*ASQ) + ((g_ & 1) * 8 + rrl) * ASQ + (g_ >> 1) * 8;
    int bB = ((g_ >> 1) * 8 + rrl) * ASQ + (g_ & 1) * 8;
    uint32_t sb = smem_u32(asmem);

    int qt = blockIdx.x, bh = blockIdx.y;
    const float* qb = g_q + (size_t)bh * SEQ * HDIM;
    const float* kb = g_k + (size_t)bh * SEQ * HDIM;
    const float* vb = g_v + (size_t)bh * SEQ * HDIM;
    int qr0 = qt << 7;

    // load Q tile, fold 0.125 scale, hi/lo split -> smem row-major
#pragma unroll
    for (int it = 0; it < 8; it++) {
        int idx = tid + it * 256;
        int r = idx >> 4, d4 = idx & 15;
        float4 v = *(const float4*)(qb + (size_t)(qr0 + r) * 64 + d4 * 4);
        v.x *= 0.125f; v.y *= 0.125f; v.z *= 0.125f; v.w *= 0.125f;
        bf16 h0,h1,h2,h3,l0,l1,l2,l3;
        split1(v.x,h0,l0); split1(v.y,h1,l1); split1(v.z,h2,l2); split1(v.w,h3,l3);
        int o = r * ASQ + d4 * 4;
        *(__nv_bfloat162*)&asmem[AQH + o]     = __nv_bfloat162(h0, h1);
        *(__nv_bfloat162*)&asmem[AQH + o + 2] = __nv_bfloat162(h2, h3);
        *(__nv_bfloat162*)&asmem[AQL + o]     = __nv_bfloat162(l0, l1);
        *(__nv_bfloat162*)&asmem[AQL + o + 2] = __nv_bfloat162(l2, l3);
    }

    float m_run[2] = {-3.0e38f, -3.0e38f};
    float l_run[2] = {0.f, 0.f};
    float accO[8][4];
#pragma unroll
    for (int i = 0; i < 8; i++)
#pragma unroll
        for (int j = 0; j < 4; j++) accO[i][j] = 0.f;

    int rA = qr0 + w * 16 + gid, rB = rA + 8;
    int ktmax = 2 * qt + 1;
    for (int kt = 0; kt <= ktmax; kt++) {
        int kr0 = kt << 6;
        __syncthreads();
        // load K (row-major) + V (transposed [d][key]) with hi/lo split
#pragma unroll
        for (int it = 0; it < 4; it++) {
            int idx = tid + it * 256;
            int r = idx >> 4, d4 = idx & 15;
            float4 kv = *(const float4*)(kb + (size_t)(kr0 + r) * 64 + d4 * 4);
            bf16 h0,h1,h2,h3,l0,l1,l2,l3;
            split1(kv.x,h0,l0); split1(kv.y,h1,l1); split1(kv.z,h2,l2); split1(kv.w,h3,l3);
            int o = r * ASQ + d4 * 4;
            *(__nv_bfloat162*)&asmem[AKH + o]     = __nv_bfloat162(h0, h1);
            *(__nv_bfloat162*)&asmem[AKH + o + 2] = __nv_bfloat162(h2, h3);
            *(__nv_bfloat162*)&asmem[AKL + o]     = __nv_bfloat162(l0, l1);
            *(__nv_bfloat162*)&asmem[AKL + o + 2] = __nv_bfloat162(l2, l3);
            float4 vv = *(const float4*)(vb + (size_t)(kr0 + r) * 64 + d4 * 4);
            split1(vv.x,h0,l0); split1(vv.y,h1,l1); split1(vv.z,h2,l2); split1(vv.w,h3,l3);
            asmem[AVH + (d4*4+0)*ASQ + r] = h0;  asmem[AVL + (d4*4+0)*ASQ + r] = l0;
            asmem[AVH + (d4*4+1)*ASQ + r] = h1;  asmem[AVL + (d4*4+1)*ASQ + r] = l1;
            asmem[AVH + (d4*4+2)*ASQ + r] = h2;  asmem[AVL + (d4*4+2)*ASQ + r] = l2;
            asmem[AVH + (d4*4+3)*ASQ + r] = h3;  asmem[AVL + (d4*4+3)*ASQ + r] = l3;
        }
        __syncthreads();

        // ---- scores: 3-pass split QK^T ----
        float acc[8][4];
#pragma unroll
        for (int i = 0; i < 8; i++)
#pragma unroll
            for (int j = 0; j < 4; j++) acc[i][j] = 0.f;
#pragma unroll
        for (int ps = 0; ps < 3; ps++) {
            uint32_t qbase = sb + (uint32_t)((ps == 1 ? AQL : AQH)) * 2;
            uint32_t kbase = sb + (uint32_t)((ps == 2 ? AKL : AKH)) * 2;
#pragma unroll
            for (int k16 = 0; k16 < 4; k16++) {
                uint32_t av[4];
                ldsm4(av, qbase + (uint32_t)(aB + k16*16) * 2);
                uint32_t bfr[16];
#pragma unroll
                for (int t = 0; t < 4; t++)
                    ldsm4(bfr + 4*t, kbase + (uint32_t)(bB + t*(16*ASQ) + k16*16) * 2);
#pragma unroll
                for (int nt = 0; nt < 8; nt++)
                    hmma(acc[nt], av, bfr + (nt >> 1) * 4 + (nt & 1) * 2);
            }
        }

        // ---- mask + online softmax ----
        if (kt >= 2 * qt) {
#pragma unroll
            for (int nt = 0; nt < 8; nt++) {
                int cb = kr0 + nt * 8 + tig * 2;
                if (cb     > rA) acc[nt][0] = -3.0e38f;
                if (cb + 1 > rA) acc[nt][1] = -3.0e38f;
                if (cb     > rB) acc[nt][2] = -3.0e38f;
                if (cb + 1 > rB) acc[nt][3] = -3.0e38f;
            }
        }
        float mxA = -3.0e38f, mxB = -3.0e38f;
#pragma unroll
        for (int nt = 0; nt < 8; nt++) {
            mxA = fmaxf(mxA, fmaxf(acc[nt][0], acc[nt][1]));
            mxB = fmaxf(mxB, fmaxf(acc[nt][2], acc[nt][3]));
        }
        mxA = fmaxf(mxA, __shfl_xor_sync(0xffffffffu, mxA, 1));
        mxA = fmaxf(mxA, __shfl_xor_sync(0xffffffffu, mxA, 2));
        mxB = fmaxf(mxB, __shfl_xor_sync(0xffffffffu, mxB, 1));
        mxB = fmaxf(mxB, __shfl_xor_sync(0xffffffffu, mxB, 2));
        float mA = fmaxf(m_run[0], mxA);
        float mB = fmaxf(m_run[1], mxB);
        float cA = __expf(m_run[0] - mA);
        float cB = __expf(m_run[1] - mB);
        float pA = 0.f, pB = 0.f;
#pragma unroll
        for (int nt = 0; nt < 8; nt++) {
            acc[nt][0] = __expf(acc[nt][0] - mA); pA += acc[nt][0];
            acc[nt][1] = __expf(acc[nt][1] - mA); pA += acc[nt][1];
            acc[nt][2] = __expf(acc[nt][2] - mB); pB += acc[nt][2];
            acc[nt][3] = __expf(acc[nt][3] - mB); pB += acc[nt][3];
        }
        pA += __shfl_xor_sync(0xffffffffu, pA, 1);
        pA += __shfl_xor_sync(0xffffffffu, pA, 2);
        pB += __shfl_xor_sync(0xffffffffu, pB, 1);
        pB += __shfl_xor_sync(0xffffffffu, pB, 2);
        l_run[0] = l_run[0] * cA + pA;  m_run[0] = mA;
        l_run[1] = l_run[1] * cB + pB;  m_run[1] = mB;
#pragma unroll
        for (int nt = 0; nt < 8; nt++) {
            accO[nt][0] *= cA; accO[nt][1] *= cA;
            accO[nt][2] *= cB; accO[nt][3] *= cB;
        }

        // ---- PV: register repack of P (C-frag -> A-frag), 3-pass split ----
#pragma unroll
        for (int j = 0; j < 4; j++) {
            float v00 = acc[2*j][0],   v01 = acc[2*j][1],   v10 = acc[2*j][2],   v11 = acc[2*j][3];
            float w00 = acc[2*j+1][0], w01 = acc[2*j+1][1], w10 = acc[2*j+1][2], w11 = acc[2*j+1][3];
            bf16 hv00 = __float2bfloat16(v00), hv01 = __float2bfloat16(v01);
            bf16 hv10 = __float2bfloat16(v10), hv11 = __float2bfloat16(v11);
            bf16 hw00 = __float2bfloat16(w00), hw01 = __float2bfloat16(w01);
            bf16 hw10 = __float2bfloat16(w10), hw11 = __float2bfloat16(w11);
            __nv_bfloat162 ph[4], pl[4];
            ph[0] = __nv_bfloat162(hv00, hv01);
            ph[1] = __nv_bfloat162(hv10, hv11);
            ph[2] = __nv_bfloat162(hw00, hw01);
            ph[3] = __nv_bfloat162(hw10, hw11);
            pl[0] = __nv_bfloat162(__float2bfloat16(v00 - __bfloat162float(hv00)),
                                   __float2bfloat16(v01 - __bfloat162float(hv01)));
            pl[1] = __nv_bfloat162(__float2bfloat16(v10 - __bfloat162float(hv10)),
                                   __float2bfloat16(v11 - __bfloat162float(hv11)));
            pl[2] = __nv_bfloat162(__float2bfloat16(w00 - __bfloat162float(hw00)),
                                   __float2bfloat16(w01 - __bfloat162float(hw01)));
            pl[3] = __nv_bfloat162(__float2bfloat16(w10 - __bfloat162float(hw10)),
                                   __float2bfloat16(w11 - __bfloat162float(hw11)));
            const uint32_t* aPh = (const uint32_t*)ph;
            const uint32_t* aPl = (const uint32_t*)pl;
#pragma unroll
            for (int ps = 0; ps < 3; ps++) {
                const uint32_t* ap = (ps == 1) ? aPl : aPh;
                uint32_t vbase = sb + (uint32_t)((ps == 2 ? AVL : AVH)) * 2;
                uint32_t bfr[16];
#pragma unroll
                for (int t = 0; t < 4; t++)
                    ldsm4(bfr + 4*t, vbase + (uint32_t)(bB + t*(16*ASQ) + j*16) * 2);
#pragma unroll
                for (int nt = 0; nt < 8; nt++)
                    hmma(accO[nt], ap, bfr + (nt >> 1) * 4 + (nt & 1) * 2);
            }
        }
    }

    // ---- epilogue: normalize + bf16 hi/lo split into g_att_hi/lo ----
    float iA = 1.f / l_run[0], iB = 1.f / l_run[1];
    int b = bh >> 4, h = bh & 15;
    size_t oA = (size_t)(b * SEQ + rA) * DMODEL + h * 64 + tig * 2;
    size_t oB = (size_t)(b * SEQ + rB) * DMODEL + h * 64 + tig * 2;
#pragma unroll
    for (int nt = 0; nt < 8; nt++) {
        bf16 h0, l0, h1, l1;
        split1(accO[nt][0] * iA, h0, l0); split1(accO[nt][1] * iA, h1, l1);
        g_att_hi[oA + nt*8]     = h0; g_att_hi[oA + nt*8 + 1] = h1;
        g_att_lo[oA + nt*8]     = l0; g_att_lo[oA + nt*8 + 1] = l1;
        split1(accO[nt][2] * iB, h0, l0); split1(accO[nt][3] * iB, h1, l1);
        g_att_hi[oB + nt*8]     = h0; g_att_hi[oB + nt*8 + 1] = h1;
        g_att_lo[oB + nt*8]     = l0; g_att_lo[oB + nt*8 + 1] = l1;
    }
}

// ---------------- launch ----------------
extern "C" void kernel_launch(void* const* d_in, const int* in_sizes, int n_in,
                              void* d_out, int out_size)
{
    (void)n_in; (void)out_size;
    const float* x   = (const float*)d_in[0];
    const float* qU  = (const float*)d_in[1];
    const float* qV  = (const float*)d_in[2];
    const float* kU  = (const float*)d_in[3];
    const float* kV  = (const float*)d_in[4];
    const float* vU  = (const float*)d_in[5];
    const float* vV  = (const float*)d_in[6];
    const float* ql  = (const float*)d_in[7];
    const float* kl  = (const float*)d_in[8];
    const float* vl  = (const float*)d_in[9];
    const float* ow  = (const float*)d_in[10];
    const int*   tk  = (const int*)d_in[11];
    int P = in_sizes[7];

    cudaFuncSetAttribute(attn_kernel,  cudaFuncAttributeMaxDynamicSharedMemorySize, ATT_SMEM);
    cudaFuncSetAttribute(mma_gemm_xu,  cudaFuncAttributeMaxDynamicSharedMemorySize, GSMEM);
    cudaFuncSetAttribute(mma_gemm_hv,  cudaFuncAttributeMaxDynamicSharedMemorySize, GSMEM);
    cudaFuncSetAttribute(mma_gemm_out, cudaFuncAttributeMaxDynamicSharedMemorySize, GSMEM);

    topk_kernel<<<1, 32>>>(ql, kl, vl, tk, P);

    conv_x<<<4096, 256>>>(x);
    conv_w<<<1024, 256>>>(ow);
    conv_ut<<<dim3(3, 16, 16), 256>>>(qU, kU, vU);
    conv_vt<<<dim3(3, 16, 16), 256>>>(qV, kV, vV);

    mma_gemm_xu<<<dim3(32, 8, 3), 256, GSMEM>>>();
    mma_gemm_hv<<<dim3(32, 8, 3), 256, GSMEM>>>();
    attn_kernel<<<dim3(SEQ / 128, BATCH * NHEAD), 256, ATT_SMEM>>>();
    mma_gemm_out<<<dim3(32, 8), 256, GSMEM>>>((float*)d_out);
}

// round 17
// speedup vs baseline: 4.9473x; 1.0767x over previous
#include <cuda_runtime.h>
#include <cuda_bf16.h>
#include <cstdint>

#define DMODEL 1024
#define SEQ    1024
#define BATCH  4
#define NHEAD  16
#define HDIM   64
#define RNK    64
#define MROWS  (BATCH*SEQ)
#define PMAX   64

typedef unsigned long long u64;
typedef __nv_bfloat16 bf16;

// ---------------- warp MMA helpers (arch-agnostic sm_80+ PTX) ----------------
__device__ __forceinline__ uint32_t smem_u32(const void* p) {
    uint32_t a;
    asm("{ .reg .u64 t; cvta.to.shared.u64 t, %1; cvt.u32.u64 %0, t; }" : "=r"(a) : "l"(p));
    return a;
}
__device__ __forceinline__ void ldsm4(uint32_t* r, uint32_t addr) {
    asm volatile("ldmatrix.sync.aligned.m8n8.x4.shared.b16 {%0,%1,%2,%3}, [%4];"
        : "=r"(r[0]), "=r"(r[1]), "=r"(r[2]), "=r"(r[3]) : "r"(addr));
}
__device__ __forceinline__ void hmma(float* d, const uint32_t* a, const uint32_t* b) {
    asm volatile("mma.sync.aligned.m16n8k16.row.col.f32.bf16.bf16.f32 "
        "{%0,%1,%2,%3}, {%4,%5,%6,%7}, {%8,%9}, {%0,%1,%2,%3};"
        : "+f"(d[0]), "+f"(d[1]), "+f"(d[2]), "+f"(d[3])
        : "r"(a[0]), "r"(a[1]), "r"(a[2]), "r"(a[3]), "r"(b[0]), "r"(b[1]));
}
#define CP_ASYNC16(dst, src) \
    asm volatile("cp.async.cg.shared.global [%0], [%1], 16;" :: "r"(dst), "l"(src))
#define CP_COMMIT() asm volatile("cp.async.commit_group;")
#define CP_WAIT1()  asm volatile("cp.async.wait_group 1;" ::: "memory")
#define CP_WAIT0()  asm volatile("cp.async.wait_group 0;" ::: "memory")

// ---------------- device scratch (uint4/float4-typed: forced 16B alignment) ------------
__device__ uint4  g_x_hi_r [(size_t)MROWS*1024/8];
__device__ uint4  g_x_lo_r [(size_t)MROWS*1024/8];
__device__ uint4  g_w_hi_r [(size_t)1024*1024/8];
__device__ uint4  g_w_lo_r [(size_t)1024*1024/8];
__device__ uint4  g_ut_hi_r[(size_t)3*16*64*1024/8];
__device__ uint4  g_ut_lo_r[(size_t)3*16*64*1024/8];
__device__ uint4  g_vt_hi_r[(size_t)3*1024*1024/8];
__device__ uint4  g_vt_lo_r[(size_t)3*1024*1024/8];
__device__ uint4  g_h_hi_r [(size_t)3*MROWS*1024/8];
__device__ uint4  g_h_lo_r [(size_t)3*MROWS*1024/8];
__device__ uint4  g_att_hi_r[(size_t)MROWS*1024/8];
__device__ uint4  g_att_lo_r[(size_t)MROWS*1024/8];
__device__ float4 g_q_r   [(size_t)BATCH*NHEAD*SEQ*HDIM/4];
__device__ float4 g_k_r   [(size_t)BATCH*NHEAD*SEQ*HDIM/4];
__device__ float4 g_v_r   [(size_t)BATCH*NHEAD*SEQ*HDIM/4];
__device__ float g_tw[3][PMAX];
__device__ int   g_ti[3][PMAX];
__device__ int   g_K;

#define g_x_hi  ((bf16*)g_x_hi_r)
#define g_x_lo  ((bf16*)g_x_lo_r)
#define g_w_hi  ((bf16*)g_w_hi_r)
#define g_w_lo  ((bf16*)g_w_lo_r)
#define g_ut_hi ((bf16*)g_ut_hi_r)
#define g_ut_lo ((bf16*)g_ut_lo_r)
#define g_vt_hi ((bf16*)g_vt_hi_r)
#define g_vt_lo ((bf16*)g_vt_lo_r)
#define g_h_hi  ((bf16*)g_h_hi_r)
#define g_h_lo  ((bf16*)g_h_lo_r)
#define g_att_hi ((bf16*)g_att_hi_r)
#define g_att_lo ((bf16*)g_att_lo_r)
#define g_q     ((float*)g_q_r)
#define g_k     ((float*)g_k_r)
#define g_v     ((float*)g_v_r)

// ---------------- top-k gating ----------------
__global__ void topk_kernel(const float* __restrict__ ql, const float* __restrict__ kl,
                            const float* __restrict__ vl, const int* __restrict__ tkp, int P)
{
    if (threadIdx.x != 0) return;
    int K = *tkp; if (K > P) K = P; if (K < 1) K = 1;
    g_K = K;
    const float* ls[3] = {ql, kl, vl};
    for (int p = 0; p < 3; p++) {
        const float* lg = ls[p];
        bool used[PMAX];
        for (int i = 0; i < P; i++) used[i] = false;
        for (int t = 0; t < K; t++) {
            int best = 0; float bv = -3.4e38f;
            for (int i = 0; i < P; i++)
                if (!used[i] && lg[i] > bv) { bv = lg[i]; best = i; }
            used[best] = true;
            g_ti[p][t] = best;
        }
        float mx = -3.4e38f;
        for (int t = 0; t < K; t++) { float v = lg[g_ti[p][t]]; if (v > mx) mx = v; }
        float ssum = 0.f, w[PMAX];
        for (int t = 0; t < K; t++) { w[t] = expf(lg[g_ti[p][t]] - mx); ssum += w[t]; }
        for (int t = 0; t < K; t++) g_tw[p][t] = w[t] / ssum;
    }
}

// ---------------- bf16 split conversions ----------------
__device__ __forceinline__ void split1(float v, bf16& h, bf16& l) {
    h = __float2bfloat16(v);
    l = __float2bfloat16(v - __bfloat162float(h));
}

__global__ void conv_x(const float* __restrict__ src)
{
    int i = blockIdx.x * blockDim.x + threadIdx.x;
    float4 v = ((const float4*)src)[i];
    bf16 h0,h1,h2,h3,l0,l1,l2,l3;
    split1(v.x,h0,l0); split1(v.y,h1,l1); split1(v.z,h2,l2); split1(v.w,h3,l3);
    g_x_hi[4*i+0]=h0; g_x_hi[4*i+1]=h1; g_x_hi[4*i+2]=h2; g_x_hi[4*i+3]=h3;
    g_x_lo[4*i+0]=l0; g_x_lo[4*i+1]=l1; g_x_lo[4*i+2]=l2; g_x_lo[4*i+3]=l3;
}

__global__ void conv_w(const float* __restrict__ src)
{
    int i = blockIdx.x * blockDim.x + threadIdx.x;
    float4 v = ((const float4*)src)[i];
    bf16 h0,h1,h2,h3,l0,l1,l2,l3;
    split1(v.x,h0,l0); split1(v.y,h1,l1); split1(v.z,h2,l2); split1(v.w,h3,l3);
    g_w_hi[4*i+0]=h0; g_w_hi[4*i+1]=h1; g_w_hi[4*i+2]=h2; g_w_hi[4*i+3]=h3;
    g_w_lo[4*i+0]=l0; g_w_lo[4*i+1]=l1; g_w_lo[4*i+2]=l2; g_w_lo[4*i+3]=l3;
}

// Ut[p][kc][j][c] = U[prim][c][j]   grid (3, 16, 16), smem-tiled transpose
__global__ __launch_bounds__(256) void conv_ut(const float* __restrict__ qU,
    const float* __restrict__ kU, const float* __restrict__ vU)
{
    int p = blockIdx.x, kc = blockIdx.y;
    if (kc >= g_K) return;
    __shared__ float tile[64][65];
    const float* U = p == 0 ? qU : p == 1 ? kU : vU;
    const float* Up = U + (size_t)g_ti[p][kc] * 65536;
    int c0 = blockIdx.z * 64;
    for (int idx = threadIdx.x; idx < 4096; idx += 256) {
        int rc = idx >> 6, jj = idx & 63;
        tile[rc][jj] = Up[(size_t)(c0 + rc) * 64 + jj];
    }
    __syncthreads();
    size_t base = (size_t)(p * 16 + kc) * 65536;
    for (int idx = threadIdx.x; idx < 4096; idx += 256) {
        int jj = idx >> 6, rc = idx & 63;
        bf16 h, l; split1(tile[rc][jj], h, l);
        g_ut_hi[base + (size_t)jj * 1024 + c0 + rc] = h;
        g_ut_lo[base + (size_t)jj * 1024 + c0 + rc] = l;
    }
}

// Vt[p][n][kc*64+j] = V[prim(kc)][j][n]   grid (3, 16, 16), smem-tiled transpose
__global__ __launch_bounds__(256) void conv_vt(const float* __restrict__ qV,
    const float* __restrict__ kV, const float* __restrict__ vV)
{
    int p = blockIdx.x, kc = blockIdx.y;
    if (kc >= g_K) return;
    __shared__ float tile[64][65];
    const float* V = p == 0 ? qV : p == 1 ? kV : vV;
    const float* Vp = V + (size_t)g_ti[p][kc] * 65536;
    int n0 = blockIdx.z * 64;
    for (int idx = threadIdx.x; idx < 4096; idx += 256) {
        int j = idx >> 6, nn = idx & 63;
        tile[j][nn] = Vp[(size_t)j * 1024 + n0 + nn];
    }
    __syncthreads();
    for (int idx = threadIdx.x; idx < 4096; idx += 256) {
        int nn = idx >> 6, j = idx & 63;
        bf16 h, l; split1(tile[j][nn], h, l);
        size_t dst = ((size_t)p * 1024 + n0 + nn) * 1024 + kc * 64 + j;
        g_vt_hi[dst] = h;
        g_vt_lo[dst] = l;
    }
}

// ---------------- fused-split HMMA GEMM: 128x128 tile, BK=32, one K-walk ----------------
// per stage: Ahi, Alo, Bhi, Blo tiles (128 x 32, stride 40) -> 3 split terms per chunk
#define SAS2 40
#define PSZ (128*SAS2)        // 5120 elems per piece
#define STG (4*PSZ)           // stage = 20480 elems
#define GSMEM (2*STG*2)       // 81920 bytes

#define MMA_ISSUE_F(buf, kk)                                                          \
    {                                                                                 \
        size_t ko_ = (size_t)(kk) * 32;                                               \
        const bf16* ps0_ = AhP + Abase + ko_;                                         \
        const bf16* ps1_ = AlP + Abase + ko_;                                         \
        const bf16* ps2_ = BhP + Bbase + ko_;                                         \
        const bf16* ps3_ = BlP + Bbase + ko_;                                         \
        _Pragma("unroll")                                                             \
        for (int it = 0; it < 2; it++) {                                              \
            int u = tid + it * 256; int r = u >> 2, q = (u & 3) * 8;                  \
            uint32_t dof = (uint32_t)((buf)*STG + r*SAS2 + q) * 2;                    \
            size_t sof = (size_t)r * 1024 + q;                                        \
            CP_ASYNC16(sb0 + dof,             ps0_ + sof);                            \
            CP_ASYNC16(sb0 + dof + PSZ*2,     ps1_ + sof);                            \
            CP_ASYNC16(sb0 + dof + 2*PSZ*2,   ps2_ + sof);                            \
            CP_ASYNC16(sb0 + dof + 3*PSZ*2,   ps3_ + sof);                            \
        }                                                                             \
        CP_COMMIT();                                                                  \
    }

#define MMA_BODY_F(NCH)                                                              \
    extern __shared__ __align__(16) bf16 dsm[];                                      \
    int tid = threadIdx.x, w = tid >> 5, l = tid & 31;                               \
    int gid = l >> 2, tig = l & 3;                                                   \
    int g_ = l >> 3, rrl = l & 7;                                                    \
    int aB = w * (16*SAS2) + ((g_ & 1) * 8 + rrl) * SAS2 + (g_ >> 1) * 8;            \
    int bB = ((g_ >> 1) * 8 + rrl) * SAS2 + (g_ & 1) * 8;                            \
    uint32_t sb0 = smem_u32(dsm);                                                    \
    float acc[16][4];                                                                \
    _Pragma("unroll") for (int i_ = 0; i_ < 16; i_++)                                \
    _Pragma("unroll") for (int j_ = 0; j_ < 4; j_++) acc[i_][j_] = 0.f;              \
    MMA_ISSUE_F(0, 0)                                                                \
    for (int c = 0; c < (NCH); c++) {                                                \
        int cur = c & 1;                                                             \
        if (c + 1 < (NCH)) { MMA_ISSUE_F(cur ^ 1, c + 1) CP_WAIT1(); }               \
        else { CP_WAIT0(); }                                                         \
        __syncthreads();                                                             \
        uint32_t base = sb0 + (uint32_t)(cur*STG) * 2;                               \
        _Pragma("unroll")                                                            \
        for (int k16 = 0; k16 < 2; k16++) {                                          \
            uint32_t avh[4], avl[4];                                                 \
            ldsm4(avh, base + (uint32_t)(aB + k16*16) * 2);                          \
            ldsm4(avl, base + (uint32_t)(PSZ + aB + k16*16) * 2);                    \
            _Pragma("unroll")                                                        \
            for (int ph = 0; ph < 2; ph++) {                                         \
                uint32_t bfr[16];                                                    \
                _Pragma("unroll")                                                    \
                for (int t = 0; t < 4; t++)                                          \
                    ldsm4(bfr + 4*t, base + (uint32_t)(2*PSZ + bB + (ph*4+t)*(16*SAS2) + k16*16) * 2); \
                _Pragma("unroll")                                                    \
                for (int nt8 = 0; nt8 < 8; nt8++) {                                  \
                    hmma(acc[ph*8+nt8], avh, bfr + (nt8 >> 1) * 4 + (nt8 & 1) * 2);  \
                    hmma(acc[ph*8+nt8], avl, bfr + (nt8 >> 1) * 4 + (nt8 & 1) * 2);  \
                }                                                                    \
                _Pragma("unroll")                                                    \
                for (int t = 0; t < 4; t++)                                          \
                    ldsm4(bfr + 4*t, base + (uint32_t)(3*PSZ + bB + (ph*4+t)*(16*SAS2) + k16*16) * 2); \
                _Pragma("unroll")                                                    \
                for (int nt8 = 0; nt8 < 8; nt8++)                                    \
                    hmma(acc[ph*8+nt8], avh, bfr + (nt8 >> 1) * 4 + (nt8 & 1) * 2);  \
            }                                                                        \
        }                                                                            \
        __syncthreads();                                                             \
    }

// GEMM 1: h[p][m][kc*64+n] = tw * x[m,:] @ U[prim], kc-pairs fused  grid (32, 8, 3)
__global__ __launch_bounds__(256, 2) void mma_gemm_xu()
{
    int proj = blockIdx.z, kc0 = blockIdx.y * 2;
    int K = g_K;
    if (kc0 >= K) return;
    int m0 = blockIdx.x << 7;
    const bf16* AhP = g_x_hi; const bf16* AlP = g_x_lo;
    const bf16* BhP = g_ut_hi + (size_t)(proj * 16 + kc0) * 65536;
    const bf16* BlP = g_ut_lo + (size_t)(proj * 16 + kc0) * 65536;
    float tws[2];
    tws[0] = g_tw[proj][kc0];
    tws[1] = (kc0 + 1 < K) ? g_tw[proj][kc0 + 1] : 0.f;
    size_t Abase = (size_t)m0 * 1024, Bbase = 0;
    MMA_BODY_F(32)
    int row = m0 + w * 16 + gid, lp = tig * 2;
#pragma unroll
    for (int nt = 0; nt < 16; nt++) {
        int n = nt * 8 + lp;
        int kcl = n >> 6;
        int kc = kc0 + kcl;
        if (kc < K) {
            float tw = tws[kcl];
            size_t b0_ = ((size_t)proj * MROWS + row) * 1024 + kc * 64 + (n & 63);
            size_t b1_ = b0_ + (size_t)8 * 1024;
            bf16 h0, l0, h1, l1;
            split1(tw * acc[nt][0], h0, l0); split1(tw * acc[nt][1], h1, l1);
            g_h_hi[b0_] = h0; g_h_hi[b0_ + 1] = h1;
            g_h_lo[b0_] = l0; g_h_lo[b0_ + 1] = l1;
            split1(tw * acc[nt][2], h0, l0); split1(tw * acc[nt][3], h1, l1);
            g_h_hi[b1_] = h0; g_h_hi[b1_ + 1] = h1;
            g_h_lo[b1_] = l0; g_h_lo[b1_ + 1] = l1;
        }
    }
}

// GEMM 2: qkv = h @ Vt -> [B,H,S,D] fp32, head-pairs fused   grid (32, 8, 3)
__global__ __launch_bounds__(256, 2) void mma_gemm_hv()
{
    int proj = blockIdx.z, hh0 = blockIdx.y * 2;
    int m0 = blockIdx.x << 7;
    int nch = 2 * g_K;
    const bf16* AhP = g_h_hi + (size_t)proj * MROWS * 1024;
    const bf16* AlP = g_h_lo + (size_t)proj * MROWS * 1024;
    const bf16* BhP = g_vt_hi + ((size_t)proj * 1024 + (hh0 << 6)) * 1024;
    const bf16* BlP = g_vt_lo + ((size_t)proj * 1024 + (hh0 << 6)) * 1024;
    size_t Abase = (size_t)m0 * 1024, Bbase = 0;
    MMA_BODY_F(nch)
    float* dst = proj == 0 ? g_q : proj == 1 ? g_k : g_v;
    int lp = tig * 2;
    int m = m0 + w * 16 + gid;
    int bb = m >> 10, sq = m & 1023;
#pragma unroll
    for (int nt = 0; nt < 16; nt++) {
        int n = nt * 8 + lp;
        int hh = hh0 + (n >> 6);
        float* d0 = dst + (((size_t)(bb * NHEAD + hh) * SEQ + sq) << 6) + (n & 63);
        float* d1 = d0 + (8 << 6);
        d0[0] = acc[nt][0]; d0[1] = acc[nt][1];
        d1[0] = acc[nt][2]; d1[1] = acc[nt][3];
    }
}

// GEMM 3: out = att @ W^T    grid (32, 8)
__global__ __launch_bounds__(256, 2) void mma_gemm_out(float* __restrict__ out)
{
    int n0 = blockIdx.y << 7;
    int m0 = blockIdx.x << 7;
    const bf16* AhP = g_att_hi; const bf16* AlP = g_att_lo;
    const bf16* BhP = g_w_hi;   const bf16* BlP = g_w_lo;
    size_t Abase = (size_t)m0 * 1024, Bbase = (size_t)n0 * 1024;
    MMA_BODY_F(32)
    int lp = tig * 2;
    int row = m0 + w * 16 + gid;
    float* d0 = out + (size_t)row * 1024 + n0;
    float* d1 = d0 + (size_t)8 * 1024;
#pragma unroll
    for (int nt = 0; nt < 16; nt++) {
        int n = nt * 8 + lp;
        d0[n] = acc[nt][0]; d0[n + 1] = acc[nt][1];
        d1[n] = acc[nt][2]; d1[n + 1] = acc[nt][3];
    }
}

// ---------------- HMMA flash attention: BQ=128, BK=64, 256 thr, 3-pass hi/lo ------------
#define ASQ 72
#define AQH 0
#define AQL (128*ASQ)
#define AKH (2*128*ASQ)
#define AKL (AKH + 64*ASQ)
#define AVH (AKL + 64*ASQ)
#define AVL (AVH + 64*ASQ)
#define ATT_SMEM ((AVL + 64*ASQ) * 2)

__global__ __launch_bounds__(256, 2) void attn_kernel()
{
    extern __shared__ __align__(16) bf16 asmem[];
    int tid = threadIdx.x, w = tid >> 5, l = tid & 31;
    int gid = l >> 2, tig = l & 3;
    int g_ = l >> 3, rrl = l & 7;
    int aB = w * (16*ASQ) + ((g_ & 1) * 8 + rrl) * ASQ + (g_ >> 1) * 8;
    int bB = ((g_ >> 1) * 8 + rrl) * ASQ + (g_ & 1) * 8;
    uint32_t sb = smem_u32(asmem);

    int qt = blockIdx.x, bh = blockIdx.y;
    const float* qb = g_q + (size_t)bh * SEQ * HDIM;
    const float* kb = g_k + (size_t)bh * SEQ * HDIM;
    const float* vb = g_v + (size_t)bh * SEQ * HDIM;
    int qr0 = qt << 7;

#pragma unroll
    for (int it = 0; it < 8; it++) {
        int idx = tid + it * 256;
        int r = idx >> 4, d4 = idx & 15;
        float4 v = *(const float4*)(qb + (size_t)(qr0 + r) * 64 + d4 * 4);
        v.x *= 0.125f; v.y *= 0.125f; v.z *= 0.125f; v.w *= 0.125f;
        bf16 h0,h1,h2,h3,l0,l1,l2,l3;
        split1(v.x,h0,l0); split1(v.y,h1,l1); split1(v.z,h2,l2); split1(v.w,h3,l3);
        int o = r * ASQ + d4 * 4;
        *(__nv_bfloat162*)&asmem[AQH + o]     = __nv_bfloat162(h0, h1);
        *(__nv_bfloat162*)&asmem[AQH + o + 2] = __nv_bfloat162(h2, h3);
        *(__nv_bfloat162*)&asmem[AQL + o]     = __nv_bfloat162(l0, l1);
        *(__nv_bfloat162*)&asmem[AQL + o + 2] = __nv_bfloat162(l2, l3);
    }

    float m_run[2] = {-3.0e38f, -3.0e38f};
    float l_run[2] = {0.f, 0.f};
    float accO[8][4];
#pragma unroll
    for (int i = 0; i < 8; i++)
#pragma unroll
        for (int j = 0; j < 4; j++) accO[i][j] = 0.f;

    int rA = qr0 + w * 16 + gid, rB = rA + 8;
    int ktmax = 2 * qt + 1;
    for (int kt = 0; kt <= ktmax; kt++) {
        int kr0 = kt << 6;
        __syncthreads();
#pragma unroll
        for (int it = 0; it < 4; it++) {
            int idx = tid + it * 256;
            int r = idx >> 4, d4 = idx & 15;
            float4 kv = *(const float4*)(kb + (size_t)(kr0 + r) * 64 + d4 * 4);
            bf16 h0,h1,h2,h3,l0,l1,l2,l3;
            split1(kv.x,h0,l0); split1(kv.y,h1,l1); split1(kv.z,h2,l2); split1(kv.w,h3,l3);
            int o = r * ASQ + d4 * 4;
            *(__nv_bfloat162*)&asmem[AKH + o]     = __nv_bfloat162(h0, h1);
            *(__nv_bfloat162*)&asmem[AKH + o + 2] = __nv_bfloat162(h2, h3);
            *(__nv_bfloat162*)&asmem[AKL + o]     = __nv_bfloat162(l0, l1);
            *(__nv_bfloat162*)&asmem[AKL + o + 2] = __nv_bfloat162(l2, l3);
            float4 vv = *(const float4*)(vb + (size_t)(kr0 + r) * 64 + d4 * 4);
            split1(vv.x,h0,l0); split1(vv.y,h1,l1); split1(vv.z,h2,l2); split1(vv.w,h3,l3);
            asmem[AVH + (d4*4+0)*ASQ + r] = h0;  asmem[AVL + (d4*4+0)*ASQ + r] = l0;
            asmem[AVH + (d4*4+1)*ASQ + r] = h1;  asmem[AVL + (d4*4+1)*ASQ + r] = l1;
            asmem[AVH + (d4*4+2)*ASQ + r] = h2;  asmem[AVL + (d4*4+2)*ASQ + r] = l2;
            asmem[AVH + (d4*4+3)*ASQ + r] = h3;  asmem[AVL + (d4*4+3)*ASQ + r] = l3;
        }
        __syncthreads();

        float acc[8][4];
#pragma unroll
        for (int i = 0; i < 8; i++)
#pragma unroll
            for (int j = 0; j < 4; j++) acc[i][j] = 0.f;
#pragma unroll
        for (int ps = 0; ps < 3; ps++) {
            uint32_t qbase = sb + (uint32_t)((ps == 1 ? AQL : AQH)) * 2;
            uint32_t kbase = sb + (uint32_t)((ps == 2 ? AKL : AKH)) * 2;
#pragma unroll
            for (int k16 = 0; k16 < 4; k16++) {
                uint32_t av[4];
                ldsm4(av, qbase + (uint32_t)(aB + k16*16) * 2);
                uint32_t bfr[16];
#pragma unroll
                for (int t = 0; t < 4; t++)
                    ldsm4(bfr + 4*t, kbase + (uint32_t)(bB + t*(16*ASQ) + k16*16) * 2);
#pragma unroll
                for (int nt = 0; nt < 8; nt++)
                    hmma(acc[nt], av, bfr + (nt >> 1) * 4 + (nt & 1) * 2);
            }
        }

        if (kt >= 2 * qt) {
#pragma unroll
            for (int nt = 0; nt < 8; nt++) {
                int cb = kr0 + nt * 8 + tig * 2;
                if (cb     > rA) acc[nt][0] = -3.0e38f;
                if (cb + 1 > rA) acc[nt][1] = -3.0e38f;
                if (cb     > rB) acc[nt][2] = -3.0e38f;
                if (cb + 1 > rB) acc[nt][3] = -3.0e38f;
            }
        }
        float mxA = -3.0e38f, mxB = -3.0e38f;
#pragma unroll
        for (int nt = 0; nt < 8; nt++) {
            mxA = fmaxf(mxA, fmaxf(acc[nt][0], acc[nt][1]));
            mxB = fmaxf(mxB, fmaxf(acc[nt][2], acc[nt][3]));
        }
        mxA = fmaxf(mxA, __shfl_xor_sync(0xffffffffu, mxA, 1));
        mxA = fmaxf(mxA, __shfl_xor_sync(0xffffffffu, mxA, 2));
        mxB = fmaxf(mxB, __shfl_xor_sync(0xffffffffu, mxB, 1));
        mxB = fmaxf(mxB, __shfl_xor_sync(0xffffffffu, mxB, 2));
        float mA = fmaxf(m_run[0], mxA);
        float mB = fmaxf(m_run[1], mxB);
        float cA = __expf(m_run[0] - mA);
        float cB = __expf(m_run[1] - mB);
        float pA = 0.f, pB = 0.f;
#pragma unroll
        for (int nt = 0; nt < 8; nt++) {
            acc[nt][0] = __expf(acc[nt][0] - mA); pA += acc[nt][0];
            acc[nt][1] = __expf(acc[nt][1] - mA); pA += acc[nt][1];
            acc[nt][2] = __expf(acc[nt][2] - mB); pB += acc[nt][2];
            acc[nt][3] = __expf(acc[nt][3] - mB); pB += acc[nt][3];
        }
        pA += __shfl_xor_sync(0xffffffffu, pA, 1);
        pA += __shfl_xor_sync(0xffffffffu, pA, 2);
        pB += __shfl_xor_sync(0xffffffffu, pB, 1);
        pB += __shfl_xor_sync(0xffffffffu, pB, 2);
        l_run[0] = l_run[0] * cA + pA;  m_run[0] = mA;
        l_run[1] = l_run[1] * cB + pB;  m_run[1] = mB;
#pragma unroll
        for (int nt = 0; nt < 8; nt++) {
            accO[nt][0] *= cA; accO[nt][1] *= cA;
            accO[nt][2] *= cB; accO[nt][3] *= cB;
        }

#pragma unroll
        for (int j = 0; j < 4; j++) {
            float v00 = acc[2*j][0],   v01 = acc[2*j][1],   v10 = acc[2*j][2],   v11 = acc[2*j][3];
            float w00 = acc[2*j+1][0], w01 = acc[2*j+1][1], w10 = acc[2*j+1][2], w11 = acc[2*j+1][3];
            bf16 hv00 = __float2bfloat16(v00), hv01 = __float2bfloat16(v01);
            bf16 hv10 = __float2bfloat16(v10), hv11 = __float2bfloat16(v11);
            bf16 hw00 = __float2bfloat16(w00), hw01 = __float2bfloat16(w01);
            bf16 hw10 = __float2bfloat16(w10), hw11 = __float2bfloat16(w11);
            __nv_bfloat162 ph[4], pl[4];
            ph[0] = __nv_bfloat162(hv00, hv01);
            ph[1] = __nv_bfloat162(hv10, hv11);
            ph[2] = __nv_bfloat162(hw00, hw01);
            ph[3] = __nv_bfloat162(hw10, hw11);
            pl[0] = __nv_bfloat162(__float2bfloat16(v00 - __bfloat162float(hv00)),
                                   __float2bfloat16(v01 - __bfloat162float(hv01)));
            pl[1] = __nv_bfloat162(__float2bfloat16(v10 - __bfloat162float(hv10)),
                                   __float2bfloat16(v11 - __bfloat162float(hv11)));
            pl[2] = __nv_bfloat162(__float2bfloat16(w00 - __bfloat162float(hw00)),
                                   __float2bfloat16(w01 - __bfloat162float(hw01)));
            pl[3] = __nv_bfloat162(__float2bfloat16(w10 - __bfloat162float(hw10)),
                                   __float2bfloat16(w11 - __bfloat162float(hw11)));
            const uint32_t* aPh = (const uint32_t*)ph;
            const uint32_t* aPl = (const uint32_t*)pl;
#pragma unroll
            for (int ps = 0; ps < 3; ps++) {
                const uint32_t* ap = (ps == 1) ? aPl : aPh;
                uint32_t vbase = sb + (uint32_t)((ps == 2 ? AVL : AVH)) * 2;
                uint32_t bfr[16];
#pragma unroll
                for (int t = 0; t < 4; t++)
                    ldsm4(bfr + 4*t, vbase + (uint32_t)(bB + t*(16*ASQ) + j*16) * 2);
#pragma unroll
                for (int nt = 0; nt < 8; nt++)
                    hmma(accO[nt], ap, bfr + (nt >> 1) * 4 + (nt & 1) * 2);
            }
        }
    }

    float iA = 1.f / l_run[0], iB = 1.f / l_run[1];
    int b = bh >> 4, h = bh & 15;
    size_t oA = (size_t)(b * SEQ + rA) * DMODEL + h * 64 + tig * 2;
    size_t oB = (size_t)(b * SEQ + rB) * DMODEL + h * 64 + tig * 2;
#pragma unroll
    for (int nt = 0; nt < 8; nt++) {
        bf16 h0, l0, h1, l1;
        split1(accO[nt][0] * iA, h0, l0); split1(accO[nt][1] * iA, h1, l1);
        g_att_hi[oA + nt*8]     = h0; g_att_hi[oA + nt*8 + 1] = h1;
        g_att_lo[oA + nt*8]     = l0; g_att_lo[oA + nt*8 + 1] = l1;
        split1(accO[nt][2] * iB, h0, l0); split1(accO[nt][3] * iB, h1, l1);
        g_att_hi[oB + nt*8]     = h0; g_att_hi[oB + nt*8 + 1] = h1;
        g_att_lo[oB + nt*8]     = l0; g_att_lo[oB + nt*8 + 1] = l1;
    }
}

// ---------------- launch ----------------
extern "C" void kernel_launch(void* const* d_in, const int* in_sizes, int n_in,
                              void* d_out, int out_size)
{
    (void)n_in; (void)out_size;
    const float* x   = (const float*)d_in[0];
    const float* qU  = (const float*)d_in[1];
    const float* qV  = (const float*)d_in[2];
    const float* kU  = (const float*)d_in[3];
    const float* kV  = (const float*)d_in[4];
    const float* vU  = (const float*)d_in[5];
    const float* vV  = (const float*)d_in[6];
    const float* ql  = (const float*)d_in[7];
    const float* kl  = (const float*)d_in[8];
    const float* vl  = (const float*)d_in[9];
    const float* ow  = (const float*)d_in[10];
    const int*   tk  = (const int*)d_in[11];
    int P = in_sizes[7];

    cudaFuncSetAttribute(attn_kernel,  cudaFuncAttributeMaxDynamicSharedMemorySize, ATT_SMEM);
    cudaFuncSetAttribute(mma_gemm_xu,  cudaFuncAttributeMaxDynamicSharedMemorySize, GSMEM);
    cudaFuncSetAttribute(mma_gemm_hv,  cudaFuncAttributeMaxDynamicSharedMemorySize, GSMEM);
    cudaFuncSetAttribute(mma_gemm_out, cudaFuncAttributeMaxDynamicSharedMemorySize, GSMEM);

    topk_kernel<<<1, 32>>>(ql, kl, vl, tk, P);

    conv_x<<<4096, 256>>>(x);
    conv_w<<<1024, 256>>>(ow);
    conv_ut<<<dim3(3, 16, 16), 256>>>(qU, kU, vU);
    conv_vt<<<dim3(3, 16, 16), 256>>>(qV, kV, vV);

    mma_gemm_xu<<<dim3(32, 8, 3), 256, GSMEM>>>();
    mma_gemm_hv<<<dim3(32, 8, 3), 256, GSMEM>>>();
    attn_kernel<<<dim3(SEQ / 128, BATCH * NHEAD), 256, ATT_SMEM>>>();
    mma_gemm_out<<<dim3(32, 8), 256, GSMEM>>>((float*)d_out);
}